// round 8
// baseline (speedup 1.0000x reference)
#include <cuda_runtime.h>
#include <math.h>
#include <stdint.h>

#define BATCH 4
#define SEQ   1024
#define HID   768
#define HEADS 12
#define NENT  32
#define MENT  4
#define WD    768
#define AD    256
#define NC    97
#define NCP   128          // padded classifier width
#define SPLITK 64
#define DD    12
#define PP    144          // DD*DD
#define NPAIR (NENT*NENT)  // 1024

// ---------------- device scratch ----------------
__device__ float d_rep[BATCH*NENT*HID];
__device__ float d_rso[BATCH*NENT*2*WD];
__device__ float d_Wso[WD*2*WD];
__device__ float d_seqR[(size_t)BATCH*SEQ*HID];   // tf32-rounded seq
__device__ float d_WcR[HID*WD];
__device__ float d_WaR[WD*AD];
__device__ float d_clfR[WD*NCP];                  // rounded + padded clf_W
__device__ float d_ga [BATCH*NENT*HEADS*SEQ];
__device__ float d_pa [(size_t)BATCH*NPAIR*SEQ];  // unnormalized, tf32-rounded
__device__ float d_painv[BATCH*NPAIR];
__device__ float d_ctxh[(size_t)BATCH*NPAIR*HID];
__device__ float d_Zs [(size_t)BATCH*NPAIR*WD];
__device__ float d_Zo [(size_t)BATCH*NPAIR*WD];
__device__ float d_P  [(size_t)BATCH*NPAIR*PP];
__device__ float d_g  [(size_t)BATCH*NPAIR*WD];
__device__ float d_t  [(size_t)BATCH*NPAIR*AD];
__device__ float d_e  [BATCH*NPAIR];
__device__ float d_arow[BATCH*NPAIR];
__device__ float d_acol[BATCH*NPAIR];
__device__ float d_Ablt[PP*WD];
__device__ float d_gclf[(size_t)BATCH*NPAIR*NCP];
__device__ float d_rgcg[2*BATCH*NENT*NC];
__device__ float d_part[2200000];                 // split-K partials

// ---------------- helpers ----------------
__device__ __forceinline__ uint32_t f2tf32(float x)
{
    uint32_t r;
    asm("cvt.rna.tf32.f32 %0, %1;" : "=r"(r) : "f"(x));
    return r;
}
__device__ __forceinline__ float rnd32(float x) { return __uint_as_float(f2tf32(x)); }

__device__ __forceinline__ void mma_tf32(float* c, const uint32_t* a, const uint32_t* b)
{
    asm volatile(
        "mma.sync.aligned.m16n8k8.row.col.f32.tf32.tf32.f32 "
        "{%0,%1,%2,%3}, {%4,%5,%6,%7}, {%8,%9}, {%0,%1,%2,%3};"
        : "+f"(c[0]), "+f"(c[1]), "+f"(c[2]), "+f"(c[3])
        : "r"(a[0]), "r"(a[1]), "r"(a[2]), "r"(a[3]), "r"(b[0]), "r"(b[1]));
}

__device__ __forceinline__ void cp16(uint32_t smem, const void* g)
{
    asm volatile("cp.async.cg.shared.global [%0], [%1], 16;" :: "r"(smem), "l"(g));
}
__device__ __forceinline__ uint32_t smem_u32(const void* p)
{
    return (uint32_t)__cvta_generic_to_shared(p);
}

// ---------------- cp.async pipelined tf32 GEMM ----------------
// C[M,N] = A[M,K] row * B[K,N] row, operands pre-rounded to tf32.
// BM=128, BN=16*NWT (64 or 128), BK=16. 8 warps: 4 m x 2 n, warp tile 32x(8*NWT).
// Canonical padded smem (conflict-free fragment LDS); cp.async double buffer.
// MODE 0: C = acc (+ biasScale*bias[n]); MODE 1: tanh(acc + bias/bias2[(gm>>5)*bS+gn]) -> C,C2;
// MODE 2: C = acc * bias[zb*bS+gm].  RND: round stored C to tf32.
// Requirements: M%128==0, (K/kSplit)%16==0, N%4==0.
#define AS_STRIDE 20
template<int NWT, int MODE, int RND>
__global__ __launch_bounds__(256, 2)
void mma_gemm(const float* __restrict__ A, const float* __restrict__ B,
              float* __restrict__ C, float* __restrict__ C2,
              int M, int N, int K,
              long long sA, long long sB, long long sC,
              int kSplit, long long partStride,
              const float* __restrict__ bias, float biasScale,
              const float* __restrict__ bias2, int biasStride)
{
    const int BN  = 16 * NWT;
    const int BSS = BN + 8;
    const int NBQ = BN / 4;              // float4 quads per B row
    const int NB  = (16 * NBQ) / 256;    // B cp.asyncs per thread (1 or 2)
    __shared__ uint32_t As[2][128 * AS_STRIDE];
    __shared__ float    Bs[2][16 * BSS];

    int zb = blockIdx.z / kSplit;
    int kz = blockIdx.z - zb * kSplit;
    A += (long long)zb * sA;
    B += (long long)zb * sB;
    C += (long long)zb * sC + (long long)kz * partStride;

    int row0 = blockIdx.y * 128;
    int col0 = blockIdx.x * BN;
    int tid = threadIdx.x, lane = tid & 31, w = tid >> 5;
    int wm = w & 3, wn = w >> 2;
    int g = lane >> 2, t = lane & 3;

    int kLen = K / kSplit;
    int k0beg = kz * kLen, k0end = k0beg + kLen;

    float acc[2][NWT][4];
    #pragma unroll
    for (int i = 0; i < 2; i++)
        #pragma unroll
        for (int j = 0; j < NWT; j++)
            #pragma unroll
            for (int r = 0; r < 4; r++) acc[i][j][r] = 0.f;

    int am0 = tid >> 2, akq = tid & 3;

    const float* gA0 = A + (long long)(row0 + am0) * K + akq * 4;
    const float* gA1 = gA0 + (long long)64 * K;
    uint32_t asA0 = smem_u32(&As[0][am0 * AS_STRIDE + akq * 4]);
    uint32_t asA1 = smem_u32(&As[0][(am0 + 64) * AS_STRIDE + akq * 4]);
    const uint32_t strA = 128 * AS_STRIDE * 4;
    const uint32_t strB = 16 * BSS * 4;

    const float* gB[NB];
    uint32_t bsD[NB];
    #pragma unroll
    for (int nb = 0; nb < NB; nb++) {
        int l = tid + nb * 256;
        int kl = l / NBQ, nq = l % NBQ;
        gB[nb]  = B + (long long)kl * N + col0 + nq * 4;
        bsD[nb] = smem_u32(&Bs[0][kl * BSS + nq * 4]);
    }

    // prologue: issue first tile
    {
        cp16(asA0, gA0 + k0beg);
        cp16(asA1, gA1 + k0beg);
        #pragma unroll
        for (int nb = 0; nb < NB; nb++)
            cp16(bsD[nb], gB[nb] + (long long)k0beg * N);
        asm volatile("cp.async.commit_group;");
    }

    int buf = 0;
    for (int k0 = k0beg; k0 < k0end; k0 += 16) {
        asm volatile("cp.async.wait_group 0;");
        __syncthreads();
        int kn = k0 + 16;
        if (kn < k0end) {
            uint32_t ao = (buf ^ 1) ? strA : 0;
            uint32_t bo = (buf ^ 1) ? strB : 0;
            cp16(asA0 + ao, gA0 + kn);
            cp16(asA1 + ao, gA1 + kn);
            #pragma unroll
            for (int nb = 0; nb < NB; nb++)
                cp16(bsD[nb] + bo, gB[nb] + (long long)kn * N);
            asm volatile("cp.async.commit_group;");
        }
        const uint32_t* as = As[buf];
        const float*    bs = Bs[buf];
        #pragma unroll
        for (int k8 = 0; k8 < 2; k8++) {
            int kb = k8 * 8;
            uint32_t a[2][4];
            #pragma unroll
            for (int mi = 0; mi < 2; mi++) {
                int mb = wm * 32 + mi * 16;
                a[mi][0] = as[(mb + g)     * AS_STRIDE + kb + t];
                a[mi][1] = as[(mb + g + 8) * AS_STRIDE + kb + t];
                a[mi][2] = as[(mb + g)     * AS_STRIDE + kb + t + 4];
                a[mi][3] = as[(mb + g + 8) * AS_STRIDE + kb + t + 4];
            }
            uint32_t b[NWT][2];
            #pragma unroll
            for (int ni = 0; ni < NWT; ni++) {
                int nb_ = wn * 8 * NWT + ni * 8 + g;
                b[ni][0] = __float_as_uint(bs[(kb + t)     * BSS + nb_]);
                b[ni][1] = __float_as_uint(bs[(kb + t + 4) * BSS + nb_]);
            }
            #pragma unroll
            for (int mi = 0; mi < 2; mi++)
                #pragma unroll
                for (int ni = 0; ni < NWT; ni++)
                    mma_tf32(acc[mi][ni], a[mi], b[ni]);
        }
        buf ^= 1;
    }

    // ---- epilogue ----
    #pragma unroll
    for (int mi = 0; mi < 2; mi++) {
        #pragma unroll
        for (int ni = 0; ni < NWT; ni++) {
            int m_base = row0 + wm * 32 + mi * 16 + g;
            int n_base = col0 + wn * 8 * NWT + ni * 8 + t * 2;
            #pragma unroll
            for (int r = 0; r < 4; r++) {
                int gm = m_base + ((r >> 1) << 3);
                int gn = n_base + (r & 1);
                if (gn >= N) continue;
                float v = acc[mi][ni][r];
                if (MODE == 0) {
                    if (bias) v += biasScale * bias[gn];
                    if (RND) v = rnd32(v);
                    C[(long long)gm * N + gn] = v;
                } else if (MODE == 1) {
                    long long br = (long long)(gm >> 5) * biasStride + gn;
                    C [(long long)gm * N + gn] = tanhf(v + bias [br]);
                    C2[(long long)gm * N + gn] = tanhf(v + bias2[br]);
                } else {
                    v *= bias[(long long)zb * biasStride + gm];
                    if (RND) v = rnd32(v);
                    C[(long long)gm * N + gn] = v;
                }
            }
        }
    }
}

__global__ void reduce_add_kernel(const float* __restrict__ src, float* __restrict__ dst,
                                  int parts, long long len)
{
    long long i = (long long)blockIdx.x * 256 + threadIdx.x;
    if (i >= len) return;
    float s = 0.f;
    for (int p = 0; p < parts; p++) s += src[(long long)p * len + i];
    dst[i] = s;
}

// ---------------- stage kernels ----------------
__global__ void rep_kernel(const float* __restrict__ seq, const int* __restrict__ ep)
{
    int bn = blockIdx.x;
    int b = bn / NENT, n = bn % NENT;
    int e0 = ep[(b * NENT + n) * MENT + 0];
    int e1 = ep[(b * NENT + n) * MENT + 1];
    int e2 = ep[(b * NENT + n) * MENT + 2];
    int e3 = ep[(b * NENT + n) * MENT + 3];
    const float* sb = seq + (long long)b * SEQ * HID;
    for (int h = threadIdx.x; h < HID; h += blockDim.x) {
        float v0 = sb[(long long)e0 * HID + h];
        float v1 = sb[(long long)e1 * HID + h];
        float v2 = sb[(long long)e2 * HID + h];
        float v3 = sb[(long long)e3 * HID + h];
        float m = fmaxf(fmaxf(v0, v1), fmaxf(v2, v3));
        float s = expf(v0 - m) + expf(v1 - m) + expf(v2 - m) + expf(v3 - m);
        d_rep[(b * NENT + n) * HID + h] = rnd32(m + logf(s));
    }
}

// round+copy inputs used as GEMM B operands (+ clf pad to 128 cols)
__global__ void roundcopy_kernel(const float* __restrict__ seq,
                                 const float* __restrict__ Wc,
                                 const float* __restrict__ Wa,
                                 const float* __restrict__ clf)
{
    const long long n1 = (long long)BATCH * SEQ * HID;
    const long long n2 = (long long)HID * WD;
    const long long n3 = (long long)WD * AD;
    const long long n4 = (long long)WD * NCP;
    long long idx = (long long)blockIdx.x * 256 + threadIdx.x;
    if (idx < n1) { d_seqR[idx] = rnd32(seq[idx]); return; }
    idx -= n1;
    if (idx < n2) { d_WcR[idx] = rnd32(Wc[idx]); return; }
    idx -= n2;
    if (idx < n3) { d_WaR[idx] = rnd32(Wa[idx]); return; }
    idx -= n3;
    if (idx < n4) {
        int row = (int)(idx >> 7), col = (int)(idx & (NCP - 1));
        d_clfR[idx] = (col < NC) ? rnd32(clf[row * NC + col]) : 0.f;
    }
}

__global__ void packA_kernel(const float* __restrict__ A_bl)
{
    int idx = blockIdx.x * 256 + threadIdx.x;
    if (idx >= WD * PP) return;
    int o = idx / PP, pq = idx % PP;
    d_Ablt[pq * WD + o] = rnd32(A_bl[idx]);
}

__global__ void packW_kernel(const float* __restrict__ W_s, const float* __restrict__ W_o)
{
    int idx = blockIdx.x * 256 + threadIdx.x;
    if (idx >= WD * WD) return;
    int k = idx / WD, j = idx % WD;
    d_Wso[(long long)k * (2 * WD) + j]      = rnd32(W_s[idx]);
    d_Wso[(long long)k * (2 * WD) + WD + j] = rnd32(W_o[idx]);
}

__global__ void ga_kernel(const float* __restrict__ att, const int* __restrict__ ep)
{
    int b = blockIdx.z;
    int n = blockIdx.y / HEADS, h = blockIdx.y % HEADS;
    int s = blockIdx.x * blockDim.x + threadIdx.x;
    const float* ab = att + ((long long)(b * HEADS + h)) * SEQ * SEQ;
    float a = 0.f;
    #pragma unroll
    for (int m = 0; m < MENT; m++) {
        int e = ep[(b * NENT + n) * MENT + m];
        a += ab[(long long)e * SEQ + s];
    }
    d_ga[((long long)((b * NENT + n) * HEADS + h)) * SEQ + s] = a;
}

__global__ __launch_bounds__(256) void pa_tiled_kernel()
{
    extern __shared__ float sm[];          // [0:12288) gi, [12288:24576) gj
    __shared__ float sred[16 * 8];
    int b = blockIdx.z, ti = blockIdx.y, tj = blockIdx.x;
    int tid = threadIdx.x, lane = tid & 31, w = tid >> 5;

    float psum[16];
    #pragma unroll
    for (int p = 0; p < 16; p++) psum[p] = 0.f;

    for (int c = 0; c < 4; c++) {
        int s0 = c * 256;
        for (int l = tid; l < 3072; l += 256) {
            int il = l / 768;
            int rem = l - il * 768;
            int h = rem / 64, sq = rem - h * 64;
            int smoff = (il * 12 + h) * 256 + sq * 4;
            *(float4*)&sm[smoff] =
                *(const float4*)&d_ga[(((long long)(b * NENT + ti * 4 + il) * HEADS + h) << 10) + s0 + sq * 4];
            *(float4*)&sm[12288 + smoff] =
                *(const float4*)&d_ga[(((long long)(b * NENT + tj * 4 + il) * HEADS + h) << 10) + s0 + sq * 4];
        }
        __syncthreads();

        float acc[16];
        #pragma unroll
        for (int p = 0; p < 16; p++) acc[p] = 0.f;
        #pragma unroll
        for (int h = 0; h < HEADS; h++) {
            float ai[4], bj[4];
            #pragma unroll
            for (int il = 0; il < 4; il++) ai[il] = sm[(il * 12 + h) * 256 + tid];
            #pragma unroll
            for (int jl = 0; jl < 4; jl++) bj[jl] = sm[12288 + (jl * 12 + h) * 256 + tid];
            #pragma unroll
            for (int il = 0; il < 4; il++)
                #pragma unroll
                for (int jl = 0; jl < 4; jl++)
                    acc[il * 4 + jl] += ai[il] * bj[jl];
        }
        #pragma unroll
        for (int il = 0; il < 4; il++)
            #pragma unroll
            for (int jl = 0; jl < 4; jl++) {
                int p = il * 4 + jl;
                int ij = (ti * 4 + il) * NENT + tj * 4 + jl;
                d_pa[((long long)(b * NPAIR + ij) << 10) + s0 + tid] = rnd32(acc[p]);
                psum[p] += acc[p];
            }
        __syncthreads();
    }

    #pragma unroll
    for (int p = 0; p < 16; p++) {
        #pragma unroll
        for (int o = 16; o > 0; o >>= 1)
            psum[p] += __shfl_xor_sync(~0u, psum[p], o);
    }
    if (lane == 0)
        #pragma unroll
        for (int p = 0; p < 16; p++) sred[p * 8 + w] = psum[p];
    __syncthreads();
    if (tid < 16) {
        float s = 0.f;
        #pragma unroll
        for (int ww = 0; ww < 8; ww++) s += sred[tid * 8 + ww];
        int il = tid >> 2, jl = tid & 3;
        int ij = (ti * 4 + il) * NENT + tj * 4 + jl;
        d_painv[b * NPAIR + ij] = 1.0f / s;
    }
}

__global__ __launch_bounds__(256) void P_kernel()
{
    __shared__ float zs[WD], zo[WD];
    long long row = blockIdx.x;
    for (int w = threadIdx.x; w < WD; w += 256) {
        zs[w] = d_Zs[row * WD + w];
        zo[w] = d_Zo[row * WD + w];
    }
    __syncthreads();
    int t = threadIdx.x;
    if (t < PP) {
        int p = t / DD, q = t % DD;
        float a = 0.f;
        #pragma unroll
        for (int k = 0; k < SPLITK; k++)
            a += zs[p * SPLITK + k] * zo[q * SPLITK + k];
        d_P[row * PP + t] = rnd32(a);
    }
}

__global__ __launch_bounds__(256) void e_kernel(const float* __restrict__ v_attn)
{
    int row = blockIdx.x;
    int tid = threadIdx.x;
    float val = tanhf(d_t[(long long)row * AD + tid]) * v_attn[tid];
    __shared__ float red[256];
    red[tid] = val;
    __syncthreads();
    for (int off = 128; off > 0; off >>= 1) {
        if (tid < off) red[tid] += red[tid + off];
        __syncthreads();
    }
    if (tid == 0) d_e[row] = red[0];
}

__global__ __launch_bounds__(1024) void softmax_kernel()
{
    int b = blockIdx.x;
    int tid = threadIdx.x;
    int w = tid >> 5, lane = tid & 31;
    const float* eb = d_e + b * NPAIR;
    float v = eb[w * 32 + lane];
    float m = v;
    for (int o = 16; o > 0; o >>= 1) m = fmaxf(m, __shfl_xor_sync(~0u, m, o));
    float ex = expf(v - m);
    float s = ex;
    for (int o = 16; o > 0; o >>= 1) s += __shfl_xor_sync(~0u, s, o);
    d_arow[b * NPAIR + w * 32 + lane] = ex / s;
    float v2 = eb[lane * 32 + w];
    float m2 = v2;
    for (int o = 16; o > 0; o >>= 1) m2 = fmaxf(m2, __shfl_xor_sync(~0u, m2, o));
    float ex2 = expf(v2 - m2);
    float s2 = ex2;
    for (int o = 16; o > 0; o >>= 1) s2 += __shfl_xor_sync(~0u, s2, o);
    d_acol[b * NPAIR + lane * 32 + w] = ex2 / s2;
}

__global__ void rowcolC_kernel()
{
    int b = blockIdx.y, n = blockIdx.x;
    int c = threadIdx.x;
    if (c >= NC) return;
    const float* gc = d_gclf + (long long)b * NPAIR * NCP;
    float rs = 0.f, cs = 0.f;
    #pragma unroll 4
    for (int k = 0; k < NENT; k++) {
        rs += d_arow[b * NPAIR + n * 32 + k] * gc[(long long)(n * 32 + k) * NCP + c];
        cs += d_acol[b * NPAIR + k * 32 + n] * gc[(long long)(k * 32 + n) * NCP + c];
    }
    d_rgcg[(b * NENT + n) * NC + c] = rs;
    d_rgcg[(BATCH * NENT + b * NENT + n) * NC + c] = cs;
}

__global__ void final_kernel(const float* __restrict__ clf_b, float* __restrict__ out)
{
    long long idx = (long long)blockIdx.x * blockDim.x + threadIdx.x;
    const long long total = (long long)BATCH * NPAIR * NC;
    if (idx >= total) return;
    int c = (int)(idx % NC);
    long long rb = idx / NC;
    int ij = (int)(rb % NPAIR);
    int b = (int)(rb / NPAIR);
    int i = ij >> 5, j = ij & 31;
    out[idx] = d_gclf[rb * NCP + c]
             + d_rgcg[(b * NENT + i) * NC + c]
             + d_rgcg[(BATCH * NENT + b * NENT + j) * NC + c]
             + clf_b[c];
}

// ---------------- host launch ----------------
extern "C" void kernel_launch(void* const* d_in, const int* in_sizes, int n_in,
                              void* d_out, int out_size)
{
    const float* seq    = (const float*)d_in[0];
    const float* att    = (const float*)d_in[1];
    const int*   ep     = (const int*)  d_in[2];
    const float* W_s    = (const float*)d_in[3];
    const float* W_o    = (const float*)d_in[4];
    const float* W_c    = (const float*)d_in[5];
    const float* A_bl   = (const float*)d_in[6];
    const float* b_bl   = (const float*)d_in[7];
    const float* W_attn = (const float*)d_in[8];
    const float* v_attn = (const float*)d_in[9];
    const float* clf_W  = (const float*)d_in[10];
    const float* clf_b  = (const float*)d_in[11];
    float* out = (float*)d_out;

    float *p_rep, *p_rso, *p_Wso, *p_seqR, *p_WcR, *p_WaR, *p_clfR, *p_pa,
          *p_painv, *p_ctxh, *p_Zs, *p_Zo, *p_P, *p_Ablt, *p_g, *p_t,
          *p_gclf, *p_part;
    cudaGetSymbolAddress((void**)&p_rep,   d_rep);
    cudaGetSymbolAddress((void**)&p_rso,   d_rso);
    cudaGetSymbolAddress((void**)&p_Wso,   d_Wso);
    cudaGetSymbolAddress((void**)&p_seqR,  d_seqR);
    cudaGetSymbolAddress((void**)&p_WcR,   d_WcR);
    cudaGetSymbolAddress((void**)&p_WaR,   d_WaR);
    cudaGetSymbolAddress((void**)&p_clfR,  d_clfR);
    cudaGetSymbolAddress((void**)&p_pa,    d_pa);
    cudaGetSymbolAddress((void**)&p_painv, d_painv);
    cudaGetSymbolAddress((void**)&p_ctxh,  d_ctxh);
    cudaGetSymbolAddress((void**)&p_Zs,    d_Zs);
    cudaGetSymbolAddress((void**)&p_Zo,    d_Zo);
    cudaGetSymbolAddress((void**)&p_P,     d_P);
    cudaGetSymbolAddress((void**)&p_Ablt,  d_Ablt);
    cudaGetSymbolAddress((void**)&p_g,     d_g);
    cudaGetSymbolAddress((void**)&p_t,     d_t);
    cudaGetSymbolAddress((void**)&p_gclf,  d_gclf);
    cudaGetSymbolAddress((void**)&p_part,  d_part);

    static bool attrSet = false;
    if (!attrSet) {
        cudaFuncSetAttribute(pa_tiled_kernel,
                             cudaFuncAttributeMaxDynamicSharedMemorySize, 98304);
        attrSet = true;
    }

    // 0. entity attention gather
    {
        dim3 grid(SEQ / 256, NENT * HEADS, BATCH);
        ga_kernel<<<grid, 256>>>(att, ep);
    }
    // 1. pairwise localized attention (unnormalized, rounded) + reciprocal sums
    {
        dim3 grid(8, 8, BATCH);
        pa_tiled_kernel<<<grid, 256, 98304>>>();
    }
    // 2. round/copy B-side inputs (seq, W_c, W_attn, clf padded)
    {
        long long total = (long long)BATCH * SEQ * HID + (long long)HID * WD
                        + (long long)WD * AD + (long long)WD * NCP;
        roundcopy_kernel<<<(unsigned)((total + 255) / 256), 256>>>(seq, W_c, W_attn, clf_W);
    }
    // 3. ctxh = (pa @ seqR) * painv[row]  NWT=8 grid(6,8,4)=192
    {
        dim3 grid(WD / 128, NPAIR / 128, BATCH);
        mma_gemm<8, 2, 1><<<grid, 256>>>(p_pa, p_seqR, p_ctxh, nullptr,
                                         NPAIR, HID, SEQ,
                                         (long long)NPAIR * SEQ, (long long)SEQ * HID,
                                         (long long)NPAIR * HID,
                                         1, 0, p_painv, 0.f, nullptr, NPAIR);
    }
    // 4. entity reps (rounded)
    rep_kernel<<<BATCH * NENT, 256>>>(seq, ep);
    // 5-6. packs (rounded)
    packA_kernel<<<(WD * PP + 255) / 256, 256>>>(A_bl);
    packW_kernel<<<(WD * WD + 255) / 256, 256>>>(W_s, W_o);
    // 7. rso partials = rep @ [W_s|W_o]  split-K 6, NWT=4 grid(24,1,6)=144
    {
        dim3 grid((2 * WD) / 64, 1, 6);
        mma_gemm<4, 0, 0><<<grid, 256>>>(p_rep, p_Wso, p_part, nullptr,
                                         BATCH * NENT, 2 * WD, HID, 0, 0, 0,
                                         6, (long long)BATCH * NENT * 2 * WD,
                                         nullptr, 0.f, nullptr, 0);
    }
    // 8. reduce rso
    reduce_add_kernel<<<(BATCH * NENT * 2 * WD + 255) / 256, 256>>>(
        p_part, p_rso, 6, (long long)BATCH * NENT * 2 * WD);
    // 9. fused: Zs/Zo = tanh(rso[i] + ctxh @ WcR)  NWT=8 grid(6,32)=192
    {
        dim3 grid(WD / 128, (BATCH * NPAIR) / 128, 1);
        mma_gemm<8, 1, 0><<<grid, 256>>>(p_ctxh, p_WcR, p_Zs, p_Zo,
                                         BATCH * NPAIR, WD, HID, 0, 0, 0,
                                         1, 0, p_rso, 0.f, p_rso + WD, 2 * WD);
    }
    // 10. P (rounded)
    P_kernel<<<BATCH * NPAIR, 256>>>();
    // 11. g = P @ Ablt + 64*b_bl (rounded)  NWT=8 grid(6,32)=192
    {
        dim3 grid(WD / 128, (BATCH * NPAIR) / 128, 1);
        mma_gemm<8, 0, 1><<<grid, 256>>>(p_P, p_Ablt, p_g, nullptr,
                                         BATCH * NPAIR, WD, PP, 0, 0, 0,
                                         1, 0, b_bl, (float)SPLITK, nullptr, 0);
    }
    // 12. t = g @ WaR  NWT=4 grid(4,32)=128
    {
        dim3 grid(AD / 64, (BATCH * NPAIR) / 128, 1);
        mma_gemm<4, 0, 0><<<grid, 256>>>(p_g, p_WaR, p_t, nullptr,
                                         BATCH * NPAIR, AD, WD, 0, 0, 0,
                                         1, 0, nullptr, 0.f, nullptr, 0);
    }
    // 13. e = tanh(t) . v_attn
    e_kernel<<<BATCH * NPAIR, 256>>>(v_attn);
    // 14. softmax
    softmax_kernel<<<BATCH, 1024>>>();
    // 15. gclf partials = g @ clfR (padded N=128, split-K 4) grid(2,32,4)=256
    {
        long long len = (long long)BATCH * NPAIR * NCP;
        dim3 grid(NCP / 64, (BATCH * NPAIR) / 128, 4);
        mma_gemm<4, 0, 0><<<grid, 256>>>(p_g, p_clfR, p_part, nullptr,
                                         BATCH * NPAIR, NCP, WD, 0, 0, 0,
                                         4, len, nullptr, 0.f, nullptr, 0);
        reduce_add_kernel<<<(unsigned)((len + 255) / 256), 256>>>(p_part, p_gclf, 4, len);
    }
    // 16. axis-attention residual folded through clf_W
    {
        dim3 grid(NENT, BATCH);
        rowcolC_kernel<<<grid, 128>>>();
    }
    // 17. out
    {
        long long total = (long long)BATCH * NPAIR * NC;
        final_kernel<<<(unsigned)((total + 255) / 256), 256>>>(clf_b, out);
    }
}

// round 9
// speedup vs baseline: 1.0287x; 1.0287x over previous
#include <cuda_runtime.h>
#include <math.h>
#include <stdint.h>

#define BATCH 4
#define SEQ   1024
#define HID   768
#define HEADS 12
#define NENT  32
#define MENT  4
#define WD    768
#define AD    256
#define NC    97
#define NCP   128          // padded classifier width
#define SPLITK 64
#define DD    12
#define PP    144          // DD*DD
#define NPAIR (NENT*NENT)  // 1024

// ---------------- device scratch ----------------
__device__ float d_rep[BATCH*NENT*HID];
__device__ float d_rso[BATCH*NENT*2*WD];
__device__ float d_Wso[WD*2*WD];
__device__ float d_seqR[(size_t)BATCH*SEQ*HID];   // tf32-rounded seq
__device__ float d_WcR[HID*WD];
__device__ float d_WaR[WD*AD];
__device__ float d_clfR[WD*NCP];                  // rounded + padded clf_W
__device__ float d_ga [BATCH*NENT*HEADS*SEQ];
__device__ float d_pa [(size_t)BATCH*NPAIR*SEQ];  // unnormalized, tf32-rounded
__device__ float d_painv[BATCH*NPAIR];
__device__ float d_ctxh[(size_t)BATCH*NPAIR*HID];
__device__ float d_Zs [(size_t)BATCH*NPAIR*WD];
__device__ float d_Zo [(size_t)BATCH*NPAIR*WD];
__device__ float d_P  [(size_t)BATCH*NPAIR*PP];
__device__ float d_g  [(size_t)BATCH*NPAIR*WD];
__device__ float d_t  [(size_t)BATCH*NPAIR*AD];
__device__ float d_e  [BATCH*NPAIR];
__device__ float d_arow[BATCH*NPAIR];
__device__ float d_acol[BATCH*NPAIR];
__device__ float d_Ablt[PP*WD];
__device__ float d_gclf[(size_t)BATCH*NPAIR*NCP];
__device__ float d_rgcg[2*BATCH*NENT*NC];
__device__ float d_part[2200000];                 // split-K partials

// ---------------- helpers ----------------
__device__ __forceinline__ uint32_t f2tf32(float x)
{
    uint32_t r;
    asm("cvt.rna.tf32.f32 %0, %1;" : "=r"(r) : "f"(x));
    return r;
}
__device__ __forceinline__ float rnd32(float x) { return __uint_as_float(f2tf32(x)); }

__device__ __forceinline__ void mma_tf32(float* c, const uint32_t* a, const uint32_t* b)
{
    asm volatile(
        "mma.sync.aligned.m16n8k8.row.col.f32.tf32.tf32.f32 "
        "{%0,%1,%2,%3}, {%4,%5,%6,%7}, {%8,%9}, {%0,%1,%2,%3};"
        : "+f"(c[0]), "+f"(c[1]), "+f"(c[2]), "+f"(c[3])
        : "r"(a[0]), "r"(a[1]), "r"(a[2]), "r"(a[3]), "r"(b[0]), "r"(b[1]));
}

__device__ __forceinline__ void cp16(uint32_t smem, const void* g)
{
    asm volatile("cp.async.cg.shared.global [%0], [%1], 16;" :: "r"(smem), "l"(g));
}
__device__ __forceinline__ uint32_t smem_u32(const void* p)
{
    return (uint32_t)__cvta_generic_to_shared(p);
}

// ---------------- 3-stage cp.async pipelined tf32 GEMM ----------------
// C[M,N] = A[M,K] row * B[K,N] row, operands pre-rounded to tf32.
// BM=128, BN=16*NWT (64 or 128), BK=16. 8 warps: 4 m x 2 n, warp tile 32x(8*NWT).
// Canonical padded smem (conflict-free fragment LDS); 3-stage cp.async ring,
// wait_group 1 in steady state (2-iteration latency budget), wait_group 0 on
// the final iteration.
// MODE 0: C = acc (+ biasScale*bias[n]); MODE 1: tanh(acc + bias/bias2[(gm>>5)*bS+gn]) -> C,C2;
// MODE 2: C = acc * bias[zb*bS+gm].  RND: round stored C to tf32.
// Requirements: M%128==0, (K/kSplit)%16==0, N%4==0, K/kSplit>=32.
#define AS_STRIDE 20
template<int NWT, int MODE, int RND>
__global__ __launch_bounds__(256, 2)
void mma_gemm(const float* __restrict__ A, const float* __restrict__ B,
              float* __restrict__ C, float* __restrict__ C2,
              int M, int N, int K,
              long long sA, long long sB, long long sC,
              int kSplit, long long partStride,
              const float* __restrict__ bias, float biasScale,
              const float* __restrict__ bias2, int biasStride)
{
    const int BN  = 16 * NWT;
    const int BSS = BN + 8;
    const int NBQ = BN / 4;              // float4 quads per B row
    const int NB  = (16 * NBQ) / 256;    // B cp.asyncs per thread (1 or 2)
    __shared__ uint32_t As[3][128 * AS_STRIDE];
    __shared__ float    Bs[3][16 * BSS];

    int zb = blockIdx.z / kSplit;
    int kz = blockIdx.z - zb * kSplit;
    A += (long long)zb * sA;
    B += (long long)zb * sB;
    C += (long long)zb * sC + (long long)kz * partStride;

    int row0 = blockIdx.y * 128;
    int col0 = blockIdx.x * BN;
    int tid = threadIdx.x, lane = tid & 31, w = tid >> 5;
    int wm = w & 3, wn = w >> 2;
    int g = lane >> 2, t = lane & 3;

    int kLen = K / kSplit;
    int k0beg = kz * kLen, k0end = k0beg + kLen;

    float acc[2][NWT][4];
    #pragma unroll
    for (int i = 0; i < 2; i++)
        #pragma unroll
        for (int j = 0; j < NWT; j++)
            #pragma unroll
            for (int r = 0; r < 4; r++) acc[i][j][r] = 0.f;

    int am0 = tid >> 2, akq = tid & 3;

    const float* gA0 = A + (long long)(row0 + am0) * K + akq * 4;
    const float* gA1 = gA0 + (long long)64 * K;
    uint32_t asA0 = smem_u32(&As[0][am0 * AS_STRIDE + akq * 4]);
    uint32_t asA1 = smem_u32(&As[0][(am0 + 64) * AS_STRIDE + akq * 4]);
    const uint32_t strA = 128 * AS_STRIDE * 4;
    const uint32_t strB = 16 * BSS * 4;

    const float* gB[NB];
    uint32_t bsD[NB];
    #pragma unroll
    for (int nb = 0; nb < NB; nb++) {
        int l = tid + nb * 256;
        int kl = l / NBQ, nq = l % NBQ;
        gB[nb]  = B + (long long)kl * N + col0 + nq * 4;
        bsD[nb] = smem_u32(&Bs[0][kl * BSS + nq * 4]);
    }

    // prologue: issue tiles 0 and 1 into stages 0 and 1
    {
        cp16(asA0, gA0 + k0beg);
        cp16(asA1, gA1 + k0beg);
        #pragma unroll
        for (int nb = 0; nb < NB; nb++)
            cp16(bsD[nb], gB[nb] + (long long)k0beg * N);
        asm volatile("cp.async.commit_group;");
        int k1 = k0beg + 16;
        if (k1 < k0end) {
            cp16(asA0 + strA, gA0 + k1);
            cp16(asA1 + strA, gA1 + k1);
            #pragma unroll
            for (int nb = 0; nb < NB; nb++)
                cp16(bsD[nb] + strB, gB[nb] + (long long)k1 * N);
            asm volatile("cp.async.commit_group;");
        }
    }

    int buf = 0;   // stage holding tile being computed (tile i -> stage i%3)
    for (int k0 = k0beg; k0 < k0end; k0 += 16) {
        if (k0 + 16 < k0end)
            asm volatile("cp.async.wait_group 1;");
        else
            asm volatile("cp.async.wait_group 0;");
        __syncthreads();

        int kn = k0 + 32;
        if (kn < k0end) {
            int wbuf = buf + 2; if (wbuf >= 3) wbuf -= 3;
            uint32_t ao = (uint32_t)wbuf * strA;
            uint32_t bo = (uint32_t)wbuf * strB;
            cp16(asA0 + ao, gA0 + kn);
            cp16(asA1 + ao, gA1 + kn);
            #pragma unroll
            for (int nb = 0; nb < NB; nb++)
                cp16(bsD[nb] + bo, gB[nb] + (long long)kn * N);
            asm volatile("cp.async.commit_group;");
        }

        const uint32_t* as = As[buf];
        const float*    bs = Bs[buf];
        #pragma unroll
        for (int k8 = 0; k8 < 2; k8++) {
            int kb = k8 * 8;
            uint32_t a[2][4];
            #pragma unroll
            for (int mi = 0; mi < 2; mi++) {
                int mb = wm * 32 + mi * 16;
                a[mi][0] = as[(mb + g)     * AS_STRIDE + kb + t];
                a[mi][1] = as[(mb + g + 8) * AS_STRIDE + kb + t];
                a[mi][2] = as[(mb + g)     * AS_STRIDE + kb + t + 4];
                a[mi][3] = as[(mb + g + 8) * AS_STRIDE + kb + t + 4];
            }
            uint32_t b[NWT][2];
            #pragma unroll
            for (int ni = 0; ni < NWT; ni++) {
                int nb_ = wn * 8 * NWT + ni * 8 + g;
                b[ni][0] = __float_as_uint(bs[(kb + t)     * BSS + nb_]);
                b[ni][1] = __float_as_uint(bs[(kb + t + 4) * BSS + nb_]);
            }
            #pragma unroll
            for (int mi = 0; mi < 2; mi++)
                #pragma unroll
                for (int ni = 0; ni < NWT; ni++)
                    mma_tf32(acc[mi][ni], a[mi], b[ni]);
        }
        buf++; if (buf >= 3) buf = 0;
    }

    // ---- epilogue ----
    #pragma unroll
    for (int mi = 0; mi < 2; mi++) {
        #pragma unroll
        for (int ni = 0; ni < NWT; ni++) {
            int m_base = row0 + wm * 32 + mi * 16 + g;
            int n_base = col0 + wn * 8 * NWT + ni * 8 + t * 2;
            #pragma unroll
            for (int r = 0; r < 4; r++) {
                int gm = m_base + ((r >> 1) << 3);
                int gn = n_base + (r & 1);
                if (gn >= N) continue;
                float v = acc[mi][ni][r];
                if (MODE == 0) {
                    if (bias) v += biasScale * bias[gn];
                    if (RND) v = rnd32(v);
                    C[(long long)gm * N + gn] = v;
                } else if (MODE == 1) {
                    long long br = (long long)(gm >> 5) * biasStride + gn;
                    C [(long long)gm * N + gn] = tanhf(v + bias [br]);
                    C2[(long long)gm * N + gn] = tanhf(v + bias2[br]);
                } else {
                    v *= bias[(long long)zb * biasStride + gm];
                    if (RND) v = rnd32(v);
                    C[(long long)gm * N + gn] = v;
                }
            }
        }
    }
}

__global__ void reduce_add_kernel(const float* __restrict__ src, float* __restrict__ dst,
                                  int parts, long long len)
{
    long long i = (long long)blockIdx.x * 256 + threadIdx.x;
    if (i >= len) return;
    float s = 0.f;
    for (int p = 0; p < parts; p++) s += src[(long long)p * len + i];
    dst[i] = s;
}

// ---------------- stage kernels ----------------
__global__ void rep_kernel(const float* __restrict__ seq, const int* __restrict__ ep)
{
    int bn = blockIdx.x;
    int b = bn / NENT, n = bn % NENT;
    int e0 = ep[(b * NENT + n) * MENT + 0];
    int e1 = ep[(b * NENT + n) * MENT + 1];
    int e2 = ep[(b * NENT + n) * MENT + 2];
    int e3 = ep[(b * NENT + n) * MENT + 3];
    const float* sb = seq + (long long)b * SEQ * HID;
    for (int h = threadIdx.x; h < HID; h += blockDim.x) {
        float v0 = sb[(long long)e0 * HID + h];
        float v1 = sb[(long long)e1 * HID + h];
        float v2 = sb[(long long)e2 * HID + h];
        float v3 = sb[(long long)e3 * HID + h];
        float m = fmaxf(fmaxf(v0, v1), fmaxf(v2, v3));
        float s = expf(v0 - m) + expf(v1 - m) + expf(v2 - m) + expf(v3 - m);
        d_rep[(b * NENT + n) * HID + h] = rnd32(m + logf(s));
    }
}

// round+copy inputs used as GEMM B operands (+ clf pad to 128 cols)
__global__ void roundcopy_kernel(const float* __restrict__ seq,
                                 const float* __restrict__ Wc,
                                 const float* __restrict__ Wa,
                                 const float* __restrict__ clf)
{
    const long long n1 = (long long)BATCH * SEQ * HID;
    const long long n2 = (long long)HID * WD;
    const long long n3 = (long long)WD * AD;
    const long long n4 = (long long)WD * NCP;
    long long idx = (long long)blockIdx.x * 256 + threadIdx.x;
    if (idx < n1) { d_seqR[idx] = rnd32(seq[idx]); return; }
    idx -= n1;
    if (idx < n2) { d_WcR[idx] = rnd32(Wc[idx]); return; }
    idx -= n2;
    if (idx < n3) { d_WaR[idx] = rnd32(Wa[idx]); return; }
    idx -= n3;
    if (idx < n4) {
        int row = (int)(idx >> 7), col = (int)(idx & (NCP - 1));
        d_clfR[idx] = (col < NC) ? rnd32(clf[row * NC + col]) : 0.f;
    }
}

__global__ void packA_kernel(const float* __restrict__ A_bl)
{
    int idx = blockIdx.x * 256 + threadIdx.x;
    if (idx >= WD * PP) return;
    int o = idx / PP, pq = idx % PP;
    d_Ablt[pq * WD + o] = rnd32(A_bl[idx]);
}

__global__ void packW_kernel(const float* __restrict__ W_s, const float* __restrict__ W_o)
{
    int idx = blockIdx.x * 256 + threadIdx.x;
    if (idx >= WD * WD) return;
    int k = idx / WD, j = idx % WD;
    d_Wso[(long long)k * (2 * WD) + j]      = rnd32(W_s[idx]);
    d_Wso[(long long)k * (2 * WD) + WD + j] = rnd32(W_o[idx]);
}

__global__ void ga_kernel(const float* __restrict__ att, const int* __restrict__ ep)
{
    int b = blockIdx.z;
    int n = blockIdx.y / HEADS, h = blockIdx.y % HEADS;
    int s = blockIdx.x * blockDim.x + threadIdx.x;
    const float* ab = att + ((long long)(b * HEADS + h)) * SEQ * SEQ;
    float a = 0.f;
    #pragma unroll
    for (int m = 0; m < MENT; m++) {
        int e = ep[(b * NENT + n) * MENT + m];
        a += ab[(long long)e * SEQ + s];
    }
    d_ga[((long long)((b * NENT + n) * HEADS + h)) * SEQ + s] = a;
}

__global__ __launch_bounds__(256) void pa_tiled_kernel()
{
    extern __shared__ float sm[];          // [0:12288) gi, [12288:24576) gj
    __shared__ float sred[16 * 8];
    int b = blockIdx.z, ti = blockIdx.y, tj = blockIdx.x;
    int tid = threadIdx.x, lane = tid & 31, w = tid >> 5;

    float psum[16];
    #pragma unroll
    for (int p = 0; p < 16; p++) psum[p] = 0.f;

    for (int c = 0; c < 4; c++) {
        int s0 = c * 256;
        for (int l = tid; l < 3072; l += 256) {
            int il = l / 768;
            int rem = l - il * 768;
            int h = rem / 64, sq = rem - h * 64;
            int smoff = (il * 12 + h) * 256 + sq * 4;
            *(float4*)&sm[smoff] =
                *(const float4*)&d_ga[(((long long)(b * NENT + ti * 4 + il) * HEADS + h) << 10) + s0 + sq * 4];
            *(float4*)&sm[12288 + smoff] =
                *(const float4*)&d_ga[(((long long)(b * NENT + tj * 4 + il) * HEADS + h) << 10) + s0 + sq * 4];
        }
        __syncthreads();

        float acc[16];
        #pragma unroll
        for (int p = 0; p < 16; p++) acc[p] = 0.f;
        #pragma unroll
        for (int h = 0; h < HEADS; h++) {
            float ai[4], bj[4];
            #pragma unroll
            for (int il = 0; il < 4; il++) ai[il] = sm[(il * 12 + h) * 256 + tid];
            #pragma unroll
            for (int jl = 0; jl < 4; jl++) bj[jl] = sm[12288 + (jl * 12 + h) * 256 + tid];
            #pragma unroll
            for (int il = 0; il < 4; il++)
                #pragma unroll
                for (int jl = 0; jl < 4; jl++)
                    acc[il * 4 + jl] += ai[il] * bj[jl];
        }
        #pragma unroll
        for (int il = 0; il < 4; il++)
            #pragma unroll
            for (int jl = 0; jl < 4; jl++) {
                int p = il * 4 + jl;
                int ij = (ti * 4 + il) * NENT + tj * 4 + jl;
                d_pa[((long long)(b * NPAIR + ij) << 10) + s0 + tid] = rnd32(acc[p]);
                psum[p] += acc[p];
            }
        __syncthreads();
    }

    #pragma unroll
    for (int p = 0; p < 16; p++) {
        #pragma unroll
        for (int o = 16; o > 0; o >>= 1)
            psum[p] += __shfl_xor_sync(~0u, psum[p], o);
    }
    if (lane == 0)
        #pragma unroll
        for (int p = 0; p < 16; p++) sred[p * 8 + w] = psum[p];
    __syncthreads();
    if (tid < 16) {
        float s = 0.f;
        #pragma unroll
        for (int ww = 0; ww < 8; ww++) s += sred[tid * 8 + ww];
        int il = tid >> 2, jl = tid & 3;
        int ij = (ti * 4 + il) * NENT + tj * 4 + jl;
        d_painv[b * NPAIR + ij] = 1.0f / s;
    }
}

__global__ __launch_bounds__(256) void P_kernel()
{
    __shared__ float zs[WD], zo[WD];
    long long row = blockIdx.x;
    for (int w = threadIdx.x; w < WD; w += 256) {
        zs[w] = d_Zs[row * WD + w];
        zo[w] = d_Zo[row * WD + w];
    }
    __syncthreads();
    int t = threadIdx.x;
    if (t < PP) {
        int p = t / DD, q = t % DD;
        float a = 0.f;
        #pragma unroll
        for (int k = 0; k < SPLITK; k++)
            a += zs[p * SPLITK + k] * zo[q * SPLITK + k];
        d_P[row * PP + t] = rnd32(a);
    }
}

__global__ __launch_bounds__(256) void e_kernel(const float* __restrict__ v_attn)
{
    int row = blockIdx.x;
    int tid = threadIdx.x;
    float val = tanhf(d_t[(long long)row * AD + tid]) * v_attn[tid];
    __shared__ float red[256];
    red[tid] = val;
    __syncthreads();
    for (int off = 128; off > 0; off >>= 1) {
        if (tid < off) red[tid] += red[tid + off];
        __syncthreads();
    }
    if (tid == 0) d_e[row] = red[0];
}

__global__ __launch_bounds__(1024) void softmax_kernel()
{
    int b = blockIdx.x;
    int tid = threadIdx.x;
    int w = tid >> 5, lane = tid & 31;
    const float* eb = d_e + b * NPAIR;
    float v = eb[w * 32 + lane];
    float m = v;
    for (int o = 16; o > 0; o >>= 1) m = fmaxf(m, __shfl_xor_sync(~0u, m, o));
    float ex = expf(v - m);
    float s = ex;
    for (int o = 16; o > 0; o >>= 1) s += __shfl_xor_sync(~0u, s, o);
    d_arow[b * NPAIR + w * 32 + lane] = ex / s;
    float v2 = eb[lane * 32 + w];
    float m2 = v2;
    for (int o = 16; o > 0; o >>= 1) m2 = fmaxf(m2, __shfl_xor_sync(~0u, m2, o));
    float ex2 = expf(v2 - m2);
    float s2 = ex2;
    for (int o = 16; o > 0; o >>= 1) s2 += __shfl_xor_sync(~0u, s2, o);
    d_acol[b * NPAIR + lane * 32 + w] = ex2 / s2;
}

__global__ void rowcolC_kernel()
{
    int b = blockIdx.y, n = blockIdx.x;
    int c = threadIdx.x;
    if (c >= NC) return;
    const float* gc = d_gclf + (long long)b * NPAIR * NCP;
    float rs = 0.f, cs = 0.f;
    #pragma unroll 4
    for (int k = 0; k < NENT; k++) {
        rs += d_arow[b * NPAIR + n * 32 + k] * gc[(long long)(n * 32 + k) * NCP + c];
        cs += d_acol[b * NPAIR + k * 32 + n] * gc[(long long)(k * 32 + n) * NCP + c];
    }
    d_rgcg[(b * NENT + n) * NC + c] = rs;
    d_rgcg[(BATCH * NENT + b * NENT + n) * NC + c] = cs;
}

__global__ void final_kernel(const float* __restrict__ clf_b, float* __restrict__ out)
{
    long long idx = (long long)blockIdx.x * blockDim.x + threadIdx.x;
    const long long total = (long long)BATCH * NPAIR * NC;
    if (idx >= total) return;
    int c = (int)(idx % NC);
    long long rb = idx / NC;
    int ij = (int)(rb % NPAIR);
    int b = (int)(rb / NPAIR);
    int i = ij >> 5, j = ij & 31;
    out[idx] = d_gclf[rb * NCP + c]
             + d_rgcg[(b * NENT + i) * NC + c]
             + d_rgcg[(BATCH * NENT + b * NENT + j) * NC + c]
             + clf_b[c];
}

// ---------------- host launch ----------------
extern "C" void kernel_launch(void* const* d_in, const int* in_sizes, int n_in,
                              void* d_out, int out_size)
{
    const float* seq    = (const float*)d_in[0];
    const float* att    = (const float*)d_in[1];
    const int*   ep     = (const int*)  d_in[2];
    const float* W_s    = (const float*)d_in[3];
    const float* W_o    = (const float*)d_in[4];
    const float* W_c    = (const float*)d_in[5];
    const float* A_bl   = (const float*)d_in[6];
    const float* b_bl   = (const float*)d_in[7];
    const float* W_attn = (const float*)d_in[8];
    const float* v_attn = (const float*)d_in[9];
    const float* clf_W  = (const float*)d_in[10];
    const float* clf_b  = (const float*)d_in[11];
    float* out = (float*)d_out;

    float *p_rep, *p_rso, *p_Wso, *p_seqR, *p_WcR, *p_WaR, *p_clfR, *p_pa,
          *p_painv, *p_ctxh, *p_Zs, *p_Zo, *p_P, *p_Ablt, *p_g, *p_t,
          *p_gclf, *p_part;
    cudaGetSymbolAddress((void**)&p_rep,   d_rep);
    cudaGetSymbolAddress((void**)&p_rso,   d_rso);
    cudaGetSymbolAddress((void**)&p_Wso,   d_Wso);
    cudaGetSymbolAddress((void**)&p_seqR,  d_seqR);
    cudaGetSymbolAddress((void**)&p_WcR,   d_WcR);
    cudaGetSymbolAddress((void**)&p_WaR,   d_WaR);
    cudaGetSymbolAddress((void**)&p_clfR,  d_clfR);
    cudaGetSymbolAddress((void**)&p_pa,    d_pa);
    cudaGetSymbolAddress((void**)&p_painv, d_painv);
    cudaGetSymbolAddress((void**)&p_ctxh,  d_ctxh);
    cudaGetSymbolAddress((void**)&p_Zs,    d_Zs);
    cudaGetSymbolAddress((void**)&p_Zo,    d_Zo);
    cudaGetSymbolAddress((void**)&p_P,     d_P);
    cudaGetSymbolAddress((void**)&p_Ablt,  d_Ablt);
    cudaGetSymbolAddress((void**)&p_g,     d_g);
    cudaGetSymbolAddress((void**)&p_t,     d_t);
    cudaGetSymbolAddress((void**)&p_gclf,  d_gclf);
    cudaGetSymbolAddress((void**)&p_part,  d_part);

    static bool attrSet = false;
    if (!attrSet) {
        cudaFuncSetAttribute(pa_tiled_kernel,
                             cudaFuncAttributeMaxDynamicSharedMemorySize, 98304);
        attrSet = true;
    }

    // 0. entity attention gather
    {
        dim3 grid(SEQ / 256, NENT * HEADS, BATCH);
        ga_kernel<<<grid, 256>>>(att, ep);
    }
    // 1. pairwise localized attention (unnormalized, rounded) + reciprocal sums
    {
        dim3 grid(8, 8, BATCH);
        pa_tiled_kernel<<<grid, 256, 98304>>>();
    }
    // 2. round/copy B-side inputs (seq, W_c, W_attn, clf padded)
    {
        long long total = (long long)BATCH * SEQ * HID + (long long)HID * WD
                        + (long long)WD * AD + (long long)WD * NCP;
        roundcopy_kernel<<<(unsigned)((total + 255) / 256), 256>>>(seq, W_c, W_attn, clf_W);
    }
    // 3. ctxh = (pa @ seqR) * painv[row]  NWT=8 grid(6,8,4)=192
    {
        dim3 grid(WD / 128, NPAIR / 128, BATCH);
        mma_gemm<8, 2, 1><<<grid, 256>>>(p_pa, p_seqR, p_ctxh, nullptr,
                                         NPAIR, HID, SEQ,
                                         (long long)NPAIR * SEQ, (long long)SEQ * HID,
                                         (long long)NPAIR * HID,
                                         1, 0, p_painv, 0.f, nullptr, NPAIR);
    }
    // 4. entity reps (rounded)
    rep_kernel<<<BATCH * NENT, 256>>>(seq, ep);
    // 5-6. packs (rounded)
    packA_kernel<<<(WD * PP + 255) / 256, 256>>>(A_bl);
    packW_kernel<<<(WD * WD + 255) / 256, 256>>>(W_s, W_o);
    // 7. rso partials = rep @ [W_s|W_o]  split-K 6, NWT=4 grid(24,1,6)=144
    {
        dim3 grid((2 * WD) / 64, 1, 6);
        mma_gemm<4, 0, 0><<<grid, 256>>>(p_rep, p_Wso, p_part, nullptr,
                                         BATCH * NENT, 2 * WD, HID, 0, 0, 0,
                                         6, (long long)BATCH * NENT * 2 * WD,
                                         nullptr, 0.f, nullptr, 0);
    }
    // 8. reduce rso
    reduce_add_kernel<<<(BATCH * NENT * 2 * WD + 255) / 256, 256>>>(
        p_part, p_rso, 6, (long long)BATCH * NENT * 2 * WD);
    // 9. fused: Zs/Zo = tanh(rso[i] + ctxh @ WcR)  NWT=8 grid(6,32)=192
    {
        dim3 grid(WD / 128, (BATCH * NPAIR) / 128, 1);
        mma_gemm<8, 1, 0><<<grid, 256>>>(p_ctxh, p_WcR, p_Zs, p_Zo,
                                         BATCH * NPAIR, WD, HID, 0, 0, 0,
                                         1, 0, p_rso, 0.f, p_rso + WD, 2 * WD);
    }
    // 10. P (rounded)
    P_kernel<<<BATCH * NPAIR, 256>>>();
    // 11. g = P @ Ablt + 64*b_bl (rounded)  NWT=8 grid(6,32)=192
    {
        dim3 grid(WD / 128, (BATCH * NPAIR) / 128, 1);
        mma_gemm<8, 0, 1><<<grid, 256>>>(p_P, p_Ablt, p_g, nullptr,
                                         BATCH * NPAIR, WD, PP, 0, 0, 0,
                                         1, 0, b_bl, (float)SPLITK, nullptr, 0);
    }
    // 12. t = g @ WaR  NWT=4 grid(4,32)=128
    {
        dim3 grid(AD / 64, (BATCH * NPAIR) / 128, 1);
        mma_gemm<4, 0, 0><<<grid, 256>>>(p_g, p_WaR, p_t, nullptr,
                                         BATCH * NPAIR, AD, WD, 0, 0, 0,
                                         1, 0, nullptr, 0.f, nullptr, 0);
    }
    // 13. e = tanh(t) . v_attn
    e_kernel<<<BATCH * NPAIR, 256>>>(v_attn);
    // 14. softmax
    softmax_kernel<<<BATCH, 1024>>>();
    // 15. gclf partials = g @ clfR (padded N=128, split-K 4) grid(2,32,4)=256
    {
        long long len = (long long)BATCH * NPAIR * NCP;
        dim3 grid(NCP / 64, (BATCH * NPAIR) / 128, 4);
        mma_gemm<4, 0, 0><<<grid, 256>>>(p_g, p_clfR, p_part, nullptr,
                                         BATCH * NPAIR, NCP, WD, 0, 0, 0,
                                         4, len, nullptr, 0.f, nullptr, 0);
        reduce_add_kernel<<<(unsigned)((len + 255) / 256), 256>>>(p_part, p_gclf, 4, len);
    }
    // 16. axis-attention residual folded through clf_W
    {
        dim3 grid(NENT, BATCH);
        rowcolC_kernel<<<grid, 128>>>();
    }
    // 17. out
    {
        long long total = (long long)BATCH * NPAIR * NC;
        final_kernel<<<(unsigned)((total + 255) / 256), 256>>>(clf_b, out);
    }
}

// round 10
// speedup vs baseline: 1.0645x; 1.0348x over previous
#include <cuda_runtime.h>
#include <math.h>
#include <stdint.h>

#define BATCH 4
#define SEQ   1024
#define HID   768
#define HEADS 12
#define NENT  32
#define MENT  4
#define WD    768
#define AD    256
#define NC    97
#define NCP   128          // padded classifier width
#define SPLITK 64
#define DD    12
#define PP    144          // DD*DD
#define NPAIR (NENT*NENT)  // 1024

// ---------------- device scratch ----------------
__device__ float d_rep[BATCH*NENT*HID];
__device__ float d_rso[BATCH*NENT*2*WD];
__device__ float d_Wso[WD*2*WD];
__device__ float d_seqR[(size_t)BATCH*SEQ*HID];   // tf32-rounded seq
__device__ float d_WcR[HID*WD];
__device__ float d_WaR[WD*AD];
__device__ float d_clfR[WD*NCP];                  // rounded + padded clf_W
__device__ float d_ga [BATCH*NENT*HEADS*SEQ];
__device__ float d_pa [(size_t)BATCH*NPAIR*SEQ];  // unnormalized, tf32-rounded
__device__ float d_painv[BATCH*NPAIR];
__device__ float d_ctxh[(size_t)BATCH*NPAIR*HID];
__device__ float d_Zs [(size_t)BATCH*NPAIR*WD];
__device__ float d_Zo [(size_t)BATCH*NPAIR*WD];
__device__ float d_P  [(size_t)BATCH*NPAIR*PP];
__device__ float d_g  [(size_t)BATCH*NPAIR*WD];
__device__ float d_t  [(size_t)BATCH*NPAIR*AD];
__device__ float d_e  [BATCH*NPAIR];
__device__ float d_arow[BATCH*NPAIR];
__device__ float d_acol[BATCH*NPAIR];
__device__ float d_Ablt[PP*WD];
__device__ float d_gclf[(size_t)BATCH*NPAIR*NCP];
__device__ float d_rgcg[2*BATCH*NENT*NC];
__device__ float d_part[2200000];                 // split-K partials

// ---------------- helpers ----------------
__device__ __forceinline__ uint32_t f2tf32(float x)
{
    uint32_t r;
    asm("cvt.rna.tf32.f32 %0, %1;" : "=r"(r) : "f"(x));
    return r;
}
__device__ __forceinline__ float rnd32(float x) { return __uint_as_float(f2tf32(x)); }

__device__ __forceinline__ void mma_tf32(float* c, const uint32_t* a, const uint32_t* b)
{
    asm volatile(
        "mma.sync.aligned.m16n8k8.row.col.f32.tf32.tf32.f32 "
        "{%0,%1,%2,%3}, {%4,%5,%6,%7}, {%8,%9}, {%0,%1,%2,%3};"
        : "+f"(c[0]), "+f"(c[1]), "+f"(c[2]), "+f"(c[3])
        : "r"(a[0]), "r"(a[1]), "r"(a[2]), "r"(a[3]), "r"(b[0]), "r"(b[1]));
}

__device__ __forceinline__ void cp16(uint32_t smem, const void* g)
{
    asm volatile("cp.async.cg.shared.global [%0], [%1], 16;" :: "r"(smem), "l"(g));
}
__device__ __forceinline__ uint32_t smem_u32(const void* p)
{
    return (uint32_t)__cvta_generic_to_shared(p);
}

// ---------------- 3-stage cp.async pipelined tf32 GEMM ----------------
// C[M,N] = A[M,K] row * B[K,N] row, operands pre-rounded to tf32.
// BM=128, BN=16*NWT (NWT=4 -> 64), BK=16. 8 warps: 4 m x 2 n, warp tile 32x32.
// Canonical padded smem (conflict-free fragment LDS); 3-stage cp.async ring,
// wait_group 1 steady state. __launch_bounds__(256,3): 3 blocks/SM (24 warps)
// so barrier/scoreboard stalls in one block are covered by the other two.
// MODE 0: C = acc (+ biasScale*bias[n]); MODE 1: tanh(acc + bias/bias2[(gm>>5)*bS+gn]) -> C,C2;
// MODE 2: C = acc * bias[zb*bS+gm].  RND: round stored C to tf32.
// Requirements: M%128==0, (K/kSplit)%16==0, N%4==0, K/kSplit>=32.
#define AS_STRIDE 20
template<int NWT, int MODE, int RND>
__global__ __launch_bounds__(256, 3)
void mma_gemm(const float* __restrict__ A, const float* __restrict__ B,
              float* __restrict__ C, float* __restrict__ C2,
              int M, int N, int K,
              long long sA, long long sB, long long sC,
              int kSplit, long long partStride,
              const float* __restrict__ bias, float biasScale,
              const float* __restrict__ bias2, int biasStride)
{
    const int BN  = 16 * NWT;
    const int BSS = BN + 8;
    const int NBQ = BN / 4;              // float4 quads per B row
    const int NB  = (16 * NBQ) / 256;    // B cp.asyncs per thread
    __shared__ uint32_t As[3][128 * AS_STRIDE];
    __shared__ float    Bs[3][16 * BSS];

    int zb = blockIdx.z / kSplit;
    int kz = blockIdx.z - zb * kSplit;
    A += (long long)zb * sA;
    B += (long long)zb * sB;
    C += (long long)zb * sC + (long long)kz * partStride;

    int row0 = blockIdx.y * 128;
    int col0 = blockIdx.x * BN;
    int tid = threadIdx.x, lane = tid & 31, w = tid >> 5;
    int wm = w & 3, wn = w >> 2;
    int g = lane >> 2, t = lane & 3;

    int kLen = K / kSplit;
    int k0beg = kz * kLen, k0end = k0beg + kLen;

    float acc[2][NWT][4];
    #pragma unroll
    for (int i = 0; i < 2; i++)
        #pragma unroll
        for (int j = 0; j < NWT; j++)
            #pragma unroll
            for (int r = 0; r < 4; r++) acc[i][j][r] = 0.f;

    int am0 = tid >> 2, akq = tid & 3;

    const float* gA0 = A + (long long)(row0 + am0) * K + akq * 4;
    const float* gA1 = gA0 + (long long)64 * K;
    uint32_t asA0 = smem_u32(&As[0][am0 * AS_STRIDE + akq * 4]);
    uint32_t asA1 = smem_u32(&As[0][(am0 + 64) * AS_STRIDE + akq * 4]);
    const uint32_t strA = 128 * AS_STRIDE * 4;
    const uint32_t strB = 16 * BSS * 4;

    const float* gB[NB];
    uint32_t bsD[NB];
    #pragma unroll
    for (int nb = 0; nb < NB; nb++) {
        int l = tid + nb * 256;
        int kl = l / NBQ, nq = l % NBQ;
        gB[nb]  = B + (long long)kl * N + col0 + nq * 4;
        bsD[nb] = smem_u32(&Bs[0][kl * BSS + nq * 4]);
    }

    // prologue: issue tiles 0 and 1 into stages 0 and 1
    {
        cp16(asA0, gA0 + k0beg);
        cp16(asA1, gA1 + k0beg);
        #pragma unroll
        for (int nb = 0; nb < NB; nb++)
            cp16(bsD[nb], gB[nb] + (long long)k0beg * N);
        asm volatile("cp.async.commit_group;");
        int k1 = k0beg + 16;
        if (k1 < k0end) {
            cp16(asA0 + strA, gA0 + k1);
            cp16(asA1 + strA, gA1 + k1);
            #pragma unroll
            for (int nb = 0; nb < NB; nb++)
                cp16(bsD[nb] + strB, gB[nb] + (long long)k1 * N);
            asm volatile("cp.async.commit_group;");
        }
    }

    int buf = 0;   // stage holding tile being computed (tile i -> stage i%3)
    for (int k0 = k0beg; k0 < k0end; k0 += 16) {
        if (k0 + 16 < k0end)
            asm volatile("cp.async.wait_group 1;");
        else
            asm volatile("cp.async.wait_group 0;");
        __syncthreads();

        int kn = k0 + 32;
        if (kn < k0end) {
            int wbuf = buf + 2; if (wbuf >= 3) wbuf -= 3;
            uint32_t ao = (uint32_t)wbuf * strA;
            uint32_t bo = (uint32_t)wbuf * strB;
            cp16(asA0 + ao, gA0 + kn);
            cp16(asA1 + ao, gA1 + kn);
            #pragma unroll
            for (int nb = 0; nb < NB; nb++)
                cp16(bsD[nb] + bo, gB[nb] + (long long)kn * N);
            asm volatile("cp.async.commit_group;");
        }

        const uint32_t* as = As[buf];
        const float*    bs = Bs[buf];
        #pragma unroll
        for (int k8 = 0; k8 < 2; k8++) {
            int kb = k8 * 8;
            uint32_t a[2][4];
            #pragma unroll
            for (int mi = 0; mi < 2; mi++) {
                int mb = wm * 32 + mi * 16;
                a[mi][0] = as[(mb + g)     * AS_STRIDE + kb + t];
                a[mi][1] = as[(mb + g + 8) * AS_STRIDE + kb + t];
                a[mi][2] = as[(mb + g)     * AS_STRIDE + kb + t + 4];
                a[mi][3] = as[(mb + g + 8) * AS_STRIDE + kb + t + 4];
            }
            uint32_t b[NWT][2];
            #pragma unroll
            for (int ni = 0; ni < NWT; ni++) {
                int nb_ = wn * 8 * NWT + ni * 8 + g;
                b[ni][0] = __float_as_uint(bs[(kb + t)     * BSS + nb_]);
                b[ni][1] = __float_as_uint(bs[(kb + t + 4) * BSS + nb_]);
            }
            #pragma unroll
            for (int mi = 0; mi < 2; mi++)
                #pragma unroll
                for (int ni = 0; ni < NWT; ni++)
                    mma_tf32(acc[mi][ni], a[mi], b[ni]);
        }
        buf++; if (buf >= 3) buf = 0;
    }

    // ---- epilogue ----
    #pragma unroll
    for (int mi = 0; mi < 2; mi++) {
        #pragma unroll
        for (int ni = 0; ni < NWT; ni++) {
            int m_base = row0 + wm * 32 + mi * 16 + g;
            int n_base = col0 + wn * 8 * NWT + ni * 8 + t * 2;
            #pragma unroll
            for (int r = 0; r < 4; r++) {
                int gm = m_base + ((r >> 1) << 3);
                int gn = n_base + (r & 1);
                if (gn >= N) continue;
                float v = acc[mi][ni][r];
                if (MODE == 0) {
                    if (bias) v += biasScale * bias[gn];
                    if (RND) v = rnd32(v);
                    C[(long long)gm * N + gn] = v;
                } else if (MODE == 1) {
                    long long br = (long long)(gm >> 5) * biasStride + gn;
                    C [(long long)gm * N + gn] = tanhf(v + bias [br]);
                    C2[(long long)gm * N + gn] = tanhf(v + bias2[br]);
                } else {
                    v *= bias[(long long)zb * biasStride + gm];
                    if (RND) v = rnd32(v);
                    C[(long long)gm * N + gn] = v;
                }
            }
        }
    }
}

__global__ void reduce_add_kernel(const float* __restrict__ src, float* __restrict__ dst,
                                  int parts, long long len)
{
    long long i = (long long)blockIdx.x * 256 + threadIdx.x;
    if (i >= len) return;
    float s = 0.f;
    for (int p = 0; p < parts; p++) s += src[(long long)p * len + i];
    dst[i] = s;
}

// ---------------- stage kernels ----------------
__global__ void rep_kernel(const float* __restrict__ seq, const int* __restrict__ ep)
{
    int bn = blockIdx.x;
    int b = bn / NENT, n = bn % NENT;
    int e0 = ep[(b * NENT + n) * MENT + 0];
    int e1 = ep[(b * NENT + n) * MENT + 1];
    int e2 = ep[(b * NENT + n) * MENT + 2];
    int e3 = ep[(b * NENT + n) * MENT + 3];
    const float* sb = seq + (long long)b * SEQ * HID;
    for (int h = threadIdx.x; h < HID; h += blockDim.x) {
        float v0 = sb[(long long)e0 * HID + h];
        float v1 = sb[(long long)e1 * HID + h];
        float v2 = sb[(long long)e2 * HID + h];
        float v3 = sb[(long long)e3 * HID + h];
        float m = fmaxf(fmaxf(v0, v1), fmaxf(v2, v3));
        float s = expf(v0 - m) + expf(v1 - m) + expf(v2 - m) + expf(v3 - m);
        d_rep[(b * NENT + n) * HID + h] = rnd32(m + logf(s));
    }
}

// round+copy inputs used as GEMM B operands (+ clf pad to 128 cols)
__global__ void roundcopy_kernel(const float* __restrict__ seq,
                                 const float* __restrict__ Wc,
                                 const float* __restrict__ Wa,
                                 const float* __restrict__ clf)
{
    const long long n1 = (long long)BATCH * SEQ * HID;
    const long long n2 = (long long)HID * WD;
    const long long n3 = (long long)WD * AD;
    const long long n4 = (long long)WD * NCP;
    long long idx = (long long)blockIdx.x * 256 + threadIdx.x;
    if (idx < n1) { d_seqR[idx] = rnd32(seq[idx]); return; }
    idx -= n1;
    if (idx < n2) { d_WcR[idx] = rnd32(Wc[idx]); return; }
    idx -= n2;
    if (idx < n3) { d_WaR[idx] = rnd32(Wa[idx]); return; }
    idx -= n3;
    if (idx < n4) {
        int row = (int)(idx >> 7), col = (int)(idx & (NCP - 1));
        d_clfR[idx] = (col < NC) ? rnd32(clf[row * NC + col]) : 0.f;
    }
}

__global__ void packA_kernel(const float* __restrict__ A_bl)
{
    int idx = blockIdx.x * 256 + threadIdx.x;
    if (idx >= WD * PP) return;
    int o = idx / PP, pq = idx % PP;
    d_Ablt[pq * WD + o] = rnd32(A_bl[idx]);
}

__global__ void packW_kernel(const float* __restrict__ W_s, const float* __restrict__ W_o)
{
    int idx = blockIdx.x * 256 + threadIdx.x;
    if (idx >= WD * WD) return;
    int k = idx / WD, j = idx % WD;
    d_Wso[(long long)k * (2 * WD) + j]      = rnd32(W_s[idx]);
    d_Wso[(long long)k * (2 * WD) + WD + j] = rnd32(W_o[idx]);
}

__global__ void ga_kernel(const float* __restrict__ att, const int* __restrict__ ep)
{
    int b = blockIdx.z;
    int n = blockIdx.y / HEADS, h = blockIdx.y % HEADS;
    int s = blockIdx.x * blockDim.x + threadIdx.x;
    const float* ab = att + ((long long)(b * HEADS + h)) * SEQ * SEQ;
    float a = 0.f;
    #pragma unroll
    for (int m = 0; m < MENT; m++) {
        int e = ep[(b * NENT + n) * MENT + m];
        a += ab[(long long)e * SEQ + s];
    }
    d_ga[((long long)((b * NENT + n) * HEADS + h)) * SEQ + s] = a;
}

__global__ __launch_bounds__(256) void pa_tiled_kernel()
{
    extern __shared__ float sm[];          // [0:12288) gi, [12288:24576) gj
    __shared__ float sred[16 * 8];
    int b = blockIdx.z, ti = blockIdx.y, tj = blockIdx.x;
    int tid = threadIdx.x, lane = tid & 31, w = tid >> 5;

    float psum[16];
    #pragma unroll
    for (int p = 0; p < 16; p++) psum[p] = 0.f;

    for (int c = 0; c < 4; c++) {
        int s0 = c * 256;
        for (int l = tid; l < 3072; l += 256) {
            int il = l / 768;
            int rem = l - il * 768;
            int h = rem / 64, sq = rem - h * 64;
            int smoff = (il * 12 + h) * 256 + sq * 4;
            *(float4*)&sm[smoff] =
                *(const float4*)&d_ga[(((long long)(b * NENT + ti * 4 + il) * HEADS + h) << 10) + s0 + sq * 4];
            *(float4*)&sm[12288 + smoff] =
                *(const float4*)&d_ga[(((long long)(b * NENT + tj * 4 + il) * HEADS + h) << 10) + s0 + sq * 4];
        }
        __syncthreads();

        float acc[16];
        #pragma unroll
        for (int p = 0; p < 16; p++) acc[p] = 0.f;
        #pragma unroll
        for (int h = 0; h < HEADS; h++) {
            float ai[4], bj[4];
            #pragma unroll
            for (int il = 0; il < 4; il++) ai[il] = sm[(il * 12 + h) * 256 + tid];
            #pragma unroll
            for (int jl = 0; jl < 4; jl++) bj[jl] = sm[12288 + (jl * 12 + h) * 256 + tid];
            #pragma unroll
            for (int il = 0; il < 4; il++)
                #pragma unroll
                for (int jl = 0; jl < 4; jl++)
                    acc[il * 4 + jl] += ai[il] * bj[jl];
        }
        #pragma unroll
        for (int il = 0; il < 4; il++)
            #pragma unroll
            for (int jl = 0; jl < 4; jl++) {
                int p = il * 4 + jl;
                int ij = (ti * 4 + il) * NENT + tj * 4 + jl;
                d_pa[((long long)(b * NPAIR + ij) << 10) + s0 + tid] = rnd32(acc[p]);
                psum[p] += acc[p];
            }
        __syncthreads();
    }

    #pragma unroll
    for (int p = 0; p < 16; p++) {
        #pragma unroll
        for (int o = 16; o > 0; o >>= 1)
            psum[p] += __shfl_xor_sync(~0u, psum[p], o);
    }
    if (lane == 0)
        #pragma unroll
        for (int p = 0; p < 16; p++) sred[p * 8 + w] = psum[p];
    __syncthreads();
    if (tid < 16) {
        float s = 0.f;
        #pragma unroll
        for (int ww = 0; ww < 8; ww++) s += sred[tid * 8 + ww];
        int il = tid >> 2, jl = tid & 3;
        int ij = (ti * 4 + il) * NENT + tj * 4 + jl;
        d_painv[b * NPAIR + ij] = 1.0f / s;
    }
}

__global__ __launch_bounds__(256) void P_kernel()
{
    __shared__ float zs[WD], zo[WD];
    long long row = blockIdx.x;
    for (int w = threadIdx.x; w < WD; w += 256) {
        zs[w] = d_Zs[row * WD + w];
        zo[w] = d_Zo[row * WD + w];
    }
    __syncthreads();
    int t = threadIdx.x;
    if (t < PP) {
        int p = t / DD, q = t % DD;
        float a = 0.f;
        #pragma unroll
        for (int k = 0; k < SPLITK; k++)
            a += zs[p * SPLITK + k] * zo[q * SPLITK + k];
        d_P[row * PP + t] = rnd32(a);
    }
}

__global__ __launch_bounds__(256) void e_kernel(const float* __restrict__ v_attn)
{
    int row = blockIdx.x;
    int tid = threadIdx.x;
    float val = tanhf(d_t[(long long)row * AD + tid]) * v_attn[tid];
    __shared__ float red[256];
    red[tid] = val;
    __syncthreads();
    for (int off = 128; off > 0; off >>= 1) {
        if (tid < off) red[tid] += red[tid + off];
        __syncthreads();
    }
    if (tid == 0) d_e[row] = red[0];
}

__global__ __launch_bounds__(1024) void softmax_kernel()
{
    int b = blockIdx.x;
    int tid = threadIdx.x;
    int w = tid >> 5, lane = tid & 31;
    const float* eb = d_e + b * NPAIR;
    float v = eb[w * 32 + lane];
    float m = v;
    for (int o = 16; o > 0; o >>= 1) m = fmaxf(m, __shfl_xor_sync(~0u, m, o));
    float ex = expf(v - m);
    float s = ex;
    for (int o = 16; o > 0; o >>= 1) s += __shfl_xor_sync(~0u, s, o);
    d_arow[b * NPAIR + w * 32 + lane] = ex / s;
    float v2 = eb[lane * 32 + w];
    float m2 = v2;
    for (int o = 16; o > 0; o >>= 1) m2 = fmaxf(m2, __shfl_xor_sync(~0u, m2, o));
    float ex2 = expf(v2 - m2);
    float s2 = ex2;
    for (int o = 16; o > 0; o >>= 1) s2 += __shfl_xor_sync(~0u, s2, o);
    d_acol[b * NPAIR + lane * 32 + w] = ex2 / s2;
}

__global__ void rowcolC_kernel()
{
    int b = blockIdx.y, n = blockIdx.x;
    int c = threadIdx.x;
    if (c >= NC) return;
    const float* gc = d_gclf + (long long)b * NPAIR * NCP;
    float rs = 0.f, cs = 0.f;
    #pragma unroll 4
    for (int k = 0; k < NENT; k++) {
        rs += d_arow[b * NPAIR + n * 32 + k] * gc[(long long)(n * 32 + k) * NCP + c];
        cs += d_acol[b * NPAIR + k * 32 + n] * gc[(long long)(k * 32 + n) * NCP + c];
    }
    d_rgcg[(b * NENT + n) * NC + c] = rs;
    d_rgcg[(BATCH * NENT + b * NENT + n) * NC + c] = cs;
}

__global__ void final_kernel(const float* __restrict__ clf_b, float* __restrict__ out)
{
    long long idx = (long long)blockIdx.x * blockDim.x + threadIdx.x;
    const long long total = (long long)BATCH * NPAIR * NC;
    if (idx >= total) return;
    int c = (int)(idx % NC);
    long long rb = idx / NC;
    int ij = (int)(rb % NPAIR);
    int b = (int)(rb / NPAIR);
    int i = ij >> 5, j = ij & 31;
    out[idx] = d_gclf[rb * NCP + c]
             + d_rgcg[(b * NENT + i) * NC + c]
             + d_rgcg[(BATCH * NENT + b * NENT + j) * NC + c]
             + clf_b[c];
}

// ---------------- host launch ----------------
extern "C" void kernel_launch(void* const* d_in, const int* in_sizes, int n_in,
                              void* d_out, int out_size)
{
    const float* seq    = (const float*)d_in[0];
    const float* att    = (const float*)d_in[1];
    const int*   ep     = (const int*)  d_in[2];
    const float* W_s    = (const float*)d_in[3];
    const float* W_o    = (const float*)d_in[4];
    const float* W_c    = (const float*)d_in[5];
    const float* A_bl   = (const float*)d_in[6];
    const float* b_bl   = (const float*)d_in[7];
    const float* W_attn = (const float*)d_in[8];
    const float* v_attn = (const float*)d_in[9];
    const float* clf_W  = (const float*)d_in[10];
    const float* clf_b  = (const float*)d_in[11];
    float* out = (float*)d_out;

    float *p_rep, *p_rso, *p_Wso, *p_seqR, *p_WcR, *p_WaR, *p_clfR, *p_pa,
          *p_painv, *p_ctxh, *p_Zs, *p_Zo, *p_P, *p_Ablt, *p_g, *p_t,
          *p_gclf, *p_part;
    cudaGetSymbolAddress((void**)&p_rep,   d_rep);
    cudaGetSymbolAddress((void**)&p_rso,   d_rso);
    cudaGetSymbolAddress((void**)&p_Wso,   d_Wso);
    cudaGetSymbolAddress((void**)&p_seqR,  d_seqR);
    cudaGetSymbolAddress((void**)&p_WcR,   d_WcR);
    cudaGetSymbolAddress((void**)&p_WaR,   d_WaR);
    cudaGetSymbolAddress((void**)&p_clfR,  d_clfR);
    cudaGetSymbolAddress((void**)&p_pa,    d_pa);
    cudaGetSymbolAddress((void**)&p_painv, d_painv);
    cudaGetSymbolAddress((void**)&p_ctxh,  d_ctxh);
    cudaGetSymbolAddress((void**)&p_Zs,    d_Zs);
    cudaGetSymbolAddress((void**)&p_Zo,    d_Zo);
    cudaGetSymbolAddress((void**)&p_P,     d_P);
    cudaGetSymbolAddress((void**)&p_Ablt,  d_Ablt);
    cudaGetSymbolAddress((void**)&p_g,     d_g);
    cudaGetSymbolAddress((void**)&p_t,     d_t);
    cudaGetSymbolAddress((void**)&p_gclf,  d_gclf);
    cudaGetSymbolAddress((void**)&p_part,  d_part);

    static bool attrSet = false;
    if (!attrSet) {
        cudaFuncSetAttribute(pa_tiled_kernel,
                             cudaFuncAttributeMaxDynamicSharedMemorySize, 98304);
        attrSet = true;
    }

    // 0. entity attention gather
    {
        dim3 grid(SEQ / 256, NENT * HEADS, BATCH);
        ga_kernel<<<grid, 256>>>(att, ep);
    }
    // 1. pairwise localized attention (unnormalized, rounded) + reciprocal sums
    {
        dim3 grid(8, 8, BATCH);
        pa_tiled_kernel<<<grid, 256, 98304>>>();
    }
    // 2. round/copy B-side inputs (seq, W_c, W_attn, clf padded)
    {
        long long total = (long long)BATCH * SEQ * HID + (long long)HID * WD
                        + (long long)WD * AD + (long long)WD * NCP;
        roundcopy_kernel<<<(unsigned)((total + 255) / 256), 256>>>(seq, W_c, W_attn, clf_W);
    }
    // 3. ctxh = (pa @ seqR) * painv[row]  NWT=4 grid(12,8,4)=384
    {
        dim3 grid(WD / 64, NPAIR / 128, BATCH);
        mma_gemm<4, 2, 1><<<grid, 256>>>(p_pa, p_seqR, p_ctxh, nullptr,
                                         NPAIR, HID, SEQ,
                                         (long long)NPAIR * SEQ, (long long)SEQ * HID,
                                         (long long)NPAIR * HID,
                                         1, 0, p_painv, 0.f, nullptr, NPAIR);
    }
    // 4. entity reps (rounded)
    rep_kernel<<<BATCH * NENT, 256>>>(seq, ep);
    // 5-6. packs (rounded)
    packA_kernel<<<(WD * PP + 255) / 256, 256>>>(A_bl);
    packW_kernel<<<(WD * WD + 255) / 256, 256>>>(W_s, W_o);
    // 7. rso partials = rep @ [W_s|W_o]  split-K 6, NWT=4 grid(24,1,6)=144
    {
        dim3 grid((2 * WD) / 64, 1, 6);
        mma_gemm<4, 0, 0><<<grid, 256>>>(p_rep, p_Wso, p_part, nullptr,
                                         BATCH * NENT, 2 * WD, HID, 0, 0, 0,
                                         6, (long long)BATCH * NENT * 2 * WD,
                                         nullptr, 0.f, nullptr, 0);
    }
    // 8. reduce rso
    reduce_add_kernel<<<(BATCH * NENT * 2 * WD + 255) / 256, 256>>>(
        p_part, p_rso, 6, (long long)BATCH * NENT * 2 * WD);
    // 9. fused: Zs/Zo = tanh(rso[i] + ctxh @ WcR)  NWT=4 grid(12,32)=384
    {
        dim3 grid(WD / 64, (BATCH * NPAIR) / 128, 1);
        mma_gemm<4, 1, 0><<<grid, 256>>>(p_ctxh, p_WcR, p_Zs, p_Zo,
                                         BATCH * NPAIR, WD, HID, 0, 0, 0,
                                         1, 0, p_rso, 0.f, p_rso + WD, 2 * WD);
    }
    // 10. P (rounded)
    P_kernel<<<BATCH * NPAIR, 256>>>();
    // 11. g = P @ Ablt + 64*b_bl (rounded)  NWT=4 grid(12,32)=384
    {
        dim3 grid(WD / 64, (BATCH * NPAIR) / 128, 1);
        mma_gemm<4, 0, 1><<<grid, 256>>>(p_P, p_Ablt, p_g, nullptr,
                                         BATCH * NPAIR, WD, PP, 0, 0, 0,
                                         1, 0, b_bl, (float)SPLITK, nullptr, 0);
    }
    // 12. t = g @ WaR  NWT=4 grid(4,32)=128
    {
        dim3 grid(AD / 64, (BATCH * NPAIR) / 128, 1);
        mma_gemm<4, 0, 0><<<grid, 256>>>(p_g, p_WaR, p_t, nullptr,
                                         BATCH * NPAIR, AD, WD, 0, 0, 0,
                                         1, 0, nullptr, 0.f, nullptr, 0);
    }
    // 13. e = tanh(t) . v_attn
    e_kernel<<<BATCH * NPAIR, 256>>>(v_attn);
    // 14. softmax
    softmax_kernel<<<BATCH, 1024>>>();
    // 15. gclf partials = g @ clfR (padded N=128, split-K 4) grid(2,32,4)=256
    {
        long long len = (long long)BATCH * NPAIR * NCP;
        dim3 grid(NCP / 64, (BATCH * NPAIR) / 128, 4);
        mma_gemm<4, 0, 0><<<grid, 256>>>(p_g, p_clfR, p_part, nullptr,
                                         BATCH * NPAIR, NCP, WD, 0, 0, 0,
                                         4, len, nullptr, 0.f, nullptr, 0);
        reduce_add_kernel<<<(unsigned)((len + 255) / 256), 256>>>(p_part, p_gclf, 4, len);
    }
    // 16. axis-attention residual folded through clf_W
    {
        dim3 grid(NENT, BATCH);
        rowcolC_kernel<<<grid, 128>>>();
    }
    // 17. out
    {
        long long total = (long long)BATCH * NPAIR * NC;
        final_kernel<<<(unsigned)((total + 255) / 256), 256>>>(clf_b, out);
    }
}

// round 11
// speedup vs baseline: 1.1540x; 1.0841x over previous
#include <cuda_runtime.h>
#include <math.h>
#include <stdint.h>

#define BATCH 4
#define SEQ   1024
#define HID   768
#define HEADS 12
#define NENT  32
#define MENT  4
#define WD    768
#define AD    256
#define NC    97
#define NCP   128          // padded classifier width
#define SPLITK 64
#define DD    12
#define PP    144          // DD*DD
#define PP2   160          // K-padded (zeros) for BK=32 GEMM
#define NPAIR (NENT*NENT)  // 1024

// ---------------- device scratch ----------------
__device__ float d_rep[BATCH*NENT*HID];
__device__ float d_rso[BATCH*NENT*2*WD];
__device__ float d_Wso[WD*2*WD];
__device__ float d_seqR[(size_t)BATCH*SEQ*HID];   // tf32-rounded seq
__device__ float d_WcR[HID*WD];
__device__ float d_WaR[WD*AD];
__device__ float d_clfR[WD*NCP];                  // rounded + padded clf_W
__device__ float d_ga [BATCH*NENT*HEADS*SEQ];
__device__ float d_pa [(size_t)BATCH*NPAIR*SEQ];  // unnormalized, tf32-rounded
__device__ float d_painv[BATCH*NPAIR];
__device__ float d_ctxh[(size_t)BATCH*NPAIR*HID];
__device__ float d_Zs [(size_t)BATCH*NPAIR*WD];
__device__ float d_Zo [(size_t)BATCH*NPAIR*WD];
__device__ float d_P  [(size_t)BATCH*NPAIR*PP2];  // cols 144..159 stay zero
__device__ float d_g  [(size_t)BATCH*NPAIR*WD];
__device__ float d_t  [(size_t)BATCH*NPAIR*AD];
__device__ float d_e  [BATCH*NPAIR];
__device__ float d_arow[BATCH*NPAIR];
__device__ float d_acol[BATCH*NPAIR];
__device__ float d_Ablt[PP2*WD];                  // rows 144..159 stay zero
__device__ float d_gclf[(size_t)BATCH*NPAIR*NCP];
__device__ float d_rgcg[2*BATCH*NENT*NC];
__device__ float d_part[2200000];                 // split-K partials

// ---------------- helpers ----------------
__device__ __forceinline__ uint32_t f2tf32(float x)
{
    uint32_t r;
    asm("cvt.rna.tf32.f32 %0, %1;" : "=r"(r) : "f"(x));
    return r;
}
__device__ __forceinline__ float rnd32(float x) { return __uint_as_float(f2tf32(x)); }

__device__ __forceinline__ void mma_tf32(float* c, const uint32_t* a, const uint32_t* b)
{
    asm volatile(
        "mma.sync.aligned.m16n8k8.row.col.f32.tf32.tf32.f32 "
        "{%0,%1,%2,%3}, {%4,%5,%6,%7}, {%8,%9}, {%0,%1,%2,%3};"
        : "+f"(c[0]), "+f"(c[1]), "+f"(c[2]), "+f"(c[3])
        : "r"(a[0]), "r"(a[1]), "r"(a[2]), "r"(a[3]), "r"(b[0]), "r"(b[1]));
}

__device__ __forceinline__ void cp16(uint32_t smem, const void* g)
{
    asm volatile("cp.async.cg.shared.global [%0], [%1], 16;" :: "r"(smem), "l"(g));
}
__device__ __forceinline__ uint32_t smem_u32(const void* p)
{
    return (uint32_t)__cvta_generic_to_shared(p);
}

// ---------------- BK=32 cp.async pipelined tf32 GEMM ----------------
// C[M,N] = A[M,K] row * B[K,N] row, operands pre-rounded to tf32.
// BM=128, BN=64, BK=32. 8 warps: 4 m x 2 n, warp tile 32x32.
// As[128][36] / Bs[32][72]: conflict-free cp.async stores AND fragment LDS.
// 2-stage ring, wait_group 0; 32 HMMA/warp between barriers (half the sync
// cadence of BK=16). 3 blocks/SM.
// MODE 0: C = acc (+ biasScale*bias[n]); MODE 1: tanh(acc + bias/bias2[(gm>>5)*bS+gn]) -> C,C2;
// MODE 2: C = acc * bias[zb*bS+gm].  RND: round stored C to tf32.
// Requirements: M%128==0, (K/kSplit)%32==0, N%4==0.
#define AS_STRIDE 36
#define BS_STRIDE 72
template<int MODE, int RND>
__global__ __launch_bounds__(256, 3)
void mma_gemm(const float* __restrict__ A, const float* __restrict__ B,
              float* __restrict__ C, float* __restrict__ C2,
              int M, int N, int K,
              long long sA, long long sB, long long sC,
              int kSplit, long long partStride,
              const float* __restrict__ bias, float biasScale,
              const float* __restrict__ bias2, int biasStride)
{
    const int NWT = 4;
    const int BN  = 64;
    __shared__ uint32_t As[2][128 * AS_STRIDE];   // 2 x 18 KB
    __shared__ float    Bs[2][32 * BS_STRIDE];    // 2 x 9 KB

    int zb = blockIdx.z / kSplit;
    int kz = blockIdx.z - zb * kSplit;
    A += (long long)zb * sA;
    B += (long long)zb * sB;
    C += (long long)zb * sC + (long long)kz * partStride;

    int row0 = blockIdx.y * 128;
    int col0 = blockIdx.x * BN;
    int tid = threadIdx.x, lane = tid & 31, w = tid >> 5;
    int wm = w & 3, wn = w >> 2;
    int g = lane >> 2, t = lane & 3;

    int kLen = K / kSplit;
    int k0beg = kz * kLen, k0end = k0beg + kLen;

    float acc[2][NWT][4];
    #pragma unroll
    for (int i = 0; i < 2; i++)
        #pragma unroll
        for (int j = 0; j < NWT; j++)
            #pragma unroll
            for (int r = 0; r < 4; r++) acc[i][j][r] = 0.f;

    // A: thread covers rows am, am+32, am+64, am+96 at k-quad ak (4 floats)
    int am = tid >> 3, ak = (tid & 7) * 4;
    const float* gA = A + (long long)(row0 + am) * K + ak;
    uint32_t asA = smem_u32(&As[0][am * AS_STRIDE + ak]);
    const uint32_t strideAstg = 128 * AS_STRIDE * 4;   // bytes per stage
    const uint32_t strideArow = 32 * AS_STRIDE * 4;    // bytes per 32-row pass

    // B: thread covers rows bk, bk+16 at n-quad bn
    int bk = tid >> 4, bn = (tid & 15) * 4;
    uint32_t bsB = smem_u32(&Bs[0][bk * BS_STRIDE + bn]);
    const uint32_t strideBstg = 32 * BS_STRIDE * 4;
    const uint32_t strideBrow = 16 * BS_STRIDE * 4;

    // prologue: issue tile 0 into stage 0
    {
        #pragma unroll
        for (int p = 0; p < 4; p++)
            cp16(asA + p * strideArow, gA + (long long)p * 32 * K + k0beg);
        #pragma unroll
        for (int p = 0; p < 2; p++)
            cp16(bsB + p * strideBrow,
                 B + (long long)(k0beg + bk + p * 16) * N + col0 + bn);
        asm volatile("cp.async.commit_group;");
    }

    int buf = 0;
    for (int k0 = k0beg; k0 < k0end; k0 += 32) {
        asm volatile("cp.async.wait_group 0;");
        __syncthreads();

        int kn = k0 + 32;
        if (kn < k0end) {
            uint32_t ao = (buf ^ 1) ? strideAstg : 0;
            uint32_t bo = (buf ^ 1) ? strideBstg : 0;
            #pragma unroll
            for (int p = 0; p < 4; p++)
                cp16(asA + ao + p * strideArow, gA + (long long)p * 32 * K + kn);
            #pragma unroll
            for (int p = 0; p < 2; p++)
                cp16(bsB + bo + p * strideBrow,
                     B + (long long)(kn + bk + p * 16) * N + col0 + bn);
            asm volatile("cp.async.commit_group;");
        }

        const uint32_t* as = As[buf];
        const float*    bs = Bs[buf];
        #pragma unroll
        for (int k8 = 0; k8 < 4; k8++) {
            int kb = k8 * 8;
            uint32_t a[2][4];
            #pragma unroll
            for (int mi = 0; mi < 2; mi++) {
                int mb = wm * 32 + mi * 16;
                a[mi][0] = as[(mb + g)     * AS_STRIDE + kb + t];
                a[mi][1] = as[(mb + g + 8) * AS_STRIDE + kb + t];
                a[mi][2] = as[(mb + g)     * AS_STRIDE + kb + t + 4];
                a[mi][3] = as[(mb + g + 8) * AS_STRIDE + kb + t + 4];
            }
            uint32_t b[NWT][2];
            #pragma unroll
            for (int ni = 0; ni < NWT; ni++) {
                int nb_ = wn * 32 + ni * 8 + g;
                b[ni][0] = __float_as_uint(bs[(kb + t)     * BS_STRIDE + nb_]);
                b[ni][1] = __float_as_uint(bs[(kb + t + 4) * BS_STRIDE + nb_]);
            }
            #pragma unroll
            for (int mi = 0; mi < 2; mi++)
                #pragma unroll
                for (int ni = 0; ni < NWT; ni++)
                    mma_tf32(acc[mi][ni], a[mi], b[ni]);
        }
        buf ^= 1;
    }

    // ---- epilogue ----
    #pragma unroll
    for (int mi = 0; mi < 2; mi++) {
        #pragma unroll
        for (int ni = 0; ni < NWT; ni++) {
            int m_base = row0 + wm * 32 + mi * 16 + g;
            int n_base = col0 + wn * 32 + ni * 8 + t * 2;
            #pragma unroll
            for (int r = 0; r < 4; r++) {
                int gm = m_base + ((r >> 1) << 3);
                int gn = n_base + (r & 1);
                if (gn >= N) continue;
                float v = acc[mi][ni][r];
                if (MODE == 0) {
                    if (bias) v += biasScale * bias[gn];
                    if (RND) v = rnd32(v);
                    C[(long long)gm * N + gn] = v;
                } else if (MODE == 1) {
                    long long br = (long long)(gm >> 5) * biasStride + gn;
                    C [(long long)gm * N + gn] = tanhf(v + bias [br]);
                    C2[(long long)gm * N + gn] = tanhf(v + bias2[br]);
                } else {
                    v *= bias[(long long)zb * biasStride + gm];
                    if (RND) v = rnd32(v);
                    C[(long long)gm * N + gn] = v;
                }
            }
        }
    }
}

__global__ void reduce_add_kernel(const float* __restrict__ src, float* __restrict__ dst,
                                  int parts, long long len)
{
    long long i = (long long)blockIdx.x * 256 + threadIdx.x;
    if (i >= len) return;
    float s = 0.f;
    for (int p = 0; p < parts; p++) s += src[(long long)p * len + i];
    dst[i] = s;
}

// ---------------- stage kernels ----------------
__global__ void rep_kernel(const float* __restrict__ seq, const int* __restrict__ ep)
{
    int bn = blockIdx.x;
    int b = bn / NENT, n = bn % NENT;
    int e0 = ep[(b * NENT + n) * MENT + 0];
    int e1 = ep[(b * NENT + n) * MENT + 1];
    int e2 = ep[(b * NENT + n) * MENT + 2];
    int e3 = ep[(b * NENT + n) * MENT + 3];
    const float* sb = seq + (long long)b * SEQ * HID;
    for (int h = threadIdx.x; h < HID; h += blockDim.x) {
        float v0 = sb[(long long)e0 * HID + h];
        float v1 = sb[(long long)e1 * HID + h];
        float v2 = sb[(long long)e2 * HID + h];
        float v3 = sb[(long long)e3 * HID + h];
        float m = fmaxf(fmaxf(v0, v1), fmaxf(v2, v3));
        float s = expf(v0 - m) + expf(v1 - m) + expf(v2 - m) + expf(v3 - m);
        d_rep[(b * NENT + n) * HID + h] = rnd32(m + logf(s));
    }
}

// round+copy ALL static operands in one launch:
// seq, W_c, W_attn, clf (padded), A_bl transpose, [W_s|W_o] pack
__global__ void prep_kernel(const float* __restrict__ seq,
                            const float* __restrict__ Wc,
                            const float* __restrict__ Wa,
                            const float* __restrict__ clf,
                            const float* __restrict__ A_bl,
                            const float* __restrict__ W_s,
                            const float* __restrict__ W_o)
{
    const long long n1 = (long long)BATCH * SEQ * HID;
    const long long n2 = (long long)HID * WD;
    const long long n3 = (long long)WD * AD;
    const long long n4 = (long long)WD * NCP;
    const long long n5 = (long long)WD * PP;
    const long long n6 = (long long)WD * WD;
    long long idx = (long long)blockIdx.x * 256 + threadIdx.x;
    if (idx < n1) { d_seqR[idx] = rnd32(seq[idx]); return; }
    idx -= n1;
    if (idx < n2) { d_WcR[idx] = rnd32(Wc[idx]); return; }
    idx -= n2;
    if (idx < n3) { d_WaR[idx] = rnd32(Wa[idx]); return; }
    idx -= n3;
    if (idx < n4) {
        int row = (int)(idx >> 7), col = (int)(idx & (NCP - 1));
        d_clfR[idx] = (col < NC) ? rnd32(clf[row * NC + col]) : 0.f;
        return;
    }
    idx -= n4;
    if (idx < n5) {
        int o = (int)(idx / PP), pq = (int)(idx % PP);
        d_Ablt[pq * WD + o] = rnd32(A_bl[idx]);
        return;
    }
    idx -= n5;
    if (idx < n6) {
        int k = (int)(idx / WD), j = (int)(idx % WD);
        d_Wso[(long long)k * (2 * WD) + j]      = rnd32(W_s[idx]);
        d_Wso[(long long)k * (2 * WD) + WD + j] = rnd32(W_o[idx]);
    }
}

__global__ void ga_kernel(const float* __restrict__ att, const int* __restrict__ ep)
{
    int b = blockIdx.z;
    int n = blockIdx.y / HEADS, h = blockIdx.y % HEADS;
    int s = blockIdx.x * blockDim.x + threadIdx.x;
    const float* ab = att + ((long long)(b * HEADS + h)) * SEQ * SEQ;
    float a = 0.f;
    #pragma unroll
    for (int m = 0; m < MENT; m++) {
        int e = ep[(b * NENT + n) * MENT + m];
        a += ab[(long long)e * SEQ + s];
    }
    d_ga[((long long)((b * NENT + n) * HEADS + h)) * SEQ + s] = a;
}

__global__ __launch_bounds__(256) void pa_tiled_kernel()
{
    extern __shared__ float sm[];          // [0:12288) gi, [12288:24576) gj
    __shared__ float sred[16 * 8];
    int b = blockIdx.z, ti = blockIdx.y, tj = blockIdx.x;
    int tid = threadIdx.x, lane = tid & 31, w = tid >> 5;

    float psum[16];
    #pragma unroll
    for (int p = 0; p < 16; p++) psum[p] = 0.f;

    for (int c = 0; c < 4; c++) {
        int s0 = c * 256;
        for (int l = tid; l < 3072; l += 256) {
            int il = l / 768;
            int rem = l - il * 768;
            int h = rem / 64, sq = rem - h * 64;
            int smoff = (il * 12 + h) * 256 + sq * 4;
            *(float4*)&sm[smoff] =
                *(const float4*)&d_ga[(((long long)(b * NENT + ti * 4 + il) * HEADS + h) << 10) + s0 + sq * 4];
            *(float4*)&sm[12288 + smoff] =
                *(const float4*)&d_ga[(((long long)(b * NENT + tj * 4 + il) * HEADS + h) << 10) + s0 + sq * 4];
        }
        __syncthreads();

        float acc[16];
        #pragma unroll
        for (int p = 0; p < 16; p++) acc[p] = 0.f;
        #pragma unroll
        for (int h = 0; h < HEADS; h++) {
            float ai[4], bj[4];
            #pragma unroll
            for (int il = 0; il < 4; il++) ai[il] = sm[(il * 12 + h) * 256 + tid];
            #pragma unroll
            for (int jl = 0; jl < 4; jl++) bj[jl] = sm[12288 + (jl * 12 + h) * 256 + tid];
            #pragma unroll
            for (int il = 0; il < 4; il++)
                #pragma unroll
                for (int jl = 0; jl < 4; jl++)
                    acc[il * 4 + jl] += ai[il] * bj[jl];
        }
        #pragma unroll
        for (int il = 0; il < 4; il++)
            #pragma unroll
            for (int jl = 0; jl < 4; jl++) {
                int p = il * 4 + jl;
                int ij = (ti * 4 + il) * NENT + tj * 4 + jl;
                d_pa[((long long)(b * NPAIR + ij) << 10) + s0 + tid] = rnd32(acc[p]);
                psum[p] += acc[p];
            }
        __syncthreads();
    }

    #pragma unroll
    for (int p = 0; p < 16; p++) {
        #pragma unroll
        for (int o = 16; o > 0; o >>= 1)
            psum[p] += __shfl_xor_sync(~0u, psum[p], o);
    }
    if (lane == 0)
        #pragma unroll
        for (int p = 0; p < 16; p++) sred[p * 8 + w] = psum[p];
    __syncthreads();
    if (tid < 16) {
        float s = 0.f;
        #pragma unroll
        for (int ww = 0; ww < 8; ww++) s += sred[tid * 8 + ww];
        int il = tid >> 2, jl = tid & 3;
        int ij = (ti * 4 + il) * NENT + tj * 4 + jl;
        d_painv[b * NPAIR + ij] = 1.0f / s;
    }
}

__global__ __launch_bounds__(256) void P_kernel()
{
    __shared__ float zs[WD], zo[WD];
    long long row = blockIdx.x;
    for (int w = threadIdx.x; w < WD; w += 256) {
        zs[w] = d_Zs[row * WD + w];
        zo[w] = d_Zo[row * WD + w];
    }
    __syncthreads();
    int t = threadIdx.x;
    if (t < PP) {
        int p = t / DD, q = t % DD;
        float a = 0.f;
        #pragma unroll
        for (int k = 0; k < SPLITK; k++)
            a += zs[p * SPLITK + k] * zo[q * SPLITK + k];
        d_P[row * PP2 + t] = rnd32(a);   // cols 144..159 remain zero
    }
}

__global__ __launch_bounds__(256) void e_kernel(const float* __restrict__ v_attn)
{
    int row = blockIdx.x;
    int tid = threadIdx.x;
    float val = tanhf(d_t[(long long)row * AD + tid]) * v_attn[tid];
    __shared__ float red[256];
    red[tid] = val;
    __syncthreads();
    for (int off = 128; off > 0; off >>= 1) {
        if (tid < off) red[tid] += red[tid + off];
        __syncthreads();
    }
    if (tid == 0) d_e[row] = red[0];
}

__global__ __launch_bounds__(1024) void softmax_kernel()
{
    int b = blockIdx.x;
    int tid = threadIdx.x;
    int w = tid >> 5, lane = tid & 31;
    const float* eb = d_e + b * NPAIR;
    float v = eb[w * 32 + lane];
    float m = v;
    for (int o = 16; o > 0; o >>= 1) m = fmaxf(m, __shfl_xor_sync(~0u, m, o));
    float ex = expf(v - m);
    float s = ex;
    for (int o = 16; o > 0; o >>= 1) s += __shfl_xor_sync(~0u, s, o);
    d_arow[b * NPAIR + w * 32 + lane] = ex / s;
    float v2 = eb[lane * 32 + w];
    float m2 = v2;
    for (int o = 16; o > 0; o >>= 1) m2 = fmaxf(m2, __shfl_xor_sync(~0u, m2, o));
    float ex2 = expf(v2 - m2);
    float s2 = ex2;
    for (int o = 16; o > 0; o >>= 1) s2 += __shfl_xor_sync(~0u, s2, o);
    d_acol[b * NPAIR + lane * 32 + w] = ex2 / s2;
}

__global__ void rowcolC_kernel()
{
    int b = blockIdx.y, n = blockIdx.x;
    int c = threadIdx.x;
    if (c >= NC) return;
    const float* gc = d_gclf + (long long)b * NPAIR * NCP;
    float rs = 0.f, cs = 0.f;
    #pragma unroll 4
    for (int k = 0; k < NENT; k++) {
        rs += d_arow[b * NPAIR + n * 32 + k] * gc[(long long)(n * 32 + k) * NCP + c];
        cs += d_acol[b * NPAIR + k * 32 + n] * gc[(long long)(k * 32 + n) * NCP + c];
    }
    d_rgcg[(b * NENT + n) * NC + c] = rs;
    d_rgcg[(BATCH * NENT + b * NENT + n) * NC + c] = cs;
}

__global__ void final_kernel(const float* __restrict__ clf_b, float* __restrict__ out)
{
    long long idx = (long long)blockIdx.x * blockDim.x + threadIdx.x;
    const long long total = (long long)BATCH * NPAIR * NC;
    if (idx >= total) return;
    int c = (int)(idx % NC);
    long long rb = idx / NC;
    int ij = (int)(rb % NPAIR);
    int b = (int)(rb / NPAIR);
    int i = ij >> 5, j = ij & 31;
    out[idx] = d_gclf[rb * NCP + c]
             + d_rgcg[(b * NENT + i) * NC + c]
             + d_rgcg[(BATCH * NENT + b * NENT + j) * NC + c]
             + clf_b[c];
}

// ---------------- host launch ----------------
extern "C" void kernel_launch(void* const* d_in, const int* in_sizes, int n_in,
                              void* d_out, int out_size)
{
    const float* seq    = (const float*)d_in[0];
    const float* att    = (const float*)d_in[1];
    const int*   ep     = (const int*)  d_in[2];
    const float* W_s    = (const float*)d_in[3];
    const float* W_o    = (const float*)d_in[4];
    const float* W_c    = (const float*)d_in[5];
    const float* A_bl   = (const float*)d_in[6];
    const float* b_bl   = (const float*)d_in[7];
    const float* W_attn = (const float*)d_in[8];
    const float* v_attn = (const float*)d_in[9];
    const float* clf_W  = (const float*)d_in[10];
    const float* clf_b  = (const float*)d_in[11];
    float* out = (float*)d_out;

    float *p_rep, *p_rso, *p_Wso, *p_seqR, *p_WcR, *p_WaR, *p_clfR, *p_pa,
          *p_painv, *p_ctxh, *p_Zs, *p_Zo, *p_P, *p_Ablt, *p_g, *p_t,
          *p_gclf, *p_part;
    cudaGetSymbolAddress((void**)&p_rep,   d_rep);
    cudaGetSymbolAddress((void**)&p_rso,   d_rso);
    cudaGetSymbolAddress((void**)&p_Wso,   d_Wso);
    cudaGetSymbolAddress((void**)&p_seqR,  d_seqR);
    cudaGetSymbolAddress((void**)&p_WcR,   d_WcR);
    cudaGetSymbolAddress((void**)&p_WaR,   d_WaR);
    cudaGetSymbolAddress((void**)&p_clfR,  d_clfR);
    cudaGetSymbolAddress((void**)&p_pa,    d_pa);
    cudaGetSymbolAddress((void**)&p_painv, d_painv);
    cudaGetSymbolAddress((void**)&p_ctxh,  d_ctxh);
    cudaGetSymbolAddress((void**)&p_Zs,    d_Zs);
    cudaGetSymbolAddress((void**)&p_Zo,    d_Zo);
    cudaGetSymbolAddress((void**)&p_P,     d_P);
    cudaGetSymbolAddress((void**)&p_Ablt,  d_Ablt);
    cudaGetSymbolAddress((void**)&p_g,     d_g);
    cudaGetSymbolAddress((void**)&p_t,     d_t);
    cudaGetSymbolAddress((void**)&p_gclf,  d_gclf);
    cudaGetSymbolAddress((void**)&p_part,  d_part);

    static bool attrSet = false;
    if (!attrSet) {
        cudaFuncSetAttribute(pa_tiled_kernel,
                             cudaFuncAttributeMaxDynamicSharedMemorySize, 98304);
        attrSet = true;
    }

    // 0. entity attention gather
    {
        dim3 grid(SEQ / 256, NENT * HEADS, BATCH);
        ga_kernel<<<grid, 256>>>(att, ep);
    }
    // 1. pairwise localized attention (unnormalized, rounded) + reciprocal sums
    {
        dim3 grid(8, 8, BATCH);
        pa_tiled_kernel<<<grid, 256, 98304>>>();
    }
    // 2. prep: round/copy/pack all static operands (one launch)
    {
        long long total = (long long)BATCH * SEQ * HID + (long long)HID * WD
                        + (long long)WD * AD + (long long)WD * NCP
                        + (long long)WD * PP + (long long)WD * WD;
        prep_kernel<<<(unsigned)((total + 255) / 256), 256>>>(
            seq, W_c, W_attn, clf_W, A_bl, W_s, W_o);
    }
    // 3. ctxh = (pa @ seqR) * painv[row]  grid(12,8,4)=384
    {
        dim3 grid(WD / 64, NPAIR / 128, BATCH);
        mma_gemm<2, 1><<<grid, 256>>>(p_pa, p_seqR, p_ctxh, nullptr,
                                      NPAIR, HID, SEQ,
                                      (long long)NPAIR * SEQ, (long long)SEQ * HID,
                                      (long long)NPAIR * HID,
                                      1, 0, p_painv, 0.f, nullptr, NPAIR);
    }
    // 4. entity reps (rounded)
    rep_kernel<<<BATCH * NENT, 256>>>(seq, ep);
    // 5. rso partials = rep @ [W_s|W_o]  split-K 6 (kLen=128), grid(24,1,6)=144
    {
        dim3 grid((2 * WD) / 64, 1, 6);
        mma_gemm<0, 0><<<grid, 256>>>(p_rep, p_Wso, p_part, nullptr,
                                      BATCH * NENT, 2 * WD, HID, 0, 0, 0,
                                      6, (long long)BATCH * NENT * 2 * WD,
                                      nullptr, 0.f, nullptr, 0);
    }
    // 6. reduce rso
    reduce_add_kernel<<<(BATCH * NENT * 2 * WD + 255) / 256, 256>>>(
        p_part, p_rso, 6, (long long)BATCH * NENT * 2 * WD);
    // 7. fused: Zs/Zo = tanh(rso[i] + ctxh @ WcR)  grid(12,32)=384
    {
        dim3 grid(WD / 64, (BATCH * NPAIR) / 128, 1);
        mma_gemm<1, 0><<<grid, 256>>>(p_ctxh, p_WcR, p_Zs, p_Zo,
                                      BATCH * NPAIR, WD, HID, 0, 0, 0,
                                      1, 0, p_rso, 0.f, p_rso + WD, 2 * WD);
    }
    // 8. P (rounded, K-padded to 160)
    P_kernel<<<BATCH * NPAIR, 256>>>();
    // 9. g = P @ Ablt + 64*b_bl (rounded)  K=160, grid(12,32)=384
    {
        dim3 grid(WD / 64, (BATCH * NPAIR) / 128, 1);
        mma_gemm<0, 1><<<grid, 256>>>(p_P, p_Ablt, p_g, nullptr,
                                      BATCH * NPAIR, WD, PP2, 0, 0, 0,
                                      1, 0, b_bl, (float)SPLITK, nullptr, 0);
    }
    // 10. t = g @ WaR  grid(4,32)=128
    {
        dim3 grid(AD / 64, (BATCH * NPAIR) / 128, 1);
        mma_gemm<0, 0><<<grid, 256>>>(p_g, p_WaR, p_t, nullptr,
                                      BATCH * NPAIR, AD, WD, 0, 0, 0,
                                      1, 0, nullptr, 0.f, nullptr, 0);
    }
    // 11. e = tanh(t) . v_attn
    e_kernel<<<BATCH * NPAIR, 256>>>(v_attn);
    // 12. softmax
    softmax_kernel<<<BATCH, 1024>>>();
    // 13. gclf partials = g @ clfR (padded N=128, split-K 4, kLen=192) grid(2,32,4)=256
    {
        long long len = (long long)BATCH * NPAIR * NCP;
        dim3 grid(NCP / 64, (BATCH * NPAIR) / 128, 4);
        mma_gemm<0, 0><<<grid, 256>>>(p_g, p_clfR, p_part, nullptr,
                                      BATCH * NPAIR, NCP, WD, 0, 0, 0,
                                      4, len, nullptr, 0.f, nullptr, 0);
        reduce_add_kernel<<<(unsigned)((len + 255) / 256), 256>>>(p_part, p_gclf, 4, len);
    }
    // 14. axis-attention residual folded through clf_W
    {
        dim3 grid(NENT, BATCH);
        rowcolC_kernel<<<grid, 128>>>();
    }
    // 15. out
    {
        long long total = (long long)BATCH * NPAIR * NC;
        final_kernel<<<(unsigned)((total + 255) / 256), 256>>>(clf_b, out);
    }
}

// round 13
// speedup vs baseline: 1.2093x; 1.0480x over previous
#include <cuda_runtime.h>
#include <math.h>
#include <stdint.h>

#define BATCH 4
#define SEQ   1024
#define HID   768
#define HEADS 12
#define NENT  32
#define MENT  4
#define WD    768
#define AD    256
#define NC    97
#define NCP   128          // padded classifier width
#define SPLITK 64
#define DD    12
#define PP    144          // DD*DD
#define PP2   160          // K-padded (zeros) for BK=32 GEMM
#define NPAIR (NENT*NENT)  // 1024

// ---------------- device scratch ----------------
__device__ float d_rep[BATCH*NENT*HID];
__device__ float d_rso[BATCH*NENT*2*WD];
__device__ float d_Wso[WD*2*WD];
__device__ float d_seqR[(size_t)BATCH*SEQ*HID];   // tf32-rounded seq
__device__ float d_WcR[HID*WD];
__device__ float d_WaR[WD*AD];
__device__ float d_clfR[WD*NCP];                  // rounded + padded clf_W
__device__ float d_ga [BATCH*NENT*HEADS*SEQ];
__device__ float d_pa [(size_t)BATCH*NPAIR*SEQ];  // unnormalized, tf32-rounded
__device__ float d_painv[BATCH*NPAIR];
__device__ float d_ctxh[(size_t)BATCH*NPAIR*HID];
__device__ float d_Zs [(size_t)BATCH*NPAIR*WD];
__device__ float d_Zo [(size_t)BATCH*NPAIR*WD];
__device__ float d_P  [(size_t)BATCH*NPAIR*PP2];  // cols 144..159 stay zero
__device__ float d_g  [(size_t)BATCH*NPAIR*WD];
__device__ float d_t  [(size_t)BATCH*NPAIR*AD];
__device__ float d_e  [BATCH*NPAIR];
__device__ float d_arow[BATCH*NPAIR];
__device__ float d_acol[BATCH*NPAIR];
__device__ float d_Ablt[PP2*WD];                  // rows 144..159 stay zero
__device__ float d_gclf[(size_t)BATCH*NPAIR*NCP];
__device__ float d_rgcg[2*BATCH*NENT*NC];
__device__ float d_part [3300000];                // rso / t split-K partials
__device__ float d_part2[3300000];                // gclf split-K partials (concurrent)

// ---------------- helpers ----------------
__device__ __forceinline__ uint32_t f2tf32(float x)
{
    uint32_t r;
    asm("cvt.rna.tf32.f32 %0, %1;" : "=r"(r) : "f"(x));
    return r;
}
__device__ __forceinline__ float rnd32(float x) { return __uint_as_float(f2tf32(x)); }

__device__ __forceinline__ void mma_tf32(float* c, const uint32_t* a, const uint32_t* b)
{
    asm volatile(
        "mma.sync.aligned.m16n8k8.row.col.f32.tf32.tf32.f32 "
        "{%0,%1,%2,%3}, {%4,%5,%6,%7}, {%8,%9}, {%0,%1,%2,%3};"
        : "+f"(c[0]), "+f"(c[1]), "+f"(c[2]), "+f"(c[3])
        : "r"(a[0]), "r"(a[1]), "r"(a[2]), "r"(a[3]), "r"(b[0]), "r"(b[1]));
}

__device__ __forceinline__ void cp16(uint32_t smem, const void* g)
{
    asm volatile("cp.async.cg.shared.global [%0], [%1], 16;" :: "r"(smem), "l"(g));
}
__device__ __forceinline__ uint32_t smem_u32(const void* p)
{
    return (uint32_t)__cvta_generic_to_shared(p);
}

// ---------------- BK=32 cp.async pipelined tf32 GEMM ----------------
// C[M,N] = A[M,K] row * B[K,N] row, operands pre-rounded to tf32.
// BM=128, BN=64, BK=32. 8 warps: 4 m x 2 n, warp tile 32x32.
// As[128][36] / Bs[32][72]: conflict-free cp.async stores AND fragment LDS.
// 2-stage ring, wait_group 0; 32 HMMA/warp between barriers. 3 blocks/SM.
// MODE 0: C = acc (+ biasScale*bias[n]); MODE 1: tanh(acc + bias/bias2[(gm>>5)*bS+gn]) -> C,C2;
// MODE 2: C = acc * bias[zb*bS+gm].  RND: round stored C to tf32.
// Requirements: M%128==0, (K/kSplit)%32==0, N%4==0.
#define AS_STRIDE 36
#define BS_STRIDE 72
template<int MODE, int RND>
__global__ __launch_bounds__(256, 3)
void mma_gemm(const float* __restrict__ A, const float* __restrict__ B,
              float* __restrict__ C, float* __restrict__ C2,
              int M, int N, int K,
              long long sA, long long sB, long long sC,
              int kSplit, long long partStride,
              const float* __restrict__ bias, float biasScale,
              const float* __restrict__ bias2, int biasStride)
{
    const int NWT = 4;
    const int BN  = 64;
    __shared__ uint32_t As[2][128 * AS_STRIDE];   // 2 x 18 KB
    __shared__ float    Bs[2][32 * BS_STRIDE];    // 2 x 9 KB

    int zb = blockIdx.z / kSplit;
    int kz = blockIdx.z - zb * kSplit;
    A += (long long)zb * sA;
    B += (long long)zb * sB;
    C += (long long)zb * sC + (long long)kz * partStride;

    int row0 = blockIdx.y * 128;
    int col0 = blockIdx.x * BN;
    int tid = threadIdx.x, lane = tid & 31, w = tid >> 5;
    int wm = w & 3, wn = w >> 2;
    int g = lane >> 2, t = lane & 3;

    int kLen = K / kSplit;
    int k0beg = kz * kLen, k0end = k0beg + kLen;

    float acc[2][NWT][4];
    #pragma unroll
    for (int i = 0; i < 2; i++)
        #pragma unroll
        for (int j = 0; j < NWT; j++)
            #pragma unroll
            for (int r = 0; r < 4; r++) acc[i][j][r] = 0.f;

    int am = tid >> 3, ak = (tid & 7) * 4;
    const float* gA = A + (long long)(row0 + am) * K + ak;
    uint32_t asA = smem_u32(&As[0][am * AS_STRIDE + ak]);
    const uint32_t strideAstg = 128 * AS_STRIDE * 4;
    const uint32_t strideArow = 32 * AS_STRIDE * 4;

    int bk = tid >> 4, bn = (tid & 15) * 4;
    uint32_t bsB = smem_u32(&Bs[0][bk * BS_STRIDE + bn]);
    const uint32_t strideBstg = 32 * BS_STRIDE * 4;
    const uint32_t strideBrow = 16 * BS_STRIDE * 4;

    // prologue
    {
        #pragma unroll
        for (int p = 0; p < 4; p++)
            cp16(asA + p * strideArow, gA + (long long)p * 32 * K + k0beg);
        #pragma unroll
        for (int p = 0; p < 2; p++)
            cp16(bsB + p * strideBrow,
                 B + (long long)(k0beg + bk + p * 16) * N + col0 + bn);
        asm volatile("cp.async.commit_group;");
    }

    int buf = 0;
    for (int k0 = k0beg; k0 < k0end; k0 += 32) {
        asm volatile("cp.async.wait_group 0;");
        __syncthreads();

        int kn = k0 + 32;
        if (kn < k0end) {
            uint32_t ao = (buf ^ 1) ? strideAstg : 0;
            uint32_t bo = (buf ^ 1) ? strideBstg : 0;
            #pragma unroll
            for (int p = 0; p < 4; p++)
                cp16(asA + ao + p * strideArow, gA + (long long)p * 32 * K + kn);
            #pragma unroll
            for (int p = 0; p < 2; p++)
                cp16(bsB + bo + p * strideBrow,
                     B + (long long)(kn + bk + p * 16) * N + col0 + bn);
            asm volatile("cp.async.commit_group;");
        }

        const uint32_t* as = As[buf];
        const float*    bs = Bs[buf];
        #pragma unroll
        for (int k8 = 0; k8 < 4; k8++) {
            int kb = k8 * 8;
            uint32_t a[2][4];
            #pragma unroll
            for (int mi = 0; mi < 2; mi++) {
                int mb = wm * 32 + mi * 16;
                a[mi][0] = as[(mb + g)     * AS_STRIDE + kb + t];
                a[mi][1] = as[(mb + g + 8) * AS_STRIDE + kb + t];
                a[mi][2] = as[(mb + g)     * AS_STRIDE + kb + t + 4];
                a[mi][3] = as[(mb + g + 8) * AS_STRIDE + kb + t + 4];
            }
            uint32_t b[NWT][2];
            #pragma unroll
            for (int ni = 0; ni < NWT; ni++) {
                int nb_ = wn * 32 + ni * 8 + g;
                b[ni][0] = __float_as_uint(bs[(kb + t)     * BS_STRIDE + nb_]);
                b[ni][1] = __float_as_uint(bs[(kb + t + 4) * BS_STRIDE + nb_]);
            }
            #pragma unroll
            for (int mi = 0; mi < 2; mi++)
                #pragma unroll
                for (int ni = 0; ni < NWT; ni++)
                    mma_tf32(acc[mi][ni], a[mi], b[ni]);
        }
        buf ^= 1;
    }

    // ---- epilogue ----
    #pragma unroll
    for (int mi = 0; mi < 2; mi++) {
        #pragma unroll
        for (int ni = 0; ni < NWT; ni++) {
            int m_base = row0 + wm * 32 + mi * 16 + g;
            int n_base = col0 + wn * 32 + ni * 8 + t * 2;
            #pragma unroll
            for (int r = 0; r < 4; r++) {
                int gm = m_base + ((r >> 1) << 3);
                int gn = n_base + (r & 1);
                if (gn >= N) continue;
                float v = acc[mi][ni][r];
                if (MODE == 0) {
                    if (bias) v += biasScale * bias[gn];
                    if (RND) v = rnd32(v);
                    C[(long long)gm * N + gn] = v;
                } else if (MODE == 1) {
                    long long br = (long long)(gm >> 5) * biasStride + gn;
                    C [(long long)gm * N + gn] = tanhf(v + bias [br]);
                    C2[(long long)gm * N + gn] = tanhf(v + bias2[br]);
                } else {
                    v *= bias[(long long)zb * biasStride + gm];
                    if (RND) v = rnd32(v);
                    C[(long long)gm * N + gn] = v;
                }
            }
        }
    }
}

__global__ void reduce_add_kernel(const float* __restrict__ src, float* __restrict__ dst,
                                  int parts, long long len)
{
    long long i = (long long)blockIdx.x * 256 + threadIdx.x;
    if (i >= len) return;
    float s = 0.f;
    for (int p = 0; p < parts; p++) s += src[(long long)p * len + i];
    dst[i] = s;
}

// ---------------- stage kernels ----------------
__global__ void rep_kernel(const float* __restrict__ seq, const int* __restrict__ ep)
{
    int bn = blockIdx.x;
    int b = bn / NENT, n = bn % NENT;
    int e0 = ep[(b * NENT + n) * MENT + 0];
    int e1 = ep[(b * NENT + n) * MENT + 1];
    int e2 = ep[(b * NENT + n) * MENT + 2];
    int e3 = ep[(b * NENT + n) * MENT + 3];
    const float* sb = seq + (long long)b * SEQ * HID;
    for (int h = threadIdx.x; h < HID; h += blockDim.x) {
        float v0 = sb[(long long)e0 * HID + h];
        float v1 = sb[(long long)e1 * HID + h];
        float v2 = sb[(long long)e2 * HID + h];
        float v3 = sb[(long long)e3 * HID + h];
        float m = fmaxf(fmaxf(v0, v1), fmaxf(v2, v3));
        float s = expf(v0 - m) + expf(v1 - m) + expf(v2 - m) + expf(v3 - m);
        d_rep[(b * NENT + n) * HID + h] = rnd32(m + logf(s));
    }
}

// seq round (main chain; ctxh's B operand)
__global__ void prep_seq_kernel(const float* __restrict__ seq)
{
    long long idx = (long long)blockIdx.x * 256 + threadIdx.x;
    if (idx < (long long)BATCH * SEQ * HID) d_seqR[idx] = rnd32(seq[idx]);
}

// weight prep (side stream): W_c, W_attn, clf (padded), A_bl transpose, [Ws|Wo] pack
__global__ void prep_w_kernel(const float* __restrict__ Wc,
                              const float* __restrict__ Wa,
                              const float* __restrict__ clf,
                              const float* __restrict__ A_bl,
                              const float* __restrict__ W_s,
                              const float* __restrict__ W_o)
{
    const long long n2 = (long long)HID * WD;
    const long long n3 = (long long)WD * AD;
    const long long n4 = (long long)WD * NCP;
    const long long n5 = (long long)WD * PP;
    const long long n6 = (long long)WD * WD;
    long long idx = (long long)blockIdx.x * 256 + threadIdx.x;
    if (idx < n2) { d_WcR[idx] = rnd32(Wc[idx]); return; }
    idx -= n2;
    if (idx < n3) { d_WaR[idx] = rnd32(Wa[idx]); return; }
    idx -= n3;
    if (idx < n4) {
        int row = (int)(idx >> 7), col = (int)(idx & (NCP - 1));
        d_clfR[idx] = (col < NC) ? rnd32(clf[row * NC + col]) : 0.f;
        return;
    }
    idx -= n4;
    if (idx < n5) {
        int o = (int)(idx / PP), pq = (int)(idx % PP);
        d_Ablt[pq * WD + o] = rnd32(A_bl[idx]);
        return;
    }
    idx -= n5;
    if (idx < n6) {
        int k = (int)(idx / WD), j = (int)(idx % WD);
        d_Wso[(long long)k * (2 * WD) + j]      = rnd32(W_s[idx]);
        d_Wso[(long long)k * (2 * WD) + WD + j] = rnd32(W_o[idx]);
    }
}

__global__ void ga_kernel(const float* __restrict__ att, const int* __restrict__ ep)
{
    int b = blockIdx.z;
    int n = blockIdx.y / HEADS, h = blockIdx.y % HEADS;
    int s = blockIdx.x * blockDim.x + threadIdx.x;
    const float* ab = att + ((long long)(b * HEADS + h)) * SEQ * SEQ;
    float a = 0.f;
    #pragma unroll
    for (int m = 0; m < MENT; m++) {
        int e = ep[(b * NENT + n) * MENT + m];
        a += ab[(long long)e * SEQ + s];
    }
    d_ga[((long long)((b * NENT + n) * HEADS + h)) * SEQ + s] = a;
}

__global__ __launch_bounds__(256) void pa_tiled_kernel()
{
    extern __shared__ float sm[];          // [0:12288) gi, [12288:24576) gj
    __shared__ float sred[16 * 8];
    int b = blockIdx.z, ti = blockIdx.y, tj = blockIdx.x;
    int tid = threadIdx.x, lane = tid & 31, w = tid >> 5;

    float psum[16];
    #pragma unroll
    for (int p = 0; p < 16; p++) psum[p] = 0.f;

    for (int c = 0; c < 4; c++) {
        int s0 = c * 256;
        for (int l = tid; l < 3072; l += 256) {
            int il = l / 768;
            int rem = l - il * 768;
            int h = rem / 64, sq = rem - h * 64;
            int smoff = (il * 12 + h) * 256 + sq * 4;
            *(float4*)&sm[smoff] =
                *(const float4*)&d_ga[(((long long)(b * NENT + ti * 4 + il) * HEADS + h) << 10) + s0 + sq * 4];
            *(float4*)&sm[12288 + smoff] =
                *(const float4*)&d_ga[(((long long)(b * NENT + tj * 4 + il) * HEADS + h) << 10) + s0 + sq * 4];
        }
        __syncthreads();

        float acc[16];
        #pragma unroll
        for (int p = 0; p < 16; p++) acc[p] = 0.f;
        #pragma unroll
        for (int h = 0; h < HEADS; h++) {
            float ai[4], bj[4];
            #pragma unroll
            for (int il = 0; il < 4; il++) ai[il] = sm[(il * 12 + h) * 256 + tid];
            #pragma unroll
            for (int jl = 0; jl < 4; jl++) bj[jl] = sm[12288 + (jl * 12 + h) * 256 + tid];
            #pragma unroll
            for (int il = 0; il < 4; il++)
                #pragma unroll
                for (int jl = 0; jl < 4; jl++)
                    acc[il * 4 + jl] += ai[il] * bj[jl];
        }
        #pragma unroll
        for (int il = 0; il < 4; il++)
            #pragma unroll
            for (int jl = 0; jl < 4; jl++) {
                int p = il * 4 + jl;
                int ij = (ti * 4 + il) * NENT + tj * 4 + jl;
                d_pa[((long long)(b * NPAIR + ij) << 10) + s0 + tid] = rnd32(acc[p]);
                psum[p] += acc[p];
            }
        __syncthreads();
    }

    #pragma unroll
    for (int p = 0; p < 16; p++) {
        #pragma unroll
        for (int o = 16; o > 0; o >>= 1)
            psum[p] += __shfl_xor_sync(~0u, psum[p], o);
    }
    if (lane == 0)
        #pragma unroll
        for (int p = 0; p < 16; p++) sred[p * 8 + w] = psum[p];
    __syncthreads();
    if (tid < 16) {
        float s = 0.f;
        #pragma unroll
        for (int ww = 0; ww < 8; ww++) s += sred[tid * 8 + ww];
        int il = tid >> 2, jl = tid & 3;
        int ij = (ti * 4 + il) * NENT + tj * 4 + jl;
        d_painv[b * NPAIR + ij] = 1.0f / s;
    }
}

__global__ __launch_bounds__(256) void P_kernel()
{
    __shared__ float zs[WD], zo[WD];
    long long row = blockIdx.x;
    for (int w = threadIdx.x; w < WD; w += 256) {
        zs[w] = d_Zs[row * WD + w];
        zo[w] = d_Zo[row * WD + w];
    }
    __syncthreads();
    int t = threadIdx.x;
    if (t < PP) {
        int p = t / DD, q = t % DD;
        float a = 0.f;
        #pragma unroll
        for (int k = 0; k < SPLITK; k++)
            a += zs[p * SPLITK + k] * zo[q * SPLITK + k];
        d_P[row * PP2 + t] = rnd32(a);   // cols 144..159 remain zero
    }
}

__global__ __launch_bounds__(256) void e_kernel(const float* __restrict__ v_attn)
{
    int row = blockIdx.x;
    int tid = threadIdx.x;
    float val = tanhf(d_t[(long long)row * AD + tid]) * v_attn[tid];
    __shared__ float red[256];
    red[tid] = val;
    __syncthreads();
    for (int off = 128; off > 0; off >>= 1) {
        if (tid < off) red[tid] += red[tid + off];
        __syncthreads();
    }
    if (tid == 0) d_e[row] = red[0];
}

__global__ __launch_bounds__(1024) void softmax_kernel()
{
    int b = blockIdx.x;
    int tid = threadIdx.x;
    int w = tid >> 5, lane = tid & 31;
    const float* eb = d_e + b * NPAIR;
    float v = eb[w * 32 + lane];
    float m = v;
    for (int o = 16; o > 0; o >>= 1) m = fmaxf(m, __shfl_xor_sync(~0u, m, o));
    float ex = expf(v - m);
    float s = ex;
    for (int o = 16; o > 0; o >>= 1) s += __shfl_xor_sync(~0u, s, o);
    d_arow[b * NPAIR + w * 32 + lane] = ex / s;
    float v2 = eb[lane * 32 + w];
    float m2 = v2;
    for (int o = 16; o > 0; o >>= 1) m2 = fmaxf(m2, __shfl_xor_sync(~0u, m2, o));
    float ex2 = expf(v2 - m2);
    float s2 = ex2;
    for (int o = 16; o > 0; o >>= 1) s2 += __shfl_xor_sync(~0u, s2, o);
    d_acol[b * NPAIR + lane * 32 + w] = ex2 / s2;
}

__global__ void rowcolC_kernel()
{
    int b = blockIdx.y, n = blockIdx.x;
    int c = threadIdx.x;
    if (c >= NC) return;
    const float* gc = d_gclf + (long long)b * NPAIR * NCP;
    float rs = 0.f, cs = 0.f;
    #pragma unroll 4
    for (int k = 0; k < NENT; k++) {
        rs += d_arow[b * NPAIR + n * 32 + k] * gc[(long long)(n * 32 + k) * NCP + c];
        cs += d_acol[b * NPAIR + k * 32 + n] * gc[(long long)(k * 32 + n) * NCP + c];
    }
    d_rgcg[(b * NENT + n) * NC + c] = rs;
    d_rgcg[(BATCH * NENT + b * NENT + n) * NC + c] = cs;
}

__global__ void final_kernel(const float* __restrict__ clf_b, float* __restrict__ out)
{
    long long idx = (long long)blockIdx.x * blockDim.x + threadIdx.x;
    const long long total = (long long)BATCH * NPAIR * NC;
    if (idx >= total) return;
    int c = (int)(idx % NC);
    long long rb = idx / NC;
    int ij = (int)(rb % NPAIR);
    int b = (int)(rb / NPAIR);
    int i = ij >> 5, j = ij & 31;
    out[idx] = d_gclf[rb * NCP + c]
             + d_rgcg[(b * NENT + i) * NC + c]
             + d_rgcg[(BATCH * NENT + b * NENT + j) * NC + c]
             + clf_b[c];
}

// ---------------- host launch ----------------
extern "C" void kernel_launch(void* const* d_in, const int* in_sizes, int n_in,
                              void* d_out, int out_size)
{
    const float* seq    = (const float*)d_in[0];
    const float* att    = (const float*)d_in[1];
    const int*   ep     = (const int*)  d_in[2];
    const float* W_s    = (const float*)d_in[3];
    const float* W_o    = (const float*)d_in[4];
    const float* W_c    = (const float*)d_in[5];
    const float* A_bl   = (const float*)d_in[6];
    const float* b_bl   = (const float*)d_in[7];
    const float* W_attn = (const float*)d_in[8];
    const float* v_attn = (const float*)d_in[9];
    const float* clf_W  = (const float*)d_in[10];
    const float* clf_b  = (const float*)d_in[11];
    float* out = (float*)d_out;

    float *p_rep, *p_rso, *p_Wso, *p_seqR, *p_WcR, *p_WaR, *p_clfR, *p_pa,
          *p_painv, *p_ctxh, *p_Zs, *p_Zo, *p_P, *p_Ablt, *p_g, *p_t,
          *p_gclf, *p_part, *p_part2;
    cudaGetSymbolAddress((void**)&p_rep,   d_rep);
    cudaGetSymbolAddress((void**)&p_rso,   d_rso);
    cudaGetSymbolAddress((void**)&p_Wso,   d_Wso);
    cudaGetSymbolAddress((void**)&p_seqR,  d_seqR);
    cudaGetSymbolAddress((void**)&p_WcR,   d_WcR);
    cudaGetSymbolAddress((void**)&p_WaR,   d_WaR);
    cudaGetSymbolAddress((void**)&p_clfR,  d_clfR);
    cudaGetSymbolAddress((void**)&p_pa,    d_pa);
    cudaGetSymbolAddress((void**)&p_painv, d_painv);
    cudaGetSymbolAddress((void**)&p_ctxh,  d_ctxh);
    cudaGetSymbolAddress((void**)&p_Zs,    d_Zs);
    cudaGetSymbolAddress((void**)&p_Zo,    d_Zo);
    cudaGetSymbolAddress((void**)&p_P,     d_P);
    cudaGetSymbolAddress((void**)&p_Ablt,  d_Ablt);
    cudaGetSymbolAddress((void**)&p_g,     d_g);
    cudaGetSymbolAddress((void**)&p_t,     d_t);
    cudaGetSymbolAddress((void**)&p_gclf,  d_gclf);
    cudaGetSymbolAddress((void**)&p_part,  d_part);
    cudaGetSymbolAddress((void**)&p_part2, d_part2);

    static cudaStream_t sSide = nullptr;
    static cudaEvent_t evFork1, evJoin1, evFork2, evJoin2;
    static bool inited = false;
    if (!inited) {
        cudaFuncSetAttribute(pa_tiled_kernel,
                             cudaFuncAttributeMaxDynamicSharedMemorySize, 98304);
        cudaStreamCreateWithFlags(&sSide, cudaStreamNonBlocking);
        cudaEventCreateWithFlags(&evFork1, cudaEventDisableTiming);
        cudaEventCreateWithFlags(&evJoin1, cudaEventDisableTiming);
        cudaEventCreateWithFlags(&evFork2, cudaEventDisableTiming);
        cudaEventCreateWithFlags(&evJoin2, cudaEventDisableTiming);
        inited = true;
    }

    // ---- fork 1: side = weight prep + rep + rso; main = ga/pa/seq/ctxh ----
    cudaEventRecord(evFork1, 0);
    cudaStreamWaitEvent(sSide, evFork1, 0);

    // side stream
    {
        long long totw = (long long)HID * WD + (long long)WD * AD
                       + (long long)WD * NCP + (long long)WD * PP + (long long)WD * WD;
        prep_w_kernel<<<(unsigned)((totw + 255) / 256), 256, 0, sSide>>>(
            W_c, W_attn, clf_W, A_bl, W_s, W_o);
        rep_kernel<<<BATCH * NENT, 256, 0, sSide>>>(seq, ep);
        dim3 grid((2 * WD) / 64, 1, 6);
        mma_gemm<0, 0><<<grid, 256, 0, sSide>>>(p_rep, p_Wso, p_part, nullptr,
                                                BATCH * NENT, 2 * WD, HID, 0, 0, 0,
                                                6, (long long)BATCH * NENT * 2 * WD,
                                                nullptr, 0.f, nullptr, 0);
        reduce_add_kernel<<<(BATCH * NENT * 2 * WD + 255) / 256, 256, 0, sSide>>>(
            p_part, p_rso, 6, (long long)BATCH * NENT * 2 * WD);
        cudaEventRecord(evJoin1, sSide);
    }

    // main stream
    {
        dim3 grid(SEQ / 256, NENT * HEADS, BATCH);
        ga_kernel<<<grid, 256>>>(att, ep);
    }
    {
        dim3 grid(8, 8, BATCH);
        pa_tiled_kernel<<<grid, 256, 98304>>>();
    }
    {
        long long tot = (long long)BATCH * SEQ * HID;
        prep_seq_kernel<<<(unsigned)((tot + 255) / 256), 256>>>(seq);
    }
    // ctxh = (pa @ seqR) * painv[row]  grid(12,8,4)=384
    {
        dim3 grid(WD / 64, NPAIR / 128, BATCH);
        mma_gemm<2, 1><<<grid, 256>>>(p_pa, p_seqR, p_ctxh, nullptr,
                                      NPAIR, HID, SEQ,
                                      (long long)NPAIR * SEQ, (long long)SEQ * HID,
                                      (long long)NPAIR * HID,
                                      1, 0, p_painv, 0.f, nullptr, NPAIR);
    }
    // join 1: Zs needs rso + WcR from side
    cudaStreamWaitEvent(0, evJoin1, 0);
    // Zs/Zo = tanh(rso[i] + ctxh @ WcR)  grid(12,32)=384
    {
        dim3 grid(WD / 64, (BATCH * NPAIR) / 128, 1);
        mma_gemm<1, 0><<<grid, 256>>>(p_ctxh, p_WcR, p_Zs, p_Zo,
                                      BATCH * NPAIR, WD, HID, 0, 0, 0,
                                      1, 0, p_rso, 0.f, p_rso + WD, 2 * WD);
    }
    // P (rounded, K-padded to 160)
    P_kernel<<<BATCH * NPAIR, 256>>>();
    // g = P @ Ablt + 64*b_bl (rounded)  K=160, grid(12,32)=384
    {
        dim3 grid(WD / 64, (BATCH * NPAIR) / 128, 1);
        mma_gemm<0, 1><<<grid, 256>>>(p_P, p_Ablt, p_g, nullptr,
                                      BATCH * NPAIR, WD, PP2, 0, 0, 0,
                                      1, 0, b_bl, (float)SPLITK, nullptr, 0);
    }

    // ---- fork 2: side = gclf; main = t -> e -> softmax ----
    cudaEventRecord(evFork2, 0);
    cudaStreamWaitEvent(sSide, evFork2, 0);
    {
        long long len = (long long)BATCH * NPAIR * NCP;
        dim3 grid(NCP / 64, (BATCH * NPAIR) / 128, 6);   // kSplit 6, kLen=128
        mma_gemm<0, 0><<<grid, 256, 0, sSide>>>(p_g, p_clfR, p_part2, nullptr,
                                                BATCH * NPAIR, NCP, WD, 0, 0, 0,
                                                6, len, nullptr, 0.f, nullptr, 0);
        reduce_add_kernel<<<(unsigned)((len + 255) / 256), 256, 0, sSide>>>(
            p_part2, p_gclf, 6, len);
        cudaEventRecord(evJoin2, sSide);
    }
    // main: t = g @ WaR  split-K 3 (kLen=256) grid(4,32,3)=384
    {
        long long len = (long long)BATCH * NPAIR * AD;
        dim3 grid(AD / 64, (BATCH * NPAIR) / 128, 3);
        mma_gemm<0, 0><<<grid, 256>>>(p_g, p_WaR, p_part, nullptr,
                                      BATCH * NPAIR, AD, WD, 0, 0, 0,
                                      3, len, nullptr, 0.f, nullptr, 0);
        reduce_add_kernel<<<(unsigned)((len + 255) / 256), 256>>>(p_part, p_t, 3, len);
    }
    e_kernel<<<BATCH * NPAIR, 256>>>(v_attn);
    softmax_kernel<<<BATCH, 1024>>>();
    // join 2: rowcolC needs gclf
    cudaStreamWaitEvent(0, evJoin2, 0);
    {
        dim3 grid(NENT, BATCH);
        rowcolC_kernel<<<grid, 128>>>();
    }
    {
        long long total = (long long)BATCH * NPAIR * NC;
        final_kernel<<<(unsigned)((total + 255) / 256), 256>>>(clf_b, out);
    }
}

// round 15
// speedup vs baseline: 1.2674x; 1.0480x over previous
#include <cuda_runtime.h>
#include <math.h>
#include <stdint.h>

#define BATCH 4
#define SEQ   1024
#define HID   768
#define HEADS 12
#define NENT  32
#define MENT  4
#define WD    768
#define AD    256
#define NC    97
#define NCP   128          // padded classifier width
#define SPLITK 64
#define DD    12
#define PP    144          // DD*DD
#define PP2   160          // K-padded (zeros) for BK=32 GEMM
#define NPAIR (NENT*NENT)  // 1024

// ---------------- device scratch ----------------
__device__ float d_rep[BATCH*NENT*HID];
__device__ float d_rso[BATCH*NENT*2*WD];
__device__ float d_Wso[WD*2*WD];
__device__ float d_seqR[(size_t)BATCH*SEQ*HID];   // tf32-rounded seq
__device__ float d_WcR[HID*WD];
__device__ float d_WaR[WD*AD];
__device__ float d_clfR[WD*NCP];                  // rounded + padded clf_W
__device__ float d_seqWc[(size_t)BATCH*SEQ*WD];   // rnd(seq @ W_c), tf32-rounded
__device__ float d_ga [BATCH*NENT*HEADS*SEQ];
__device__ float d_pa [(size_t)BATCH*NPAIR*SEQ];  // unnormalized, tf32-rounded
__device__ float d_painv[BATCH*NPAIR];
__device__ float d_Zs [(size_t)BATCH*NPAIR*WD];
__device__ float d_Zo [(size_t)BATCH*NPAIR*WD];
__device__ float d_P  [(size_t)BATCH*NPAIR*PP2];  // cols 144..159 stay zero
__device__ float d_g  [(size_t)BATCH*NPAIR*WD];
__device__ float d_t  [(size_t)BATCH*NPAIR*AD];
__device__ float d_e  [BATCH*NPAIR];
__device__ float d_arow[BATCH*NPAIR];
__device__ float d_acol[BATCH*NPAIR];
__device__ float d_Ablt[PP2*WD];                  // rows 144..159 stay zero
__device__ float d_gclf[(size_t)BATCH*NPAIR*NCP];
__device__ float d_rgcg[2*BATCH*NENT*NC];
__device__ float d_part [3300000];                // rso / t split-K partials
__device__ float d_part2[3300000];                // gclf split-K partials (concurrent)

// ---------------- helpers ----------------
__device__ __forceinline__ uint32_t f2tf32(float x)
{
    uint32_t r;
    asm("cvt.rna.tf32.f32 %0, %1;" : "=r"(r) : "f"(x));
    return r;
}
__device__ __forceinline__ float rnd32(float x) { return __uint_as_float(f2tf32(x)); }

__device__ __forceinline__ void mma_tf32(float* c, const uint32_t* a, const uint32_t* b)
{
    asm volatile(
        "mma.sync.aligned.m16n8k8.row.col.f32.tf32.tf32.f32 "
        "{%0,%1,%2,%3}, {%4,%5,%6,%7}, {%8,%9}, {%0,%1,%2,%3};"
        : "+f"(c[0]), "+f"(c[1]), "+f"(c[2]), "+f"(c[3])
        : "r"(a[0]), "r"(a[1]), "r"(a[2]), "r"(a[3]), "r"(b[0]), "r"(b[1]));
}

__device__ __forceinline__ void cp16(uint32_t smem, const void* g)
{
    asm volatile("cp.async.cg.shared.global [%0], [%1], 16;" :: "r"(smem), "l"(g));
}
__device__ __forceinline__ uint32_t smem_u32(const void* p)
{
    return (uint32_t)__cvta_generic_to_shared(p);
}

// ---------------- BK=32 cp.async pipelined tf32 GEMM ----------------
// C[M,N] = A[M,K] row * B[K,N] row, operands pre-rounded to tf32.
// BM=128, BN=64, BK=32. 8 warps: 4 m x 2 n, warp tile 32x32.
// As[128][36] / Bs[32][72]: conflict-free cp.async stores AND fragment LDS.
// 2-stage ring, wait_group 0; 32 HMMA/warp between barriers. 3 blocks/SM.
// MODE 0: C = acc (+ biasScale*bias[n]).
// MODE 1: C = tanh(acc + bias[(gm>>5)*bS+gn]); C2 likewise with bias2.
// MODE 2: C = acc * bias[zb*bS+gm].
// MODE 3: v = acc * scale[zb*NPAIR+gm];
//         C  = tanh(v + bias [((zb*NENT)+(gm>>5))*bS+gn]);
//         C2 = tanh(v + bias2[...same row...]).
// RND: round stored C to tf32 (MODE 0/2).
// Requirements: M%128==0, (K/kSplit)%32==0, N%4==0.
#define AS_STRIDE 36
#define BS_STRIDE 72
template<int MODE, int RND>
__global__ __launch_bounds__(256, 3)
void mma_gemm(const float* __restrict__ A, const float* __restrict__ B,
              float* __restrict__ C, float* __restrict__ C2,
              int M, int N, int K,
              long long sA, long long sB, long long sC,
              int kSplit, long long partStride,
              const float* __restrict__ bias, float biasScale,
              const float* __restrict__ bias2, int biasStride,
              const float* __restrict__ scale)
{
    const int NWT = 4;
    const int BN  = 64;
    __shared__ uint32_t As[2][128 * AS_STRIDE];   // 2 x 18 KB
    __shared__ float    Bs[2][32 * BS_STRIDE];    // 2 x 9 KB

    int zb = blockIdx.z / kSplit;
    int kz = blockIdx.z - zb * kSplit;
    A += (long long)zb * sA;
    B += (long long)zb * sB;
    C += (long long)zb * sC + (long long)kz * partStride;
    if (C2) C2 += (long long)zb * sC;            // FIX: batch-offset the second output

    int row0 = blockIdx.y * 128;
    int col0 = blockIdx.x * BN;
    int tid = threadIdx.x, lane = tid & 31, w = tid >> 5;
    int wm = w & 3, wn = w >> 2;
    int g = lane >> 2, t = lane & 3;

    int kLen = K / kSplit;
    int k0beg = kz * kLen, k0end = k0beg + kLen;

    float acc[2][NWT][4];
    #pragma unroll
    for (int i = 0; i < 2; i++)
        #pragma unroll
        for (int j = 0; j < NWT; j++)
            #pragma unroll
            for (int r = 0; r < 4; r++) acc[i][j][r] = 0.f;

    int am = tid >> 3, ak = (tid & 7) * 4;
    const float* gA = A + (long long)(row0 + am) * K + ak;
    uint32_t asA = smem_u32(&As[0][am * AS_STRIDE + ak]);
    const uint32_t strideAstg = 128 * AS_STRIDE * 4;
    const uint32_t strideArow = 32 * AS_STRIDE * 4;

    int bk = tid >> 4, bn = (tid & 15) * 4;
    uint32_t bsB = smem_u32(&Bs[0][bk * BS_STRIDE + bn]);
    const uint32_t strideBstg = 32 * BS_STRIDE * 4;
    const uint32_t strideBrow = 16 * BS_STRIDE * 4;

    // prologue
    {
        #pragma unroll
        for (int p = 0; p < 4; p++)
            cp16(asA + p * strideArow, gA + (long long)p * 32 * K + k0beg);
        #pragma unroll
        for (int p = 0; p < 2; p++)
            cp16(bsB + p * strideBrow,
                 B + (long long)(k0beg + bk + p * 16) * N + col0 + bn);
        asm volatile("cp.async.commit_group;");
    }

    int buf = 0;
    for (int k0 = k0beg; k0 < k0end; k0 += 32) {
        asm volatile("cp.async.wait_group 0;");
        __syncthreads();

        int kn = k0 + 32;
        if (kn < k0end) {
            uint32_t ao = (buf ^ 1) ? strideAstg : 0;
            uint32_t bo = (buf ^ 1) ? strideBstg : 0;
            #pragma unroll
            for (int p = 0; p < 4; p++)
                cp16(asA + ao + p * strideArow, gA + (long long)p * 32 * K + kn);
            #pragma unroll
            for (int p = 0; p < 2; p++)
                cp16(bsB + bo + p * strideBrow,
                     B + (long long)(kn + bk + p * 16) * N + col0 + bn);
            asm volatile("cp.async.commit_group;");
        }

        const uint32_t* as = As[buf];
        const float*    bs = Bs[buf];
        #pragma unroll
        for (int k8 = 0; k8 < 4; k8++) {
            int kb = k8 * 8;
            uint32_t a[2][4];
            #pragma unroll
            for (int mi = 0; mi < 2; mi++) {
                int mb = wm * 32 + mi * 16;
                a[mi][0] = as[(mb + g)     * AS_STRIDE + kb + t];
                a[mi][1] = as[(mb + g + 8) * AS_STRIDE + kb + t];
                a[mi][2] = as[(mb + g)     * AS_STRIDE + kb + t + 4];
                a[mi][3] = as[(mb + g + 8) * AS_STRIDE + kb + t + 4];
            }
            uint32_t b[NWT][2];
            #pragma unroll
            for (int ni = 0; ni < NWT; ni++) {
                int nb_ = wn * 32 + ni * 8 + g;
                b[ni][0] = __float_as_uint(bs[(kb + t)     * BS_STRIDE + nb_]);
                b[ni][1] = __float_as_uint(bs[(kb + t + 4) * BS_STRIDE + nb_]);
            }
            #pragma unroll
            for (int mi = 0; mi < 2; mi++)
                #pragma unroll
                for (int ni = 0; ni < NWT; ni++)
                    mma_tf32(acc[mi][ni], a[mi], b[ni]);
        }
        buf ^= 1;
    }

    // ---- epilogue ----
    #pragma unroll
    for (int mi = 0; mi < 2; mi++) {
        #pragma unroll
        for (int ni = 0; ni < NWT; ni++) {
            int m_base = row0 + wm * 32 + mi * 16 + g;
            int n_base = col0 + wn * 32 + ni * 8 + t * 2;
            #pragma unroll
            for (int r = 0; r < 4; r++) {
                int gm = m_base + ((r >> 1) << 3);
                int gn = n_base + (r & 1);
                if (gn >= N) continue;
                float v = acc[mi][ni][r];
                if (MODE == 0) {
                    if (bias) v += biasScale * bias[gn];
                    if (RND) v = rnd32(v);
                    C[(long long)gm * N + gn] = v;
                } else if (MODE == 1) {
                    long long br = (long long)(gm >> 5) * biasStride + gn;
                    C [(long long)gm * N + gn] = tanhf(v + bias [br]);
                    C2[(long long)gm * N + gn] = tanhf(v + bias2[br]);
                } else if (MODE == 2) {
                    v *= bias[(long long)zb * biasStride + gm];
                    if (RND) v = rnd32(v);
                    C[(long long)gm * N + gn] = v;
                } else {
                    float vv = v * scale[(long long)zb * NPAIR + gm];
                    long long br = (long long)((zb << 5) + (gm >> 5)) * biasStride + gn;
                    C [(long long)gm * N + gn] = tanhf(vv + bias [br]);
                    C2[(long long)gm * N + gn] = tanhf(vv + bias2[br]);
                }
            }
        }
    }
}

__global__ void reduce_add_kernel(const float* __restrict__ src, float* __restrict__ dst,
                                  int parts, long long len)
{
    long long i = (long long)blockIdx.x * 256 + threadIdx.x;
    if (i >= len) return;
    float s = 0.f;
    for (int p = 0; p < parts; p++) s += src[(long long)p * len + i];
    dst[i] = s;
}

// ---------------- stage kernels ----------------
__global__ void rep_kernel(const float* __restrict__ seq, const int* __restrict__ ep)
{
    int bn = blockIdx.x;
    int b = bn / NENT, n = bn % NENT;
    int e0 = ep[(b * NENT + n) * MENT + 0];
    int e1 = ep[(b * NENT + n) * MENT + 1];
    int e2 = ep[(b * NENT + n) * MENT + 2];
    int e3 = ep[(b * NENT + n) * MENT + 3];
    const float* sb = seq + (long long)b * SEQ * HID;
    for (int h = threadIdx.x; h < HID; h += blockDim.x) {
        float v0 = sb[(long long)e0 * HID + h];
        float v1 = sb[(long long)e1 * HID + h];
        float v2 = sb[(long long)e2 * HID + h];
        float v3 = sb[(long long)e3 * HID + h];
        float m = fmaxf(fmaxf(v0, v1), fmaxf(v2, v3));
        float s = expf(v0 - m) + expf(v1 - m) + expf(v2 - m) + expf(v3 - m);
        d_rep[(b * NENT + n) * HID + h] = rnd32(m + logf(s));
    }
}

// side1 prep: round seq and W_c (operands of the seqWc GEMM)
__global__ void prep_seqWc_kernel(const float* __restrict__ seq,
                                  const float* __restrict__ Wc)
{
    const long long n1 = (long long)BATCH * SEQ * HID;
    const long long n2 = (long long)HID * WD;
    long long idx = (long long)blockIdx.x * 256 + threadIdx.x;
    if (idx < n1) { d_seqR[idx] = rnd32(seq[idx]); return; }
    idx -= n1;
    if (idx < n2) d_WcR[idx] = rnd32(Wc[idx]);
}

// side2 prep: W_attn, clf (padded), A_bl transpose, [Ws|Wo] pack
__global__ void prep_w2_kernel(const float* __restrict__ Wa,
                               const float* __restrict__ clf,
                               const float* __restrict__ A_bl,
                               const float* __restrict__ W_s,
                               const float* __restrict__ W_o)
{
    const long long n3 = (long long)WD * AD;
    const long long n4 = (long long)WD * NCP;
    const long long n5 = (long long)WD * PP;
    const long long n6 = (long long)WD * WD;
    long long idx = (long long)blockIdx.x * 256 + threadIdx.x;
    if (idx < n3) { d_WaR[idx] = rnd32(Wa[idx]); return; }
    idx -= n3;
    if (idx < n4) {
        int row = (int)(idx >> 7), col = (int)(idx & (NCP - 1));
        d_clfR[idx] = (col < NC) ? rnd32(clf[row * NC + col]) : 0.f;
        return;
    }
    idx -= n4;
    if (idx < n5) {
        int o = (int)(idx / PP), pq = (int)(idx % PP);
        d_Ablt[pq * WD + o] = rnd32(A_bl[idx]);
        return;
    }
    idx -= n5;
    if (idx < n6) {
        int k = (int)(idx / WD), j = (int)(idx % WD);
        d_Wso[(long long)k * (2 * WD) + j]      = rnd32(W_s[idx]);
        d_Wso[(long long)k * (2 * WD) + WD + j] = rnd32(W_o[idx]);
    }
}

__global__ void ga_kernel(const float* __restrict__ att, const int* __restrict__ ep)
{
    int b = blockIdx.z;
    int n = blockIdx.y / HEADS, h = blockIdx.y % HEADS;
    int s = blockIdx.x * blockDim.x + threadIdx.x;
    const float* ab = att + ((long long)(b * HEADS + h)) * SEQ * SEQ;
    float a = 0.f;
    #pragma unroll
    for (int m = 0; m < MENT; m++) {
        int e = ep[(b * NENT + n) * MENT + m];
        a += ab[(long long)e * SEQ + s];
    }
    d_ga[((long long)((b * NENT + n) * HEADS + h)) * SEQ + s] = a;
}

__global__ __launch_bounds__(256) void pa_tiled_kernel()
{
    extern __shared__ float sm[];          // [0:12288) gi, [12288:24576) gj
    __shared__ float sred[16 * 8];
    int b = blockIdx.z, ti = blockIdx.y, tj = blockIdx.x;
    int tid = threadIdx.x, lane = tid & 31, w = tid >> 5;

    float psum[16];
    #pragma unroll
    for (int p = 0; p < 16; p++) psum[p] = 0.f;

    for (int c = 0; c < 4; c++) {
        int s0 = c * 256;
        for (int l = tid; l < 3072; l += 256) {
            int il = l / 768;
            int rem = l - il * 768;
            int h = rem / 64, sq = rem - h * 64;
            int smoff = (il * 12 + h) * 256 + sq * 4;
            *(float4*)&sm[smoff] =
                *(const float4*)&d_ga[(((long long)(b * NENT + ti * 4 + il) * HEADS + h) << 10) + s0 + sq * 4];
            *(float4*)&sm[12288 + smoff] =
                *(const float4*)&d_ga[(((long long)(b * NENT + tj * 4 + il) * HEADS + h) << 10) + s0 + sq * 4];
        }
        __syncthreads();

        float acc[16];
        #pragma unroll
        for (int p = 0; p < 16; p++) acc[p] = 0.f;
        #pragma unroll
        for (int h = 0; h < HEADS; h++) {
            float ai[4], bj[4];
            #pragma unroll
            for (int il = 0; il < 4; il++) ai[il] = sm[(il * 12 + h) * 256 + tid];
            #pragma unroll
            for (int jl = 0; jl < 4; jl++) bj[jl] = sm[12288 + (jl * 12 + h) * 256 + tid];
            #pragma unroll
            for (int il = 0; il < 4; il++)
                #pragma unroll
                for (int jl = 0; jl < 4; jl++)
                    acc[il * 4 + jl] += ai[il] * bj[jl];
        }
        #pragma unroll
        for (int il = 0; il < 4; il++)
            #pragma unroll
            for (int jl = 0; jl < 4; jl++) {
                int p = il * 4 + jl;
                int ij = (ti * 4 + il) * NENT + tj * 4 + jl;
                d_pa[((long long)(b * NPAIR + ij) << 10) + s0 + tid] = rnd32(acc[p]);
                psum[p] += acc[p];
            }
        __syncthreads();
    }

    #pragma unroll
    for (int p = 0; p < 16; p++) {
        #pragma unroll
        for (int o = 16; o > 0; o >>= 1)
            psum[p] += __shfl_xor_sync(~0u, psum[p], o);
    }
    if (lane == 0)
        #pragma unroll
        for (int p = 0; p < 16; p++) sred[p * 8 + w] = psum[p];
    __syncthreads();
    if (tid < 16) {
        float s = 0.f;
        #pragma unroll
        for (int ww = 0; ww < 8; ww++) s += sred[tid * 8 + ww];
        int il = tid >> 2, jl = tid & 3;
        int ij = (ti * 4 + il) * NENT + tj * 4 + jl;
        d_painv[b * NPAIR + ij] = 1.0f / s;
    }
}

__global__ __launch_bounds__(256) void P_kernel()
{
    __shared__ float zs[WD], zo[WD];
    long long row = blockIdx.x;
    for (int w = threadIdx.x; w < WD; w += 256) {
        zs[w] = d_Zs[row * WD + w];
        zo[w] = d_Zo[row * WD + w];
    }
    __syncthreads();
    int t = threadIdx.x;
    if (t < PP) {
        int p = t / DD, q = t % DD;
        float a = 0.f;
        #pragma unroll
        for (int k = 0; k < SPLITK; k++)
            a += zs[p * SPLITK + k] * zo[q * SPLITK + k];
        d_P[row * PP2 + t] = rnd32(a);   // cols 144..159 remain zero
    }
}

__global__ __launch_bounds__(256) void e_kernel(const float* __restrict__ v_attn)
{
    int row = blockIdx.x;
    int tid = threadIdx.x;
    float val = tanhf(d_t[(long long)row * AD + tid]) * v_attn[tid];
    __shared__ float red[256];
    red[tid] = val;
    __syncthreads();
    for (int off = 128; off > 0; off >>= 1) {
        if (tid < off) red[tid] += red[tid + off];
        __syncthreads();
    }
    if (tid == 0) d_e[row] = red[0];
}

__global__ __launch_bounds__(1024) void softmax_kernel()
{
    int b = blockIdx.x;
    int tid = threadIdx.x;
    int w = tid >> 5, lane = tid & 31;
    const float* eb = d_e + b * NPAIR;
    float v = eb[w * 32 + lane];
    float m = v;
    for (int o = 16; o > 0; o >>= 1) m = fmaxf(m, __shfl_xor_sync(~0u, m, o));
    float ex = expf(v - m);
    float s = ex;
    for (int o = 16; o > 0; o >>= 1) s += __shfl_xor_sync(~0u, s, o);
    d_arow[b * NPAIR + w * 32 + lane] = ex / s;
    float v2 = eb[lane * 32 + w];
    float m2 = v2;
    for (int o = 16; o > 0; o >>= 1) m2 = fmaxf(m2, __shfl_xor_sync(~0u, m2, o));
    float ex2 = expf(v2 - m2);
    float s2 = ex2;
    for (int o = 16; o > 0; o >>= 1) s2 += __shfl_xor_sync(~0u, s2, o);
    d_acol[b * NPAIR + lane * 32 + w] = ex2 / s2;
}

__global__ void rowcolC_kernel()
{
    int b = blockIdx.y, n = blockIdx.x;
    int c = threadIdx.x;
    if (c >= NC) return;
    const float* gc = d_gclf + (long long)b * NPAIR * NCP;
    float rs = 0.f, cs = 0.f;
    #pragma unroll 4
    for (int k = 0; k < NENT; k++) {
        rs += d_arow[b * NPAIR + n * 32 + k] * gc[(long long)(n * 32 + k) * NCP + c];
        cs += d_acol[b * NPAIR + k * 32 + n] * gc[(long long)(k * 32 + n) * NCP + c];
    }
    d_rgcg[(b * NENT + n) * NC + c] = rs;
    d_rgcg[(BATCH * NENT + b * NENT + n) * NC + c] = cs;
}

__global__ void final_kernel(const float* __restrict__ clf_b, float* __restrict__ out)
{
    long long idx = (long long)blockIdx.x * blockDim.x + threadIdx.x;
    const long long total = (long long)BATCH * NPAIR * NC;
    if (idx >= total) return;
    int c = (int)(idx % NC);
    long long rb = idx / NC;
    int ij = (int)(rb % NPAIR);
    int b = (int)(rb / NPAIR);
    int i = ij >> 5, j = ij & 31;
    out[idx] = d_gclf[rb * NCP + c]
             + d_rgcg[(b * NENT + i) * NC + c]
             + d_rgcg[(BATCH * NENT + b * NENT + j) * NC + c]
             + clf_b[c];
}

// ---------------- host launch ----------------
extern "C" void kernel_launch(void* const* d_in, const int* in_sizes, int n_in,
                              void* d_out, int out_size)
{
    const float* seq    = (const float*)d_in[0];
    const float* att    = (const float*)d_in[1];
    const int*   ep     = (const int*)  d_in[2];
    const float* W_s    = (const float*)d_in[3];
    const float* W_o    = (const float*)d_in[4];
    const float* W_c    = (const float*)d_in[5];
    const float* A_bl   = (const float*)d_in[6];
    const float* b_bl   = (const float*)d_in[7];
    const float* W_attn = (const float*)d_in[8];
    const float* v_attn = (const float*)d_in[9];
    const float* clf_W  = (const float*)d_in[10];
    const float* clf_b  = (const float*)d_in[11];
    float* out = (float*)d_out;

    float *p_rep, *p_rso, *p_Wso, *p_seqR, *p_WcR, *p_WaR, *p_clfR, *p_seqWc,
          *p_pa, *p_painv, *p_Zs, *p_Zo, *p_P, *p_Ablt, *p_g, *p_t,
          *p_gclf, *p_part, *p_part2;
    cudaGetSymbolAddress((void**)&p_rep,   d_rep);
    cudaGetSymbolAddress((void**)&p_rso,   d_rso);
    cudaGetSymbolAddress((void**)&p_Wso,   d_Wso);
    cudaGetSymbolAddress((void**)&p_seqR,  d_seqR);
    cudaGetSymbolAddress((void**)&p_WcR,   d_WcR);
    cudaGetSymbolAddress((void**)&p_WaR,   d_WaR);
    cudaGetSymbolAddress((void**)&p_clfR,  d_clfR);
    cudaGetSymbolAddress((void**)&p_seqWc, d_seqWc);
    cudaGetSymbolAddress((void**)&p_pa,    d_pa);
    cudaGetSymbolAddress((void**)&p_painv, d_painv);
    cudaGetSymbolAddress((void**)&p_Zs,    d_Zs);
    cudaGetSymbolAddress((void**)&p_Zo,    d_Zo);
    cudaGetSymbolAddress((void**)&p_P,     d_P);
    cudaGetSymbolAddress((void**)&p_Ablt,  d_Ablt);
    cudaGetSymbolAddress((void**)&p_g,     d_g);
    cudaGetSymbolAddress((void**)&p_t,     d_t);
    cudaGetSymbolAddress((void**)&p_gclf,  d_gclf);
    cudaGetSymbolAddress((void**)&p_part,  d_part);
    cudaGetSymbolAddress((void**)&p_part2, d_part2);

    static cudaStream_t s1 = nullptr, s2 = nullptr;
    static cudaEvent_t evF, evJ1, evJ2, evF2, evJ3;
    static bool inited = false;
    if (!inited) {
        cudaFuncSetAttribute(pa_tiled_kernel,
                             cudaFuncAttributeMaxDynamicSharedMemorySize, 98304);
        cudaStreamCreateWithFlags(&s1, cudaStreamNonBlocking);
        cudaStreamCreateWithFlags(&s2, cudaStreamNonBlocking);
        cudaEventCreateWithFlags(&evF,  cudaEventDisableTiming);
        cudaEventCreateWithFlags(&evJ1, cudaEventDisableTiming);
        cudaEventCreateWithFlags(&evJ2, cudaEventDisableTiming);
        cudaEventCreateWithFlags(&evF2, cudaEventDisableTiming);
        cudaEventCreateWithFlags(&evJ3, cudaEventDisableTiming);
        inited = true;
    }

    // ---- fork: s1 = seqWc chain; s2 = weights/rep/rso; main = ga/pa ----
    cudaEventRecord(evF, 0);
    cudaStreamWaitEvent(s1, evF, 0);
    cudaStreamWaitEvent(s2, evF, 0);

    // s1: round seq+Wc, then seqWc = rnd(seqR @ WcR)  grid(12,8,4)=384
    {
        long long tot = (long long)BATCH * SEQ * HID + (long long)HID * WD;
        prep_seqWc_kernel<<<(unsigned)((tot + 255) / 256), 256, 0, s1>>>(seq, W_c);
        dim3 grid(WD / 64, SEQ / 128, BATCH);
        mma_gemm<0, 1><<<grid, 256, 0, s1>>>(p_seqR, p_WcR, p_seqWc, nullptr,
                                             SEQ, WD, HID,
                                             (long long)SEQ * HID, 0, (long long)SEQ * WD,
                                             1, 0, nullptr, 0.f, nullptr, 0, nullptr);
        cudaEventRecord(evJ1, s1);
    }
    // s2: remaining weight prep, rep, rso
    {
        long long totw = (long long)WD * AD + (long long)WD * NCP
                       + (long long)WD * PP + (long long)WD * WD;
        prep_w2_kernel<<<(unsigned)((totw + 255) / 256), 256, 0, s2>>>(
            W_attn, clf_W, A_bl, W_s, W_o);
        rep_kernel<<<BATCH * NENT, 256, 0, s2>>>(seq, ep);
        dim3 grid((2 * WD) / 64, 1, 6);
        mma_gemm<0, 0><<<grid, 256, 0, s2>>>(p_rep, p_Wso, p_part, nullptr,
                                             BATCH * NENT, 2 * WD, HID, 0, 0, 0,
                                             6, (long long)BATCH * NENT * 2 * WD,
                                             nullptr, 0.f, nullptr, 0, nullptr);
        reduce_add_kernel<<<(BATCH * NENT * 2 * WD + 255) / 256, 256, 0, s2>>>(
            p_part, p_rso, 6, (long long)BATCH * NENT * 2 * WD);
        cudaEventRecord(evJ2, s2);
    }
    // main: ga + pa
    {
        dim3 grid(SEQ / 256, NENT * HEADS, BATCH);
        ga_kernel<<<grid, 256>>>(att, ep);
    }
    {
        dim3 grid(8, 8, BATCH);
        pa_tiled_kernel<<<grid, 256, 98304>>>();
    }
    // join: fused GEMM needs seqWc (s1), rso (s2), pa/painv (main)
    cudaStreamWaitEvent(0, evJ1, 0);
    cudaStreamWaitEvent(0, evJ2, 0);
    // fused: Zs/Zo = tanh(rso[i] + painv[row]*(pa @ seqWc))  grid(12,8,4)=384
    {
        dim3 grid(WD / 64, NPAIR / 128, BATCH);
        mma_gemm<3, 0><<<grid, 256>>>(p_pa, p_seqWc, p_Zs, p_Zo,
                                      NPAIR, WD, SEQ,
                                      (long long)NPAIR * SEQ, (long long)SEQ * WD,
                                      (long long)NPAIR * WD,
                                      1, 0, p_rso, 0.f, p_rso + WD, 2 * WD, p_painv);
    }
    // P (rounded, K-padded to 160)
    P_kernel<<<BATCH * NPAIR, 256>>>();
    // g = P @ Ablt + 64*b_bl (rounded)  K=160, grid(12,32)=384
    {
        dim3 grid(WD / 64, (BATCH * NPAIR) / 128, 1);
        mma_gemm<0, 1><<<grid, 256>>>(p_P, p_Ablt, p_g, nullptr,
                                      BATCH * NPAIR, WD, PP2, 0, 0, 0,
                                      1, 0, b_bl, (float)SPLITK, nullptr, 0, nullptr);
    }
    // ---- fork 2: s1 = gclf; main = t -> e -> softmax ----
    cudaEventRecord(evF2, 0);
    cudaStreamWaitEvent(s1, evF2, 0);
    {
        long long len = (long long)BATCH * NPAIR * NCP;
        dim3 grid(NCP / 64, (BATCH * NPAIR) / 128, 6);
        mma_gemm<0, 0><<<grid, 256, 0, s1>>>(p_g, p_clfR, p_part2, nullptr,
                                             BATCH * NPAIR, NCP, WD, 0, 0, 0,
                                             6, len, nullptr, 0.f, nullptr, 0, nullptr);
        reduce_add_kernel<<<(unsigned)((len + 255) / 256), 256, 0, s1>>>(
            p_part2, p_gclf, 6, len);
        cudaEventRecord(evJ3, s1);
    }
    // main: t = g @ WaR  split-K 3, grid(4,32,3)=384
    {
        long long len = (long long)BATCH * NPAIR * AD;
        dim3 grid(AD / 64, (BATCH * NPAIR) / 128, 3);
        mma_gemm<0, 0><<<grid, 256>>>(p_g, p_WaR, p_part, nullptr,
                                      BATCH * NPAIR, AD, WD, 0, 0, 0,
                                      3, len, nullptr, 0.f, nullptr, 0, nullptr);
        reduce_add_kernel<<<(unsigned)((len + 255) / 256), 256>>>(p_part, p_t, 3, len);
    }
    e_kernel<<<BATCH * NPAIR, 256>>>(v_attn);
    softmax_kernel<<<BATCH, 1024>>>();
    cudaStreamWaitEvent(0, evJ3, 0);
    {
        dim3 grid(NENT, BATCH);
        rowcolC_kernel<<<grid, 128>>>();
    }
    {
        long long total = (long long)BATCH * NPAIR * NC;
        final_kernel<<<(unsigned)((total + 255) / 256), 256>>>(clf_b, out);
    }
}

// round 16
// speedup vs baseline: 1.2990x; 1.0249x over previous
#include <cuda_runtime.h>
#include <math.h>
#include <stdint.h>

#define BATCH 4
#define SEQ   1024
#define HID   768
#define HEADS 12
#define NENT  32
#define MENT  4
#define WD    768
#define AD    256
#define NC    97
#define NCP   128          // padded classifier width
#define SPLITK 64
#define DD    12
#define PP    144          // DD*DD
#define PP2   160          // K-padded (zeros) for BK=32 GEMM
#define NPAIR (NENT*NENT)  // 1024

// ---------------- device scratch ----------------
__device__ float d_rep[BATCH*NENT*HID];
__device__ float d_rso[BATCH*NENT*2*WD];
__device__ float d_Wso[WD*2*WD];
__device__ float d_seqR[(size_t)BATCH*SEQ*HID];   // tf32-rounded seq
__device__ float d_WcR[HID*WD];
__device__ float d_WaR[WD*AD];
__device__ float d_clfR[WD*NCP];                  // rounded + padded clf_W
__device__ float d_seqWc[(size_t)BATCH*SEQ*WD];   // rnd(seq @ W_c), tf32-rounded
__device__ float d_ga [BATCH*NENT*HEADS*SEQ];
__device__ float d_pa [(size_t)BATCH*NPAIR*SEQ];  // unnormalized, tf32-rounded
__device__ float d_painv[BATCH*NPAIR];
__device__ float d_Zs [(size_t)BATCH*NPAIR*WD];
__device__ float d_Zo [(size_t)BATCH*NPAIR*WD];
__device__ float d_P  [(size_t)BATCH*NPAIR*PP2];  // cols 144..159 stay zero
__device__ float d_g  [(size_t)BATCH*NPAIR*WD];
__device__ float d_e  [BATCH*NPAIR];
__device__ float d_arow[BATCH*NPAIR];
__device__ float d_acol[BATCH*NPAIR];
__device__ float d_Ablt[PP2*WD];                  // rows 144..159 stay zero
__device__ float d_gclf[(size_t)BATCH*NPAIR*NCP];
__device__ float d_rgcg[2*BATCH*NENT*NC];
__device__ float d_part [3300000];                // rso / t split-K partials
__device__ float d_part2[3300000];                // gclf split-K partials (concurrent)

// ---------------- helpers ----------------
__device__ __forceinline__ uint32_t f2tf32(float x)
{
    uint32_t r;
    asm("cvt.rna.tf32.f32 %0, %1;" : "=r"(r) : "f"(x));
    return r;
}
__device__ __forceinline__ float rnd32(float x) { return __uint_as_float(f2tf32(x)); }

__device__ __forceinline__ void mma_tf32(float* c, const uint32_t* a, const uint32_t* b)
{
    asm volatile(
        "mma.sync.aligned.m16n8k8.row.col.f32.tf32.tf32.f32 "
        "{%0,%1,%2,%3}, {%4,%5,%6,%7}, {%8,%9}, {%0,%1,%2,%3};"
        : "+f"(c[0]), "+f"(c[1]), "+f"(c[2]), "+f"(c[3])
        : "r"(a[0]), "r"(a[1]), "r"(a[2]), "r"(a[3]), "r"(b[0]), "r"(b[1]));
}

__device__ __forceinline__ void cp16(uint32_t smem, const void* g)
{
    asm volatile("cp.async.cg.shared.global [%0], [%1], 16;" :: "r"(smem), "l"(g));
}
__device__ __forceinline__ uint32_t smem_u32(const void* p)
{
    return (uint32_t)__cvta_generic_to_shared(p);
}

// ---------------- BK=32 cp.async pipelined tf32 GEMM ----------------
// C[M,N] = A[M,K] row * B[K,N] row, operands pre-rounded to tf32.
// BM=128, BN=64, BK=32. 8 warps: 4 m x 2 n, warp tile 32x32.
// As[128][36] / Bs[32][72]: conflict-free cp.async stores AND fragment LDS.
// 2-stage ring, wait_group 0; 32 HMMA/warp between barriers. 3 blocks/SM.
// MODE 0: C = acc (+ biasScale*bias[n]).
// MODE 1: C = tanh(acc + bias[(gm>>5)*bS+gn]); C2 likewise with bias2.
// MODE 2: C = acc * bias[zb*bS+gm].
// MODE 3: v = acc * scale[zb*NPAIR+gm];
//         C  = tanh(v + bias [((zb*NENT)+(gm>>5))*bS+gn]);
//         C2 = tanh(v + bias2[...same row...]).
// RND: round stored C to tf32 (MODE 0/2).
// Requirements: M%128==0, (K/kSplit)%32==0, N%4==0.
#define AS_STRIDE 36
#define BS_STRIDE 72
template<int MODE, int RND>
__global__ __launch_bounds__(256, 3)
void mma_gemm(const float* __restrict__ A, const float* __restrict__ B,
              float* __restrict__ C, float* __restrict__ C2,
              int M, int N, int K,
              long long sA, long long sB, long long sC,
              int kSplit, long long partStride,
              const float* __restrict__ bias, float biasScale,
              const float* __restrict__ bias2, int biasStride,
              const float* __restrict__ scale)
{
    const int NWT = 4;
    const int BN  = 64;
    __shared__ uint32_t As[2][128 * AS_STRIDE];   // 2 x 18 KB
    __shared__ float    Bs[2][32 * BS_STRIDE];    // 2 x 9 KB

    int zb = blockIdx.z / kSplit;
    int kz = blockIdx.z - zb * kSplit;
    A += (long long)zb * sA;
    B += (long long)zb * sB;
    C += (long long)zb * sC + (long long)kz * partStride;
    if (C2) C2 += (long long)zb * sC;             // batch-offset second output

    int row0 = blockIdx.y * 128;
    int col0 = blockIdx.x * BN;
    int tid = threadIdx.x, lane = tid & 31, w = tid >> 5;
    int wm = w & 3, wn = w >> 2;
    int g = lane >> 2, t = lane & 3;

    int kLen = K / kSplit;
    int k0beg = kz * kLen, k0end = k0beg + kLen;

    float acc[2][NWT][4];
    #pragma unroll
    for (int i = 0; i < 2; i++)
        #pragma unroll
        for (int j = 0; j < NWT; j++)
            #pragma unroll
            for (int r = 0; r < 4; r++) acc[i][j][r] = 0.f;

    int am = tid >> 3, ak = (tid & 7) * 4;
    const float* gA = A + (long long)(row0 + am) * K + ak;
    uint32_t asA = smem_u32(&As[0][am * AS_STRIDE + ak]);
    const uint32_t strideAstg = 128 * AS_STRIDE * 4;
    const uint32_t strideArow = 32 * AS_STRIDE * 4;

    int bk = tid >> 4, bn = (tid & 15) * 4;
    uint32_t bsB = smem_u32(&Bs[0][bk * BS_STRIDE + bn]);
    const uint32_t strideBstg = 32 * BS_STRIDE * 4;
    const uint32_t strideBrow = 16 * BS_STRIDE * 4;

    // prologue
    {
        #pragma unroll
        for (int p = 0; p < 4; p++)
            cp16(asA + p * strideArow, gA + (long long)p * 32 * K + k0beg);
        #pragma unroll
        for (int p = 0; p < 2; p++)
            cp16(bsB + p * strideBrow,
                 B + (long long)(k0beg + bk + p * 16) * N + col0 + bn);
        asm volatile("cp.async.commit_group;");
    }

    int buf = 0;
    for (int k0 = k0beg; k0 < k0end; k0 += 32) {
        asm volatile("cp.async.wait_group 0;");
        __syncthreads();

        int kn = k0 + 32;
        if (kn < k0end) {
            uint32_t ao = (buf ^ 1) ? strideAstg : 0;
            uint32_t bo = (buf ^ 1) ? strideBstg : 0;
            #pragma unroll
            for (int p = 0; p < 4; p++)
                cp16(asA + ao + p * strideArow, gA + (long long)p * 32 * K + kn);
            #pragma unroll
            for (int p = 0; p < 2; p++)
                cp16(bsB + bo + p * strideBrow,
                     B + (long long)(kn + bk + p * 16) * N + col0 + bn);
            asm volatile("cp.async.commit_group;");
        }

        const uint32_t* as = As[buf];
        const float*    bs = Bs[buf];
        #pragma unroll
        for (int k8 = 0; k8 < 4; k8++) {
            int kb = k8 * 8;
            uint32_t a[2][4];
            #pragma unroll
            for (int mi = 0; mi < 2; mi++) {
                int mb = wm * 32 + mi * 16;
                a[mi][0] = as[(mb + g)     * AS_STRIDE + kb + t];
                a[mi][1] = as[(mb + g + 8) * AS_STRIDE + kb + t];
                a[mi][2] = as[(mb + g)     * AS_STRIDE + kb + t + 4];
                a[mi][3] = as[(mb + g + 8) * AS_STRIDE + kb + t + 4];
            }
            uint32_t b[NWT][2];
            #pragma unroll
            for (int ni = 0; ni < NWT; ni++) {
                int nb_ = wn * 32 + ni * 8 + g;
                b[ni][0] = __float_as_uint(bs[(kb + t)     * BS_STRIDE + nb_]);
                b[ni][1] = __float_as_uint(bs[(kb + t + 4) * BS_STRIDE + nb_]);
            }
            #pragma unroll
            for (int mi = 0; mi < 2; mi++)
                #pragma unroll
                for (int ni = 0; ni < NWT; ni++)
                    mma_tf32(acc[mi][ni], a[mi], b[ni]);
        }
        buf ^= 1;
    }

    // ---- epilogue ----
    #pragma unroll
    for (int mi = 0; mi < 2; mi++) {
        #pragma unroll
        for (int ni = 0; ni < NWT; ni++) {
            int m_base = row0 + wm * 32 + mi * 16 + g;
            int n_base = col0 + wn * 32 + ni * 8 + t * 2;
            #pragma unroll
            for (int r = 0; r < 4; r++) {
                int gm = m_base + ((r >> 1) << 3);
                int gn = n_base + (r & 1);
                if (gn >= N) continue;
                float v = acc[mi][ni][r];
                if (MODE == 0) {
                    if (bias) v += biasScale * bias[gn];
                    if (RND) v = rnd32(v);
                    C[(long long)gm * N + gn] = v;
                } else if (MODE == 1) {
                    long long br = (long long)(gm >> 5) * biasStride + gn;
                    C [(long long)gm * N + gn] = tanhf(v + bias [br]);
                    C2[(long long)gm * N + gn] = tanhf(v + bias2[br]);
                } else if (MODE == 2) {
                    v *= bias[(long long)zb * biasStride + gm];
                    if (RND) v = rnd32(v);
                    C[(long long)gm * N + gn] = v;
                } else {
                    float vv = v * scale[(long long)zb * NPAIR + gm];
                    long long br = (long long)((zb << 5) + (gm >> 5)) * biasStride + gn;
                    C [(long long)gm * N + gn] = tanhf(vv + bias [br]);
                    C2[(long long)gm * N + gn] = tanhf(vv + bias2[br]);
                }
            }
        }
    }
}

__global__ void reduce_add_kernel(const float* __restrict__ src, float* __restrict__ dst,
                                  int parts, long long len)
{
    long long i = (long long)blockIdx.x * 256 + threadIdx.x;
    if (i >= len) return;
    float s = 0.f;
    for (int p = 0; p < parts; p++) s += src[(long long)p * len + i];
    dst[i] = s;
}

// ---------------- stage kernels ----------------
__global__ void rep_kernel(const float* __restrict__ seq, const int* __restrict__ ep)
{
    int bn = blockIdx.x;
    int b = bn / NENT, n = bn % NENT;
    int e0 = ep[(b * NENT + n) * MENT + 0];
    int e1 = ep[(b * NENT + n) * MENT + 1];
    int e2 = ep[(b * NENT + n) * MENT + 2];
    int e3 = ep[(b * NENT + n) * MENT + 3];
    const float* sb = seq + (long long)b * SEQ * HID;
    for (int h = threadIdx.x; h < HID; h += blockDim.x) {
        float v0 = sb[(long long)e0 * HID + h];
        float v1 = sb[(long long)e1 * HID + h];
        float v2 = sb[(long long)e2 * HID + h];
        float v3 = sb[(long long)e3 * HID + h];
        float m = fmaxf(fmaxf(v0, v1), fmaxf(v2, v3));
        float s = expf(v0 - m) + expf(v1 - m) + expf(v2 - m) + expf(v3 - m);
        d_rep[(b * NENT + n) * HID + h] = rnd32(m + logf(s));
    }
}

// side1 prep: round seq and W_c (operands of the seqWc GEMM)
__global__ void prep_seqWc_kernel(const float* __restrict__ seq,
                                  const float* __restrict__ Wc)
{
    const long long n1 = (long long)BATCH * SEQ * HID;
    const long long n2 = (long long)HID * WD;
    long long idx = (long long)blockIdx.x * 256 + threadIdx.x;
    if (idx < n1) { d_seqR[idx] = rnd32(seq[idx]); return; }
    idx -= n1;
    if (idx < n2) d_WcR[idx] = rnd32(Wc[idx]);
}

// side2 prep: W_attn, clf (padded), A_bl transpose, [Ws|Wo] pack
__global__ void prep_w2_kernel(const float* __restrict__ Wa,
                               const float* __restrict__ clf,
                               const float* __restrict__ A_bl,
                               const float* __restrict__ W_s,
                               const float* __restrict__ W_o)
{
    const long long n3 = (long long)WD * AD;
    const long long n4 = (long long)WD * NCP;
    const long long n5 = (long long)WD * PP;
    const long long n6 = (long long)WD * WD;
    long long idx = (long long)blockIdx.x * 256 + threadIdx.x;
    if (idx < n3) { d_WaR[idx] = rnd32(Wa[idx]); return; }
    idx -= n3;
    if (idx < n4) {
        int row = (int)(idx >> 7), col = (int)(idx & (NCP - 1));
        d_clfR[idx] = (col < NC) ? rnd32(clf[row * NC + col]) : 0.f;
        return;
    }
    idx -= n4;
    if (idx < n5) {
        int o = (int)(idx / PP), pq = (int)(idx % PP);
        d_Ablt[pq * WD + o] = rnd32(A_bl[idx]);
        return;
    }
    idx -= n5;
    if (idx < n6) {
        int k = (int)(idx / WD), j = (int)(idx % WD);
        d_Wso[(long long)k * (2 * WD) + j]      = rnd32(W_s[idx]);
        d_Wso[(long long)k * (2 * WD) + WD + j] = rnd32(W_o[idx]);
    }
}

__global__ void ga_kernel(const float* __restrict__ att, const int* __restrict__ ep)
{
    int b = blockIdx.z;
    int n = blockIdx.y / HEADS, h = blockIdx.y % HEADS;
    int s = blockIdx.x * blockDim.x + threadIdx.x;
    const float* ab = att + ((long long)(b * HEADS + h)) * SEQ * SEQ;
    float a = 0.f;
    #pragma unroll
    for (int m = 0; m < MENT; m++) {
        int e = ep[(b * NENT + n) * MENT + m];
        a += ab[(long long)e * SEQ + s];
    }
    d_ga[((long long)((b * NENT + n) * HEADS + h)) * SEQ + s] = a;
}

__global__ __launch_bounds__(256) void pa_tiled_kernel()
{
    extern __shared__ float sm[];          // [0:12288) gi, [12288:24576) gj
    __shared__ float sred[16 * 8];
    int b = blockIdx.z, ti = blockIdx.y, tj = blockIdx.x;
    int tid = threadIdx.x, lane = tid & 31, w = tid >> 5;

    float psum[16];
    #pragma unroll
    for (int p = 0; p < 16; p++) psum[p] = 0.f;

    for (int c = 0; c < 4; c++) {
        int s0 = c * 256;
        for (int l = tid; l < 3072; l += 256) {
            int il = l / 768;
            int rem = l - il * 768;
            int h = rem / 64, sq = rem - h * 64;
            int smoff = (il * 12 + h) * 256 + sq * 4;
            *(float4*)&sm[smoff] =
                *(const float4*)&d_ga[(((long long)(b * NENT + ti * 4 + il) * HEADS + h) << 10) + s0 + sq * 4];
            *(float4*)&sm[12288 + smoff] =
                *(const float4*)&d_ga[(((long long)(b * NENT + tj * 4 + il) * HEADS + h) << 10) + s0 + sq * 4];
        }
        __syncthreads();

        float acc[16];
        #pragma unroll
        for (int p = 0; p < 16; p++) acc[p] = 0.f;
        #pragma unroll
        for (int h = 0; h < HEADS; h++) {
            float ai[4], bj[4];
            #pragma unroll
            for (int il = 0; il < 4; il++) ai[il] = sm[(il * 12 + h) * 256 + tid];
            #pragma unroll
            for (int jl = 0; jl < 4; jl++) bj[jl] = sm[12288 + (jl * 12 + h) * 256 + tid];
            #pragma unroll
            for (int il = 0; il < 4; il++)
                #pragma unroll
                for (int jl = 0; jl < 4; jl++)
                    acc[il * 4 + jl] += ai[il] * bj[jl];
        }
        #pragma unroll
        for (int il = 0; il < 4; il++)
            #pragma unroll
            for (int jl = 0; jl < 4; jl++) {
                int p = il * 4 + jl;
                int ij = (ti * 4 + il) * NENT + tj * 4 + jl;
                d_pa[((long long)(b * NPAIR + ij) << 10) + s0 + tid] = rnd32(acc[p]);
                psum[p] += acc[p];
            }
        __syncthreads();
    }

    #pragma unroll
    for (int p = 0; p < 16; p++) {
        #pragma unroll
        for (int o = 16; o > 0; o >>= 1)
            psum[p] += __shfl_xor_sync(~0u, psum[p], o);
    }
    if (lane == 0)
        #pragma unroll
        for (int p = 0; p < 16; p++) sred[p * 8 + w] = psum[p];
    __syncthreads();
    if (tid < 16) {
        float s = 0.f;
        #pragma unroll
        for (int ww = 0; ww < 8; ww++) s += sred[tid * 8 + ww];
        int il = tid >> 2, jl = tid & 3;
        int ij = (ti * 4 + il) * NENT + tj * 4 + jl;
        d_painv[b * NPAIR + ij] = 1.0f / s;
    }
}

// one row per block; 160 threads (144 compute), float4 smem fills.
__global__ __launch_bounds__(160) void P_kernel()
{
    __shared__ float zs[WD], zo[WD];
    long long row = blockIdx.x;
    for (int w = threadIdx.x * 4; w < WD; w += 160 * 4) {
        *(float4*)&zs[w] = *(const float4*)&d_Zs[row * WD + w];
        *(float4*)&zo[w] = *(const float4*)&d_Zo[row * WD + w];
    }
    __syncthreads();
    int t = threadIdx.x;
    if (t < PP) {
        int p = t / DD, q = t % DD;
        float a = 0.f;
        #pragma unroll
        for (int k = 0; k < SPLITK; k++)
            a += zs[p * SPLITK + k] * zo[q * SPLITK + k];
        d_P[row * PP2 + t] = rnd32(a);   // cols 144..159 remain zero
    }
}

// e = tanh(sum of 3 t-partials) . v_attn  (t reduce folded in)
__global__ __launch_bounds__(256) void e_kernel(const float* __restrict__ v_attn)
{
    const long long plen = (long long)BATCH * NPAIR * AD;
    long long base = (long long)blockIdx.x * AD + threadIdx.x;
    int tid = threadIdx.x;
    float tv = d_part[base] + d_part[plen + base] + d_part[2 * plen + base];
    float val = tanhf(tv) * v_attn[tid];
    __shared__ float red[256];
    red[tid] = val;
    __syncthreads();
    for (int off = 128; off > 0; off >>= 1) {
        if (tid < off) red[tid] += red[tid + off];
        __syncthreads();
    }
    if (tid == 0) d_e[blockIdx.x] = red[0];
}

__global__ __launch_bounds__(1024) void softmax_kernel()
{
    int b = blockIdx.x;
    int tid = threadIdx.x;
    int w = tid >> 5, lane = tid & 31;
    const float* eb = d_e + b * NPAIR;
    float v = eb[w * 32 + lane];
    float m = v;
    for (int o = 16; o > 0; o >>= 1) m = fmaxf(m, __shfl_xor_sync(~0u, m, o));
    float ex = expf(v - m);
    float s = ex;
    for (int o = 16; o > 0; o >>= 1) s += __shfl_xor_sync(~0u, s, o);
    d_arow[b * NPAIR + w * 32 + lane] = ex / s;
    float v2 = eb[lane * 32 + w];
    float m2 = v2;
    for (int o = 16; o > 0; o >>= 1) m2 = fmaxf(m2, __shfl_xor_sync(~0u, m2, o));
    float ex2 = expf(v2 - m2);
    float s2 = ex2;
    for (int o = 16; o > 0; o >>= 1) s2 += __shfl_xor_sync(~0u, s2, o);
    d_acol[b * NPAIR + lane * 32 + w] = ex2 / s2;
}

__global__ void rowcolC_kernel()
{
    int b = blockIdx.y, n = blockIdx.x;
    int c = threadIdx.x;
    if (c >= NC) return;
    const float* gc = d_gclf + (long long)b * NPAIR * NCP;
    float rs = 0.f, cs = 0.f;
    #pragma unroll 4
    for (int k = 0; k < NENT; k++) {
        rs += d_arow[b * NPAIR + n * 32 + k] * gc[(long long)(n * 32 + k) * NCP + c];
        cs += d_acol[b * NPAIR + k * 32 + n] * gc[(long long)(k * 32 + n) * NCP + c];
    }
    d_rgcg[(b * NENT + n) * NC + c] = rs;
    d_rgcg[(BATCH * NENT + b * NENT + n) * NC + c] = cs;
}

__global__ void final_kernel(const float* __restrict__ clf_b, float* __restrict__ out)
{
    long long idx = (long long)blockIdx.x * blockDim.x + threadIdx.x;
    const long long total = (long long)BATCH * NPAIR * NC;
    if (idx >= total) return;
    int c = (int)(idx % NC);
    long long rb = idx / NC;
    int ij = (int)(rb % NPAIR);
    int b = (int)(rb / NPAIR);
    int i = ij >> 5, j = ij & 31;
    out[idx] = d_gclf[rb * NCP + c]
             + d_rgcg[(b * NENT + i) * NC + c]
             + d_rgcg[(BATCH * NENT + b * NENT + j) * NC + c]
             + clf_b[c];
}

// ---------------- host launch ----------------
extern "C" void kernel_launch(void* const* d_in, const int* in_sizes, int n_in,
                              void* d_out, int out_size)
{
    const float* seq    = (const float*)d_in[0];
    const float* att    = (const float*)d_in[1];
    const int*   ep     = (const int*)  d_in[2];
    const float* W_s    = (const float*)d_in[3];
    const float* W_o    = (const float*)d_in[4];
    const float* W_c    = (const float*)d_in[5];
    const float* A_bl   = (const float*)d_in[6];
    const float* b_bl   = (const float*)d_in[7];
    const float* W_attn = (const float*)d_in[8];
    const float* v_attn = (const float*)d_in[9];
    const float* clf_W  = (const float*)d_in[10];
    const float* clf_b  = (const float*)d_in[11];
    float* out = (float*)d_out;

    float *p_rep, *p_rso, *p_Wso, *p_seqR, *p_WcR, *p_WaR, *p_clfR, *p_seqWc,
          *p_pa, *p_painv, *p_Zs, *p_Zo, *p_P, *p_Ablt, *p_g,
          *p_gclf, *p_part, *p_part2;
    cudaGetSymbolAddress((void**)&p_rep,   d_rep);
    cudaGetSymbolAddress((void**)&p_rso,   d_rso);
    cudaGetSymbolAddress((void**)&p_Wso,   d_Wso);
    cudaGetSymbolAddress((void**)&p_seqR,  d_seqR);
    cudaGetSymbolAddress((void**)&p_WcR,   d_WcR);
    cudaGetSymbolAddress((void**)&p_WaR,   d_WaR);
    cudaGetSymbolAddress((void**)&p_clfR,  d_clfR);
    cudaGetSymbolAddress((void**)&p_seqWc, d_seqWc);
    cudaGetSymbolAddress((void**)&p_pa,    d_pa);
    cudaGetSymbolAddress((void**)&p_painv, d_painv);
    cudaGetSymbolAddress((void**)&p_Zs,    d_Zs);
    cudaGetSymbolAddress((void**)&p_Zo,    d_Zo);
    cudaGetSymbolAddress((void**)&p_P,     d_P);
    cudaGetSymbolAddress((void**)&p_Ablt,  d_Ablt);
    cudaGetSymbolAddress((void**)&p_g,     d_g);
    cudaGetSymbolAddress((void**)&p_gclf,  d_gclf);
    cudaGetSymbolAddress((void**)&p_part,  d_part);
    cudaGetSymbolAddress((void**)&p_part2, d_part2);

    static cudaStream_t s1 = nullptr, s2 = nullptr;
    static cudaEvent_t evF, evJ1, evJ2, evF2, evJ3;
    static bool inited = false;
    if (!inited) {
        cudaFuncSetAttribute(pa_tiled_kernel,
                             cudaFuncAttributeMaxDynamicSharedMemorySize, 98304);
        cudaStreamCreateWithFlags(&s1, cudaStreamNonBlocking);
        cudaStreamCreateWithFlags(&s2, cudaStreamNonBlocking);
        cudaEventCreateWithFlags(&evF,  cudaEventDisableTiming);
        cudaEventCreateWithFlags(&evJ1, cudaEventDisableTiming);
        cudaEventCreateWithFlags(&evJ2, cudaEventDisableTiming);
        cudaEventCreateWithFlags(&evF2, cudaEventDisableTiming);
        cudaEventCreateWithFlags(&evJ3, cudaEventDisableTiming);
        inited = true;
    }

    // ---- fork: s1 = seqWc chain; s2 = weights/rep/rso; main = ga/pa ----
    cudaEventRecord(evF, 0);
    cudaStreamWaitEvent(s1, evF, 0);
    cudaStreamWaitEvent(s2, evF, 0);

    // s1: round seq+Wc, then seqWc = rnd(seqR @ WcR)  grid(12,8,4)=384
    {
        long long tot = (long long)BATCH * SEQ * HID + (long long)HID * WD;
        prep_seqWc_kernel<<<(unsigned)((tot + 255) / 256), 256, 0, s1>>>(seq, W_c);
        dim3 grid(WD / 64, SEQ / 128, BATCH);
        mma_gemm<0, 1><<<grid, 256, 0, s1>>>(p_seqR, p_WcR, p_seqWc, nullptr,
                                             SEQ, WD, HID,
                                             (long long)SEQ * HID, 0, (long long)SEQ * WD,
                                             1, 0, nullptr, 0.f, nullptr, 0, nullptr);
        cudaEventRecord(evJ1, s1);
    }
    // s2: remaining weight prep, rep, rso
    {
        long long totw = (long long)WD * AD + (long long)WD * NCP
                       + (long long)WD * PP + (long long)WD * WD;
        prep_w2_kernel<<<(unsigned)((totw + 255) / 256), 256, 0, s2>>>(
            W_attn, clf_W, A_bl, W_s, W_o);
        rep_kernel<<<BATCH * NENT, 256, 0, s2>>>(seq, ep);
        dim3 grid((2 * WD) / 64, 1, 6);
        mma_gemm<0, 0><<<grid, 256, 0, s2>>>(p_rep, p_Wso, p_part, nullptr,
                                             BATCH * NENT, 2 * WD, HID, 0, 0, 0,
                                             6, (long long)BATCH * NENT * 2 * WD,
                                             nullptr, 0.f, nullptr, 0, nullptr);
        reduce_add_kernel<<<(BATCH * NENT * 2 * WD + 255) / 256, 256, 0, s2>>>(
            p_part, p_rso, 6, (long long)BATCH * NENT * 2 * WD);
        cudaEventRecord(evJ2, s2);
    }
    // main: ga + pa
    {
        dim3 grid(SEQ / 256, NENT * HEADS, BATCH);
        ga_kernel<<<grid, 256>>>(att, ep);
    }
    {
        dim3 grid(8, 8, BATCH);
        pa_tiled_kernel<<<grid, 256, 98304>>>();
    }
    // join: fused GEMM needs seqWc (s1), rso (s2), pa/painv (main)
    cudaStreamWaitEvent(0, evJ1, 0);
    cudaStreamWaitEvent(0, evJ2, 0);
    // fused: Zs/Zo = tanh(rso[i] + painv[row]*(pa @ seqWc))  grid(12,8,4)=384
    {
        dim3 grid(WD / 64, NPAIR / 128, BATCH);
        mma_gemm<3, 0><<<grid, 256>>>(p_pa, p_seqWc, p_Zs, p_Zo,
                                      NPAIR, WD, SEQ,
                                      (long long)NPAIR * SEQ, (long long)SEQ * WD,
                                      (long long)NPAIR * WD,
                                      1, 0, p_rso, 0.f, p_rso + WD, 2 * WD, p_painv);
    }
    // P (rounded, K-padded to 160)
    P_kernel<<<BATCH * NPAIR, 160>>>();
    // g = P @ Ablt + 64*b_bl (rounded)  K=160, grid(12,32)=384
    {
        dim3 grid(WD / 64, (BATCH * NPAIR) / 128, 1);
        mma_gemm<0, 1><<<grid, 256>>>(p_P, p_Ablt, p_g, nullptr,
                                      BATCH * NPAIR, WD, PP2, 0, 0, 0,
                                      1, 0, b_bl, (float)SPLITK, nullptr, 0, nullptr);
    }
    // ---- fork 2: s1 = gclf; main = t -> e -> softmax ----
    cudaEventRecord(evF2, 0);
    cudaStreamWaitEvent(s1, evF2, 0);
    {
        long long len = (long long)BATCH * NPAIR * NCP;
        dim3 grid(NCP / 64, (BATCH * NPAIR) / 128, 6);
        mma_gemm<0, 0><<<grid, 256, 0, s1>>>(p_g, p_clfR, p_part2, nullptr,
                                             BATCH * NPAIR, NCP, WD, 0, 0, 0,
                                             6, len, nullptr, 0.f, nullptr, 0, nullptr);
        reduce_add_kernel<<<(unsigned)((len + 255) / 256), 256, 0, s1>>>(
            p_part2, p_gclf, 6, len);
        cudaEventRecord(evJ3, s1);
    }
    // main: t partials = g @ WaR  split-K 3, grid(4,32,3)=384 (reduce folded into e)
    {
        long long len = (long long)BATCH * NPAIR * AD;
        dim3 grid(AD / 64, (BATCH * NPAIR) / 128, 3);
        mma_gemm<0, 0><<<grid, 256>>>(p_g, p_WaR, p_part, nullptr,
                                      BATCH * NPAIR, AD, WD, 0, 0, 0,
                                      3, len, nullptr, 0.f, nullptr, 0, nullptr);
    }
    e_kernel<<<BATCH * NPAIR, 256>>>(v_attn);
    softmax_kernel<<<BATCH, 1024>>>();
    cudaStreamWaitEvent(0, evJ3, 0);
    {
        dim3 grid(NENT, BATCH);
        rowcolC_kernel<<<grid, 128>>>();
    }
    {
        long long total = (long long)BATCH * NPAIR * NC;
        final_kernel<<<(unsigned)((total + 255) / 256), 256>>>(clf_b, out);
    }
}